// round 1
// baseline (speedup 1.0000x reference)
#include <cuda_runtime.h>
#include <math.h>

// Problem constants
#define BATCH 2
#define SEQ   2048
#define HID   2048
#define NHQ   16
#define NKV   4
#define HDIM  128
#define ROWS  (BATCH*SEQ)          // 4096
#define QCOLS (NHQ*HDIM)           // 2048
#define KCOLS (NKV*HDIM)           // 512

// Scratch (static __device__ — no allocation allowed)
__device__ float g_q[ROWS*QCOLS];
__device__ float g_k[ROWS*KCOLS];
__device__ float g_v[ROWS*KCOLS];
__device__ float g_ctx[ROWS*QCOLS];
__device__ float g_cos[SEQ*64];
__device__ float g_sin[SEQ*64];

// ---------------------------------------------------------------------------
// SGEMM: C[M,N] = A[M,K] @ B[K,N], row-major, all dims multiples of tile sizes.
// 128x128x8 tile, 256 threads, 8x8 microtile, split 4+4 for conflict-free LDS.128.
// ---------------------------------------------------------------------------
__global__ __launch_bounds__(256)
void sgemm128(const float* __restrict__ A, const float* __restrict__ B,
              float* __restrict__ C, int M, int N, int K)
{
    __shared__ float As[8*128];   // transposed: As[k][m]
    __shared__ float Bs[8*128];   // natural:    Bs[k][n]

    const int tid = threadIdx.x;
    const int tx = tid & 15, ty = tid >> 4;
    const int m0 = blockIdx.y * 128, n0 = blockIdx.x * 128;

    const int la_row  = tid >> 1;          // 0..127
    const int la_half = (tid & 1) * 4;     // 0 or 4
    const int lb_k    = tid >> 5;          // 0..7
    const int lb_c    = (tid & 31) * 4;    // 0..124

    const float* Aptr = A + (size_t)(m0 + la_row) * K + la_half;
    const float* Bptr = B + (size_t)lb_k * N + n0 + lb_c;

    float acc[8][8];
    #pragma unroll
    for (int i = 0; i < 8; i++)
        #pragma unroll
        for (int j = 0; j < 8; j++) acc[i][j] = 0.0f;

    float4 av = *reinterpret_cast<const float4*>(Aptr);
    float4 bv = *reinterpret_cast<const float4*>(Bptr);

    for (int kb = 0; kb < K; kb += 8) {
        // store current tile
        As[(la_half+0)*128 + la_row] = av.x;
        As[(la_half+1)*128 + la_row] = av.y;
        As[(la_half+2)*128 + la_row] = av.z;
        As[(la_half+3)*128 + la_row] = av.w;
        *reinterpret_cast<float4*>(Bs + lb_k*128 + lb_c) = bv;
        __syncthreads();

        // prefetch next tile into registers
        if (kb + 8 < K) {
            av = *reinterpret_cast<const float4*>(Aptr + kb + 8);
            bv = *reinterpret_cast<const float4*>(Bptr + (size_t)(kb + 8) * N);
        }

        #pragma unroll
        for (int k = 0; k < 8; k++) {
            const float4 a0 = *reinterpret_cast<const float4*>(As + k*128 + ty*4);
            const float4 a1 = *reinterpret_cast<const float4*>(As + k*128 + 64 + ty*4);
            const float4 b0 = *reinterpret_cast<const float4*>(Bs + k*128 + tx*4);
            const float4 b1 = *reinterpret_cast<const float4*>(Bs + k*128 + 64 + tx*4);
            const float aa[8] = {a0.x,a0.y,a0.z,a0.w,a1.x,a1.y,a1.z,a1.w};
            const float bb[8] = {b0.x,b0.y,b0.z,b0.w,b1.x,b1.y,b1.z,b1.w};
            #pragma unroll
            for (int i = 0; i < 8; i++)
                #pragma unroll
                for (int j = 0; j < 8; j++)
                    acc[i][j] += aa[i] * bb[j];
        }
        __syncthreads();
    }

    #pragma unroll
    for (int i = 0; i < 8; i++) {
        const int row = m0 + ((i < 4) ? (ty*4 + i) : (64 + ty*4 + (i - 4)));
        float* Crow = C + (size_t)row * N + n0;
        float4 v0 = make_float4(acc[i][0], acc[i][1], acc[i][2], acc[i][3]);
        float4 v1 = make_float4(acc[i][4], acc[i][5], acc[i][6], acc[i][7]);
        *reinterpret_cast<float4*>(Crow + tx*4)      = v0;
        *reinterpret_cast<float4*>(Crow + 64 + tx*4) = v1;
    }
}

// ---------------------------------------------------------------------------
// RoPE tables (double-precision range reduction, float sincos)
// ---------------------------------------------------------------------------
__global__ void rope_table_kernel()
{
    int idx = blockIdx.x * blockDim.x + threadIdx.x;
    if (idx >= SEQ * 64) return;
    int pos = idx >> 6, i = idx & 63;
    // inv_freq = 10000^(-i/64)  (exact double)
    double inv = exp2(-(double)i * (13.287712379549449 / 64.0));
    double ang = (double)pos * inv;
    const double twopi = 6.283185307179586476925286766559;
    ang -= floor(ang * (1.0 / twopi)) * twopi;
    if (ang > 3.14159265358979323846) ang -= twopi;
    float s, c;
    sincosf((float)ang, &s, &c);
    g_cos[idx] = c;
    g_sin[idx] = s;
}

// Apply RoPE in place: one thread per (row, head, i<64) pair
__global__ void rope_apply_kernel(float* __restrict__ buf, int heads, int npairs)
{
    int idx = blockIdx.x * blockDim.x + threadIdx.x;
    if (idx >= npairs) return;
    int i    = idx & 63;
    int hp   = idx >> 6;
    int head = hp % heads;
    int row  = hp / heads;
    int pos  = row & (SEQ - 1);
    size_t base = (size_t)row * heads * HDIM + head * HDIM + i;
    float c = g_cos[pos*64 + i];
    float s = g_sin[pos*64 + i];
    float x1 = buf[base];
    float x2 = buf[base + 64];
    buf[base]      = x1 * c - x2 * s;
    buf[base + 64] = x2 * c + x1 * s;
}

// ---------------------------------------------------------------------------
// Flash attention (causal, GQA). One block per (qtile=64 rows, head, batch).
// 256 threads as 16x16; 4x4 score microtile; O is 4 rows x 8 dims per thread.
// Q^T and K^T tiles are stored in smem with an XOR swizzle so the QK inner
// loop reads are conflict-free LDS.128.
// ---------------------------------------------------------------------------
#define ATT_SMEM (29184*4)

__global__ __launch_bounds__(256)
void flash_kernel(const float* __restrict__ Q, const float* __restrict__ Kb,
                  const float* __restrict__ Vb, float* __restrict__ ctx)
{
    extern __shared__ float sm[];
    float* Qs = sm;            // [128][64] transposed+swizzled (8192)
    float* Ks = sm + 8192;     // [128][64] transposed+swizzled (8192)
    float* Vs = sm + 16384;    // [64][132] natural, padded     (8448)
    float* Ps = sm + 24832;    // [64][68]  probs, padded       (4352)

    const int tid = threadIdx.x;
    const int tx = tid & 15, ty = tid >> 4;
    const int qt = blockIdx.x, h = blockIdx.y, b = blockIdx.z;
    const int kvh = h >> 2;                 // NH/KVH = 4
    const int qrow0 = b * SEQ + qt * 64;
    const float scale = 0.08838834764831845f;  // 1/sqrt(128)

    // Load Q tile transposed+swizzled: element (d, r) at d*64 + ((r>>2 ^ (d>>2)&15)<<2) + (r&3)
    for (int idx = tid; idx < 2048; idx += 256) {
        int r = idx >> 5, c4 = idx & 31, d0 = c4 << 2;
        float4 v = *reinterpret_cast<const float4*>(
            Q + (size_t)(qrow0 + r) * QCOLS + h * HDIM + d0);
        float vv[4] = {v.x, v.y, v.z, v.w};
        #pragma unroll
        for (int q = 0; q < 4; q++) {
            int d = d0 + q;
            Qs[(d << 6) + ((((r >> 2) ^ ((d >> 2) & 15))) << 2) + (r & 3)] = vv[q];
        }
    }

    float o[32];
    #pragma unroll
    for (int i = 0; i < 32; i++) o[i] = 0.0f;
    float mi[4] = {-1e30f, -1e30f, -1e30f, -1e30f};
    float li[4] = {0.0f, 0.0f, 0.0f, 0.0f};

    for (int kt = 0; kt <= qt; kt++) {
        const int krow0 = b * SEQ + kt * 64;
        // Load K tile transposed+swizzled, V tile natural
        for (int idx = tid; idx < 2048; idx += 256) {
            int r = idx >> 5, c4 = idx & 31, d0 = c4 << 2;
            float4 v = *reinterpret_cast<const float4*>(
                Kb + (size_t)(krow0 + r) * KCOLS + kvh * HDIM + d0);
            float vv[4] = {v.x, v.y, v.z, v.w};
            #pragma unroll
            for (int q = 0; q < 4; q++) {
                int d = d0 + q;
                Ks[(d << 6) + ((((r >> 2) ^ ((d >> 2) & 15))) << 2) + (r & 3)] = vv[q];
            }
            float4 w = *reinterpret_cast<const float4*>(
                Vb + (size_t)(krow0 + r) * KCOLS + kvh * HDIM + d0);
            *reinterpret_cast<float4*>(Vs + r * 132 + d0) = w;
        }
        __syncthreads();

        // S = Q K^T (4x4 per thread)
        float s[4][4];
        #pragma unroll
        for (int i = 0; i < 4; i++)
            #pragma unroll
            for (int j = 0; j < 4; j++) s[i][j] = 0.0f;

        #pragma unroll 8
        for (int d = 0; d < 128; d++) {
            const int sw = (d >> 2) & 15;
            const float4 a  = *reinterpret_cast<const float4*>(Qs + (d << 6) + ((ty ^ sw) << 2));
            const float4 kk = *reinterpret_cast<const float4*>(Ks + (d << 6) + ((tx ^ sw) << 2));
            const float aa[4] = {a.x, a.y, a.z, a.w};
            const float bb[4] = {kk.x, kk.y, kk.z, kk.w};
            #pragma unroll
            for (int i = 0; i < 4; i++)
                #pragma unroll
                for (int j = 0; j < 4; j++)
                    s[i][j] += aa[i] * bb[j];
        }

        // scale + causal mask (diagonal tile only)
        #pragma unroll
        for (int i = 0; i < 4; i++)
            #pragma unroll
            for (int j = 0; j < 4; j++) s[i][j] *= scale;
        if (kt == qt) {
            #pragma unroll
            for (int i = 0; i < 4; i++)
                #pragma unroll
                for (int j = 0; j < 4; j++)
                    if ((tx << 2) + j > (ty << 2) + i) s[i][j] = -1e30f;
        }

        // online softmax per row
        #pragma unroll
        for (int i = 0; i < 4; i++) {
            float rm = fmaxf(fmaxf(s[i][0], s[i][1]), fmaxf(s[i][2], s[i][3]));
            #pragma unroll
            for (int off = 1; off < 16; off <<= 1)
                rm = fmaxf(rm, __shfl_xor_sync(0xffffffffu, rm, off));
            float mnew = fmaxf(mi[i], rm);
            float corr = __expf(mi[i] - mnew);
            mi[i] = mnew;
            float rs = 0.0f;
            #pragma unroll
            for (int j = 0; j < 4; j++) {
                s[i][j] = __expf(s[i][j] - mnew);
                rs += s[i][j];
            }
            #pragma unroll
            for (int off = 1; off < 16; off <<= 1)
                rs += __shfl_xor_sync(0xffffffffu, rs, off);
            li[i] = li[i] * corr + rs;
            #pragma unroll
            for (int e = 0; e < 8; e++) o[i*8 + e] *= corr;
            *reinterpret_cast<float4*>(Ps + (4*ty + i) * 68 + 4*tx) =
                make_float4(s[i][0], s[i][1], s[i][2], s[i][3]);
        }
        __syncthreads();

        // O += P V
        #pragma unroll 2
        for (int j = 0; j < 64; j++) {
            const float4 v0 = *reinterpret_cast<const float4*>(Vs + j * 132 + tx*4);
            const float4 v1 = *reinterpret_cast<const float4*>(Vs + j * 132 + 64 + tx*4);
            #pragma unroll
            for (int i = 0; i < 4; i++) {
                const float a = Ps[(4*ty + i) * 68 + j];
                o[i*8+0] += a * v0.x; o[i*8+1] += a * v0.y;
                o[i*8+2] += a * v0.z; o[i*8+3] += a * v0.w;
                o[i*8+4] += a * v1.x; o[i*8+5] += a * v1.y;
                o[i*8+6] += a * v1.z; o[i*8+7] += a * v1.w;
            }
        }
        __syncthreads();
    }

    // epilogue: normalize and write ctx[B*S][NH*HD]
    #pragma unroll
    for (int i = 0; i < 4; i++) {
        const float inv = 1.0f / li[i];
        float* crow = ctx + (size_t)(qrow0 + 4*ty + i) * QCOLS + h * HDIM;
        float4 v0 = make_float4(o[i*8+0]*inv, o[i*8+1]*inv, o[i*8+2]*inv, o[i*8+3]*inv);
        float4 v1 = make_float4(o[i*8+4]*inv, o[i*8+5]*inv, o[i*8+6]*inv, o[i*8+7]*inv);
        *reinterpret_cast<float4*>(crow + tx*4)      = v0;
        *reinterpret_cast<float4*>(crow + 64 + tx*4) = v1;
    }
}

// ---------------------------------------------------------------------------
extern "C" void kernel_launch(void* const* d_in, const int* in_sizes, int n_in,
                              void* d_out, int out_size)
{
    const float* hidden = (const float*)d_in[0];
    const float* Wq = (const float*)d_in[1];
    const float* Wk = (const float*)d_in[2];
    const float* Wv = (const float*)d_in[3];
    const float* Wo = (const float*)d_in[4];
    float* out = (float*)d_out;

    float *qb, *kb, *vb, *cb;
    cudaGetSymbolAddress((void**)&qb, g_q);
    cudaGetSymbolAddress((void**)&kb, g_k);
    cudaGetSymbolAddress((void**)&vb, g_v);
    cudaGetSymbolAddress((void**)&cb, g_ctx);

    cudaFuncSetAttribute(flash_kernel,
                         cudaFuncAttributeMaxDynamicSharedMemorySize, ATT_SMEM);

    // QKV projections
    sgemm128<<<dim3(QCOLS/128, ROWS/128), 256>>>(hidden, Wq, qb, ROWS, QCOLS, HID);
    sgemm128<<<dim3(KCOLS/128, ROWS/128), 256>>>(hidden, Wk, kb, ROWS, KCOLS, HID);
    sgemm128<<<dim3(KCOLS/128, ROWS/128), 256>>>(hidden, Wv, vb, ROWS, KCOLS, HID);

    // RoPE
    rope_table_kernel<<<(SEQ*64 + 255)/256, 256>>>();
    int npq = ROWS * NHQ * 64;   // 4194304
    int npk = ROWS * NKV * 64;   // 1048576
    rope_apply_kernel<<<(npq + 255)/256, 256>>>(qb, NHQ, npq);
    rope_apply_kernel<<<(npk + 255)/256, 256>>>(kb, NKV, npk);

    // Attention
    flash_kernel<<<dim3(SEQ/64, NHQ, BATCH), 256, ATT_SMEM>>>(qb, kb, vb, cb);

    // Output projection
    sgemm128<<<dim3(HID/128, ROWS/128), 256>>>(cb, Wo, out, ROWS, HID, HID);
}

// round 3
// speedup vs baseline: 1.5927x; 1.5927x over previous
#include <cuda_runtime.h>
#include <cuda_bf16.h>
#include <math.h>
#include <stdint.h>

// Problem constants
#define BATCH 2
#define SEQ   2048
#define HID   2048
#define NHQ   16
#define NKV   4
#define HDIM  128
#define ROWS  (BATCH*SEQ)          // 4096
#define QCOLS (NHQ*HDIM)           // 2048
#define KCOLS (NKV*HDIM)           // 512

// ---------------------------------------------------------------------------
// Device scratch (static — no allocation allowed)
// ---------------------------------------------------------------------------
__device__ float g_q[ROWS*QCOLS];
__device__ float g_k[ROWS*KCOLS];
__device__ float g_v[ROWS*KCOLS];
__device__ float g_ctx[ROWS*QCOLS];
__device__ float g_cos[SEQ*64];
__device__ float g_sin[SEQ*64];

// bf16 hi/lo split buffers (A row-major [M][K], B transposed [N][K])
__device__ __nv_bfloat16 g_ah[ROWS*HID],    g_al[ROWS*HID];     // hidden
__device__ __nv_bfloat16 g_ch[ROWS*QCOLS],  g_cl[ROWS*QCOLS];   // ctx
__device__ __nv_bfloat16 g_wqh[QCOLS*HID],  g_wql[QCOLS*HID];   // Wq^T
__device__ __nv_bfloat16 g_wkh[KCOLS*HID],  g_wkl[KCOLS*HID];   // Wk^T
__device__ __nv_bfloat16 g_wvh[KCOLS*HID],  g_wvl[KCOLS*HID];   // Wv^T
__device__ __nv_bfloat16 g_woh[HID*QCOLS],  g_wol[HID*QCOLS];   // Wo^T

// ---------------------------------------------------------------------------
// Helpers
// ---------------------------------------------------------------------------
__device__ __forceinline__ uint32_t smem_u32(const void* p) {
    uint32_t a;
    asm("{ .reg .u64 t; cvta.to.shared.u64 t, %1; cvt.u32.u64 %0, t; }" : "=r"(a) : "l"(p));
    return a;
}
__device__ __forceinline__ void cp_async16(uint32_t dst, const void* src) {
    asm volatile("cp.async.cg.shared.global [%0], [%1], 16;\n" :: "r"(dst), "l"(src) : "memory");
}
__device__ __forceinline__ void ldsm_x4(uint32_t& r0, uint32_t& r1, uint32_t& r2, uint32_t& r3,
                                        uint32_t addr) {
    asm volatile("ldmatrix.sync.aligned.m8n8.x4.shared.b16 {%0,%1,%2,%3}, [%4];"
                 : "=r"(r0), "=r"(r1), "=r"(r2), "=r"(r3) : "r"(addr));
}
__device__ __forceinline__ void mma16816(float& c0, float& c1, float& c2, float& c3,
                                         uint32_t a0, uint32_t a1, uint32_t a2, uint32_t a3,
                                         uint32_t b0, uint32_t b1) {
    asm volatile(
        "mma.sync.aligned.m16n8k16.row.col.f32.bf16.bf16.f32 "
        "{%0,%1,%2,%3}, {%4,%5,%6,%7}, {%8,%9}, {%0,%1,%2,%3};"
        : "+f"(c0), "+f"(c1), "+f"(c2), "+f"(c3)
        : "r"(a0), "r"(a1), "r"(a2), "r"(a3), "r"(b0), "r"(b1));
}

// ---------------------------------------------------------------------------
// fp32 -> bf16 hi/lo split (row-major, same layout)
// ---------------------------------------------------------------------------
__global__ void split_kernel(const float* __restrict__ in,
                             __nv_bfloat16* __restrict__ hi,
                             __nv_bfloat16* __restrict__ lo, int n4)
{
    int i = blockIdx.x * blockDim.x + threadIdx.x;
    if (i >= n4) return;
    float4 v = reinterpret_cast<const float4*>(in)[i];
    __nv_bfloat16 h0 = __float2bfloat16_rn(v.x);
    __nv_bfloat16 h1 = __float2bfloat16_rn(v.y);
    __nv_bfloat16 h2 = __float2bfloat16_rn(v.z);
    __nv_bfloat16 h3 = __float2bfloat16_rn(v.w);
    __nv_bfloat16 l0 = __float2bfloat16_rn(v.x - __bfloat162float(h0));
    __nv_bfloat16 l1 = __float2bfloat16_rn(v.y - __bfloat162float(h1));
    __nv_bfloat16 l2 = __float2bfloat16_rn(v.z - __bfloat162float(h2));
    __nv_bfloat16 l3 = __float2bfloat16_rn(v.w - __bfloat162float(h3));
    __nv_bfloat162* hp = reinterpret_cast<__nv_bfloat162*>(hi);
    __nv_bfloat162* lp = reinterpret_cast<__nv_bfloat162*>(lo);
    hp[2*i]   = __nv_bfloat162(h0, h1);
    hp[2*i+1] = __nv_bfloat162(h2, h3);
    lp[2*i]   = __nv_bfloat162(l0, l1);
    lp[2*i+1] = __nv_bfloat162(l2, l3);
}

// fp32 [Kin][Nin] -> transposed bf16 hi/lo [Nin][Kin]
__global__ void tsplit_kernel(const float* __restrict__ in,
                              __nv_bfloat16* __restrict__ hiT,
                              __nv_bfloat16* __restrict__ loT, int Kin, int Nin)
{
    __shared__ float t[32][33];
    const int tx = threadIdx.x, ty = threadIdx.y;
    const int n0 = blockIdx.x * 32, k0 = blockIdx.y * 32;
    #pragma unroll
    for (int j = 0; j < 32; j += 8)
        t[ty + j][tx] = in[(size_t)(k0 + ty + j) * Nin + n0 + tx];
    __syncthreads();
    #pragma unroll
    for (int j = 0; j < 32; j += 8) {
        float x = t[tx][ty + j];
        __nv_bfloat16 h = __float2bfloat16_rn(x);
        __nv_bfloat16 l = __float2bfloat16_rn(x - __bfloat162float(h));
        size_t o = (size_t)(n0 + ty + j) * Kin + k0 + tx;
        hiT[o] = h;
        loT[o] = l;
    }
}

// ---------------------------------------------------------------------------
// Tensor-core GEMM via mma.sync (bf16 hi/lo 3-product emulation of fp32).
// C[4096, ldc] = A[4096, 2048] @ B^T  (B stored [ldc][2048] K-major).
// 128x128 CTA tile, 8 warps (2x4), 64x32 per warp, K chunk 32, 2-stage cp.async.
//
// Smem tile layout (per operand): [128 rows][4 chunks of 16B], row stride 64B,
// chunk swizzled by ((row>>1)&3) so every ldmatrix is bank-conflict-free.
// ---------------------------------------------------------------------------
#define KCH       32
#define NCHUNKS   64            // 2048 / 32
#define TILE_B    8192          // 128 x 32 bf16
#define STAGE_B   (4*TILE_B)    // Ah, Al, Bh, Bl
#define GEMM_SMEM (2*STAGE_B)   // 64 KB

__global__ __launch_bounds__(256, 1)
void gemm_mma(const __nv_bfloat16* __restrict__ Ah, const __nv_bfloat16* __restrict__ Al,
              const __nv_bfloat16* __restrict__ Bh, const __nv_bfloat16* __restrict__ Bl,
              float* __restrict__ C, int ldc)
{
    extern __shared__ char dsm[];
    const uint32_t sbase = smem_u32(dsm);

    const int tid = threadIdx.x;
    const int wid = tid >> 5, lane = tid & 31;
    const int m0 = blockIdx.y * 128;
    const int n0 = blockIdx.x * 128;

    // ---- loader mapping: 4 tiles x 64 threads each ----
    const int tt  = tid >> 6;          // 0:Ah 1:Al 2:Bh 3:Bl
    const int t6  = tid & 63;
    const int lch = t6 & 3;            // 16B chunk within row
    const int lr0 = t6 >> 2;           // row 0..15 (stride 16)
    const __nv_bfloat16* gsrc;
    int row0;
    switch (tt) {
        case 0: gsrc = Ah; row0 = m0; break;
        case 1: gsrc = Al; row0 = m0; break;
        case 2: gsrc = Bh; row0 = n0; break;
        default: gsrc = Bl; row0 = n0; break;
    }

    auto load_chunk = [&](int ci, int st) {
        const uint32_t tb = sbase + st * STAGE_B + tt * TILE_B;
        #pragma unroll
        for (int i = 0; i < 8; i++) {
            const int r = lr0 + i * 16;
            const uint32_t dst = tb + r * 64 + ((uint32_t)(lch ^ ((r >> 1) & 3)) << 4);
            cp_async16(dst, gsrc + (size_t)(row0 + r) * 2048 + ci * KCH + lch * 8);
        }
        asm volatile("cp.async.commit_group;\n" ::: "memory");
    };

    // ---- compute mapping ----
    const int warp_m = wid & 1;        // 2 x 64 rows
    const int warp_n = wid >> 1;       // 4 x 32 cols
    const int m0w = warp_m * 64;
    const int n0w = warp_n * 32;

    // ldmatrix lane address components
    const int a_row = lane & 15;               // row within 16-row frag
    const int a_kh  = lane >> 4;               // 0/1: k halves (8 elems)
    const int b_row = (lane & 7) + ((lane >> 4) & 1) * 8;   // n within 16
    const int b_kh  = (lane >> 3) & 1;

    float acc[4][4][4];
    #pragma unroll
    for (int i = 0; i < 4; i++)
        #pragma unroll
        for (int j = 0; j < 4; j++)
            #pragma unroll
            for (int q = 0; q < 4; q++) acc[i][j][q] = 0.0f;

    load_chunk(0, 0);

    for (int ci = 0; ci < NCHUNKS; ci++) {
        const int st = ci & 1;
        if (ci + 1 < NCHUNKS) load_chunk(ci + 1, (ci + 1) & 1);
        if (ci + 1 < NCHUNKS) asm volatile("cp.async.wait_group 1;\n" ::: "memory");
        else                  asm volatile("cp.async.wait_group 0;\n" ::: "memory");
        __syncthreads();

        const uint32_t ah_b = sbase + st * STAGE_B;
        const uint32_t al_b = ah_b + TILE_B;
        const uint32_t bh_b = ah_b + 2 * TILE_B;
        const uint32_t bl_b = ah_b + 3 * TILE_B;

        #pragma unroll
        for (int ks = 0; ks < 2; ks++) {
            // A fragments (4 m-frags x hi/lo)
            uint32_t ah[4][4], al[4][4];
            #pragma unroll
            for (int mi = 0; mi < 4; mi++) {
                const int r = m0w + mi * 16 + a_row;
                const int c = ks * 2 + a_kh;
                const uint32_t off = r * 64 + ((uint32_t)(c ^ ((r >> 1) & 3)) << 4);
                ldsm_x4(ah[mi][0], ah[mi][1], ah[mi][2], ah[mi][3], ah_b + off);
                ldsm_x4(al[mi][0], al[mi][1], al[mi][2], al[mi][3], al_b + off);
            }
            // B fragments (2 x4 loads cover 4 n-frags) x hi/lo
            uint32_t bh[4][2], bl[4][2];
            #pragma unroll
            for (int jb = 0; jb < 2; jb++) {
                const int r = n0w + jb * 16 + b_row;
                const int c = ks * 2 + b_kh;
                const uint32_t off = r * 64 + ((uint32_t)(c ^ ((r >> 1) & 3)) << 4);
                ldsm_x4(bh[2*jb][0], bh[2*jb][1], bh[2*jb+1][0], bh[2*jb+1][1], bh_b + off);
                ldsm_x4(bl[2*jb][0], bl[2*jb][1], bl[2*jb+1][0], bl[2*jb+1][1], bl_b + off);
            }
            #pragma unroll
            for (int mi = 0; mi < 4; mi++)
                #pragma unroll
                for (int nj = 0; nj < 4; nj++) {
                    float* cc = acc[mi][nj];
                    mma16816(cc[0], cc[1], cc[2], cc[3],
                             ah[mi][0], ah[mi][1], ah[mi][2], ah[mi][3],
                             bh[nj][0], bh[nj][1]);
                    mma16816(cc[0], cc[1], cc[2], cc[3],
                             ah[mi][0], ah[mi][1], ah[mi][2], ah[mi][3],
                             bl[nj][0], bl[nj][1]);
                    mma16816(cc[0], cc[1], cc[2], cc[3],
                             al[mi][0], al[mi][1], al[mi][2], al[mi][3],
                             bh[nj][0], bh[nj][1]);
                }
        }
        __syncthreads();
    }

    // ---- epilogue: write acc to C ----
    const int er = lane >> 2;          // 0..7
    const int ec = (lane & 3) * 2;
    #pragma unroll
    for (int mi = 0; mi < 4; mi++) {
        const int row_a = m0 + m0w + mi * 16 + er;
        #pragma unroll
        for (int nj = 0; nj < 4; nj++) {
            const int col = n0 + n0w + nj * 8 + ec;
            float* cc = acc[mi][nj];
            *reinterpret_cast<float2*>(C + (size_t)row_a * ldc + col) =
                make_float2(cc[0], cc[1]);
            *reinterpret_cast<float2*>(C + (size_t)(row_a + 8) * ldc + col) =
                make_float2(cc[2], cc[3]);
        }
    }
}

// ---------------------------------------------------------------------------
// RoPE
// ---------------------------------------------------------------------------
__global__ void rope_table_kernel()
{
    int idx = blockIdx.x * blockDim.x + threadIdx.x;
    if (idx >= SEQ * 64) return;
    int pos = idx >> 6, i = idx & 63;
    double inv = exp2(-(double)i * (13.287712379549449 / 64.0));
    double ang = (double)pos * inv;
    const double twopi = 6.283185307179586476925286766559;
    ang -= floor(ang * (1.0 / twopi)) * twopi;
    if (ang > 3.14159265358979323846) ang -= twopi;
    float s, c;
    sincosf((float)ang, &s, &c);
    g_cos[idx] = c;
    g_sin[idx] = s;
}

__global__ void rope_apply_kernel(float* __restrict__ buf, int heads, int npairs)
{
    int idx = blockIdx.x * blockDim.x + threadIdx.x;
    if (idx >= npairs) return;
    int i    = idx & 63;
    int hp   = idx >> 6;
    int head = hp % heads;
    int row  = hp / heads;
    int pos  = row & (SEQ - 1);
    size_t base = (size_t)row * heads * HDIM + head * HDIM + i;
    float c = g_cos[pos*64 + i];
    float s = g_sin[pos*64 + i];
    float x1 = buf[base];
    float x2 = buf[base + 64];
    buf[base]      = x1 * c - x2 * s;
    buf[base + 64] = x2 * c + x1 * s;
}

// ---------------------------------------------------------------------------
// Flash attention (fp32, unchanged)
// ---------------------------------------------------------------------------
#define ATT_SMEM (29184*4)

__global__ __launch_bounds__(256)
void flash_kernel(const float* __restrict__ Q, const float* __restrict__ Kb,
                  const float* __restrict__ Vb, float* __restrict__ ctx)
{
    extern __shared__ float sm[];
    float* Qs = sm;            // [128][64] transposed+swizzled
    float* Ks = sm + 8192;     // [128][64] transposed+swizzled
    float* Vs = sm + 16384;    // [64][132] natural, padded
    float* Ps = sm + 24832;    // [64][68]  probs, padded

    const int tid = threadIdx.x;
    const int tx = tid & 15, ty = tid >> 4;
    const int qt = blockIdx.x, h = blockIdx.y, b = blockIdx.z;
    const int kvh = h >> 2;
    const int qrow0 = b * SEQ + qt * 64;
    const float scale = 0.08838834764831845f;

    for (int idx = tid; idx < 2048; idx += 256) {
        int r = idx >> 5, c4 = idx & 31, d0 = c4 << 2;
        float4 v = *reinterpret_cast<const float4*>(
            Q + (size_t)(qrow0 + r) * QCOLS + h * HDIM + d0);
        float vv[4] = {v.x, v.y, v.z, v.w};
        #pragma unroll
        for (int q = 0; q < 4; q++) {
            int d = d0 + q;
            Qs[(d << 6) + ((((r >> 2) ^ ((d >> 2) & 15))) << 2) + (r & 3)] = vv[q];
        }
    }

    float o[32];
    #pragma unroll
    for (int i = 0; i < 32; i++) o[i] = 0.0f;
    float mi[4] = {-1e30f, -1e30f, -1e30f, -1e30f};
    float li[4] = {0.0f, 0.0f, 0.0f, 0.0f};

    for (int kt = 0; kt <= qt; kt++) {
        const int krow0 = b * SEQ + kt * 64;
        for (int idx = tid; idx < 2048; idx += 256) {
            int r = idx >> 5, c4 = idx & 31, d0 = c4 << 2;
            float4 v = *reinterpret_cast<const float4*>(
                Kb + (size_t)(krow0 + r) * KCOLS + kvh * HDIM + d0);
            float vv[4] = {v.x, v.y, v.z, v.w};
            #pragma unroll
            for (int q = 0; q < 4; q++) {
                int d = d0 + q;
                Ks[(d << 6) + ((((r >> 2) ^ ((d >> 2) & 15))) << 2) + (r & 3)] = vv[q];
            }
            float4 w = *reinterpret_cast<const float4*>(
                Vb + (size_t)(krow0 + r) * KCOLS + kvh * HDIM + d0);
            *reinterpret_cast<float4*>(Vs + r * 132 + d0) = w;
        }
        __syncthreads();

        float s[4][4];
        #pragma unroll
        for (int i = 0; i < 4; i++)
            #pragma unroll
            for (int j = 0; j < 4; j++) s[i][j] = 0.0f;

        #pragma unroll 8
        for (int d = 0; d < 128; d++) {
            const int sw = (d >> 2) & 15;
            const float4 a  = *reinterpret_cast<const float4*>(Qs + (d << 6) + ((ty ^ sw) << 2));
            const float4 kk = *reinterpret_cast<const float4*>(Ks + (d << 6) + ((tx ^ sw) << 2));
            const float aa[4] = {a.x, a.y, a.z, a.w};
            const float bb[4] = {kk.x, kk.y, kk.z, kk.w};
            #pragma unroll
            for (int i = 0; i < 4; i++)
                #pragma unroll
                for (int j = 0; j < 4; j++)
                    s[i][j] += aa[i] * bb[j];
        }

        #pragma unroll
        for (int i = 0; i < 4; i++)
            #pragma unroll
            for (int j = 0; j < 4; j++) s[i][j] *= scale;
        if (kt == qt) {
            #pragma unroll
            for (int i = 0; i < 4; i++)
                #pragma unroll
                for (int j = 0; j < 4; j++)
                    if ((tx << 2) + j > (ty << 2) + i) s[i][j] = -1e30f;
        }

        #pragma unroll
        for (int i = 0; i < 4; i++) {
            float rm = fmaxf(fmaxf(s[i][0], s[i][1]), fmaxf(s[i][2], s[i][3]));
            #pragma unroll
            for (int off = 1; off < 16; off <<= 1)
                rm = fmaxf(rm, __shfl_xor_sync(0xffffffffu, rm, off));
            float mnew = fmaxf(mi[i], rm);
            float corr = __expf(mi[i] - mnew);
            mi[i] = mnew;
            float rs = 0.0f;
            #pragma unroll
            for (int j = 0; j < 4; j++) {
                s[i][j] = __expf(s[i][j] - mnew);
                rs += s[i][j];
            }
            #pragma unroll
            for (int off = 1; off < 16; off <<= 1)
                rs += __shfl_xor_sync(0xffffffffu, rs, off);
            li[i] = li[i] * corr + rs;
            #pragma unroll
            for (int e = 0; e < 8; e++) o[i*8 + e] *= corr;
            *reinterpret_cast<float4*>(Ps + (4*ty + i) * 68 + 4*tx) =
                make_float4(s[i][0], s[i][1], s[i][2], s[i][3]);
        }
        __syncthreads();

        #pragma unroll 2
        for (int j = 0; j < 64; j++) {
            const float4 v0 = *reinterpret_cast<const float4*>(Vs + j * 132 + tx*4);
            const float4 v1 = *reinterpret_cast<const float4*>(Vs + j * 132 + 64 + tx*4);
            #pragma unroll
            for (int i = 0; i < 4; i++) {
                const float a = Ps[(4*ty + i) * 68 + j];
                o[i*8+0] += a * v0.x; o[i*8+1] += a * v0.y;
                o[i*8+2] += a * v0.z; o[i*8+3] += a * v0.w;
                o[i*8+4] += a * v1.x; o[i*8+5] += a * v1.y;
                o[i*8+6] += a * v1.z; o[i*8+7] += a * v1.w;
            }
        }
        __syncthreads();
    }

    #pragma unroll
    for (int i = 0; i < 4; i++) {
        const float inv = 1.0f / li[i];
        float* crow = ctx + (size_t)(qrow0 + 4*ty + i) * QCOLS + h * HDIM;
        float4 v0 = make_float4(o[i*8+0]*inv, o[i*8+1]*inv, o[i*8+2]*inv, o[i*8+3]*inv);
        float4 v1 = make_float4(o[i*8+4]*inv, o[i*8+5]*inv, o[i*8+6]*inv, o[i*8+7]*inv);
        *reinterpret_cast<float4*>(crow + tx*4)      = v0;
        *reinterpret_cast<float4*>(crow + 64 + tx*4) = v1;
    }
}

// ---------------------------------------------------------------------------
extern "C" void kernel_launch(void* const* d_in, const int* in_sizes, int n_in,
                              void* d_out, int out_size)
{
    const float* hidden = (const float*)d_in[0];
    const float* Wq = (const float*)d_in[1];
    const float* Wk = (const float*)d_in[2];
    const float* Wv = (const float*)d_in[3];
    const float* Wo = (const float*)d_in[4];
    float* out = (float*)d_out;

    float *qb, *kb, *vb, *cb;
    __nv_bfloat16 *ah, *al, *ch, *cl, *wqh, *wql, *wkh, *wkl, *wvh, *wvl, *woh, *wol;
    cudaGetSymbolAddress((void**)&qb, g_q);
    cudaGetSymbolAddress((void**)&kb, g_k);
    cudaGetSymbolAddress((void**)&vb, g_v);
    cudaGetSymbolAddress((void**)&cb, g_ctx);
    cudaGetSymbolAddress((void**)&ah, g_ah);  cudaGetSymbolAddress((void**)&al, g_al);
    cudaGetSymbolAddress((void**)&ch, g_ch);  cudaGetSymbolAddress((void**)&cl, g_cl);
    cudaGetSymbolAddress((void**)&wqh, g_wqh); cudaGetSymbolAddress((void**)&wql, g_wql);
    cudaGetSymbolAddress((void**)&wkh, g_wkh); cudaGetSymbolAddress((void**)&wkl, g_wkl);
    cudaGetSymbolAddress((void**)&wvh, g_wvh); cudaGetSymbolAddress((void**)&wvl, g_wvl);
    cudaGetSymbolAddress((void**)&woh, g_woh); cudaGetSymbolAddress((void**)&wol, g_wol);

    cudaFuncSetAttribute(flash_kernel,
                         cudaFuncAttributeMaxDynamicSharedMemorySize, ATT_SMEM);
    cudaFuncSetAttribute(gemm_mma,
                         cudaFuncAttributeMaxDynamicSharedMemorySize, GEMM_SMEM);

    // Split/transpose inputs to bf16 hi/lo
    split_kernel<<<(ROWS*HID/4 + 255)/256, 256>>>(hidden, ah, al, ROWS*HID/4);
    tsplit_kernel<<<dim3(QCOLS/32, HID/32), dim3(32,8)>>>(Wq, wqh, wql, HID, QCOLS);
    tsplit_kernel<<<dim3(KCOLS/32, HID/32), dim3(32,8)>>>(Wk, wkh, wkl, HID, KCOLS);
    tsplit_kernel<<<dim3(KCOLS/32, HID/32), dim3(32,8)>>>(Wv, wvh, wvl, HID, KCOLS);
    tsplit_kernel<<<dim3(HID/32, QCOLS/32), dim3(32,8)>>>(Wo, woh, wol, QCOLS, HID);

    // QKV projections on tensor cores (mma.sync)
    gemm_mma<<<dim3(QCOLS/128, ROWS/128), 256, GEMM_SMEM>>>(ah, al, wqh, wql, qb, QCOLS);
    gemm_mma<<<dim3(KCOLS/128, ROWS/128), 256, GEMM_SMEM>>>(ah, al, wkh, wkl, kb, KCOLS);
    gemm_mma<<<dim3(KCOLS/128, ROWS/128), 256, GEMM_SMEM>>>(ah, al, wvh, wvl, vb, KCOLS);

    // RoPE
    rope_table_kernel<<<(SEQ*64 + 255)/256, 256>>>();
    int npq = ROWS * NHQ * 64;
    int npk = ROWS * NKV * 64;
    rope_apply_kernel<<<(npq + 255)/256, 256>>>(qb, NHQ, npq);
    rope_apply_kernel<<<(npk + 255)/256, 256>>>(kb, NKV, npk);

    // Attention
    flash_kernel<<<dim3(SEQ/64, NHQ, BATCH), 256, ATT_SMEM>>>(qb, kb, vb, cb);

    // Output projection on tensor cores
    split_kernel<<<(ROWS*QCOLS/4 + 255)/256, 256>>>(cb, ch, cl, ROWS*QCOLS/4);
    gemm_mma<<<dim3(HID/128, ROWS/128), 256, GEMM_SMEM>>>(ch, cl, woh, wol, out, HID);
}

// round 4
// speedup vs baseline: 2.8501x; 1.7895x over previous
#include <cuda_runtime.h>
#include <cuda_bf16.h>
#include <math.h>
#include <stdint.h>

// Problem constants
#define BATCH 2
#define SEQ   2048
#define HID   2048
#define NHQ   16
#define NKV   4
#define HDIM  128
#define ROWS  (BATCH*SEQ)          // 4096
#define QCOLS (NHQ*HDIM)           // 2048
#define KCOLS (NKV*HDIM)           // 512

// ---------------------------------------------------------------------------
// Device scratch (static — no allocation allowed)
// ---------------------------------------------------------------------------
__device__ float g_q[ROWS*QCOLS];
__device__ float g_k[ROWS*KCOLS];
__device__ float g_v[ROWS*KCOLS];
__device__ float g_cos[SEQ*64];
__device__ float g_sin[SEQ*64];

// bf16 hi/lo buffers
__device__ __nv_bfloat16 g_ah[ROWS*HID],    g_al[ROWS*HID];     // hidden
__device__ __nv_bfloat16 g_ch[ROWS*QCOLS],  g_cl[ROWS*QCOLS];   // ctx (flash out)
__device__ __nv_bfloat16 g_qh[ROWS*QCOLS],  g_ql[ROWS*QCOLS];   // q (rope+scale)
__device__ __nv_bfloat16 g_kh[ROWS*KCOLS],  g_kl[ROWS*KCOLS];   // k (rope)
__device__ __nv_bfloat16 g_vh[ROWS*KCOLS],  g_vl[ROWS*KCOLS];   // v
__device__ __nv_bfloat16 g_wqh[QCOLS*HID],  g_wql[QCOLS*HID];   // Wq^T
__device__ __nv_bfloat16 g_wkh[KCOLS*HID],  g_wkl[KCOLS*HID];   // Wk^T
__device__ __nv_bfloat16 g_wvh[KCOLS*HID],  g_wvl[KCOLS*HID];   // Wv^T
__device__ __nv_bfloat16 g_woh[HID*QCOLS],  g_wol[HID*QCOLS];   // Wo^T

// ---------------------------------------------------------------------------
// Helpers
// ---------------------------------------------------------------------------
__device__ __forceinline__ uint32_t smem_u32(const void* p) {
    uint32_t a;
    asm("{ .reg .u64 t; cvta.to.shared.u64 t, %1; cvt.u32.u64 %0, t; }" : "=r"(a) : "l"(p));
    return a;
}
__device__ __forceinline__ void cp_async16(uint32_t dst, const void* src) {
    asm volatile("cp.async.cg.shared.global [%0], [%1], 16;\n" :: "r"(dst), "l"(src) : "memory");
}
__device__ __forceinline__ void ldsm_x4(uint32_t& r0, uint32_t& r1, uint32_t& r2, uint32_t& r3,
                                        uint32_t addr) {
    asm volatile("ldmatrix.sync.aligned.m8n8.x4.shared.b16 {%0,%1,%2,%3}, [%4];"
                 : "=r"(r0), "=r"(r1), "=r"(r2), "=r"(r3) : "r"(addr));
}
__device__ __forceinline__ void ldsm_x4t(uint32_t& r0, uint32_t& r1, uint32_t& r2, uint32_t& r3,
                                         uint32_t addr) {
    asm volatile("ldmatrix.sync.aligned.m8n8.x4.trans.shared.b16 {%0,%1,%2,%3}, [%4];"
                 : "=r"(r0), "=r"(r1), "=r"(r2), "=r"(r3) : "r"(addr));
}
__device__ __forceinline__ void mma16816(float& c0, float& c1, float& c2, float& c3,
                                         uint32_t a0, uint32_t a1, uint32_t a2, uint32_t a3,
                                         uint32_t b0, uint32_t b1) {
    asm volatile(
        "mma.sync.aligned.m16n8k16.row.col.f32.bf16.bf16.f32 "
        "{%0,%1,%2,%3}, {%4,%5,%6,%7}, {%8,%9}, {%0,%1,%2,%3};"
        : "+f"(c0), "+f"(c1), "+f"(c2), "+f"(c3)
        : "r"(a0), "r"(a1), "r"(a2), "r"(a3), "r"(b0), "r"(b1));
}
// swizzled smem offset: row r (256B rows of bf16[128]), 16B chunk c (0..15)
#define SW(r, c) ((uint32_t)((r) * 256 + (((c) ^ ((r) & 7)) << 4)))

// ---------------------------------------------------------------------------
// fp32 -> bf16 hi/lo split (row-major, same layout)
// ---------------------------------------------------------------------------
__global__ void split_kernel(const float* __restrict__ in,
                             __nv_bfloat16* __restrict__ hi,
                             __nv_bfloat16* __restrict__ lo, int n4)
{
    int i = blockIdx.x * blockDim.x + threadIdx.x;
    if (i >= n4) return;
    float4 v = reinterpret_cast<const float4*>(in)[i];
    __nv_bfloat16 h0 = __float2bfloat16_rn(v.x);
    __nv_bfloat16 h1 = __float2bfloat16_rn(v.y);
    __nv_bfloat16 h2 = __float2bfloat16_rn(v.z);
    __nv_bfloat16 h3 = __float2bfloat16_rn(v.w);
    __nv_bfloat16 l0 = __float2bfloat16_rn(v.x - __bfloat162float(h0));
    __nv_bfloat16 l1 = __float2bfloat16_rn(v.y - __bfloat162float(h1));
    __nv_bfloat16 l2 = __float2bfloat16_rn(v.z - __bfloat162float(h2));
    __nv_bfloat16 l3 = __float2bfloat16_rn(v.w - __bfloat162float(h3));
    __nv_bfloat162* hp = reinterpret_cast<__nv_bfloat162*>(hi);
    __nv_bfloat162* lp = reinterpret_cast<__nv_bfloat162*>(lo);
    hp[2*i]   = __nv_bfloat162(h0, h1);
    hp[2*i+1] = __nv_bfloat162(h2, h3);
    lp[2*i]   = __nv_bfloat162(l0, l1);
    lp[2*i+1] = __nv_bfloat162(l2, l3);
}

// fp32 [Kin][Nin] -> transposed bf16 hi/lo [Nin][Kin]
__global__ void tsplit_kernel(const float* __restrict__ in,
                              __nv_bfloat16* __restrict__ hiT,
                              __nv_bfloat16* __restrict__ loT, int Kin, int Nin)
{
    __shared__ float t[32][33];
    const int tx = threadIdx.x, ty = threadIdx.y;
    const int n0 = blockIdx.x * 32, k0 = blockIdx.y * 32;
    #pragma unroll
    for (int j = 0; j < 32; j += 8)
        t[ty + j][tx] = in[(size_t)(k0 + ty + j) * Nin + n0 + tx];
    __syncthreads();
    #pragma unroll
    for (int j = 0; j < 32; j += 8) {
        float x = t[tx][ty + j];
        __nv_bfloat16 h = __float2bfloat16_rn(x);
        __nv_bfloat16 l = __float2bfloat16_rn(x - __bfloat162float(h));
        size_t o = (size_t)(n0 + ty + j) * Kin + k0 + tx;
        hiT[o] = h;
        loT[o] = l;
    }
}

// ---------------------------------------------------------------------------
// GEMM via mma.sync (bf16 hi/lo 3-product) — unchanged from round 3
// ---------------------------------------------------------------------------
#define KCH       32
#define NCHUNKS   64
#define TILE_B    8192
#define STAGE_B   (4*TILE_B)
#define GEMM_SMEM (2*STAGE_B)

__global__ __launch_bounds__(256, 1)
void gemm_mma(const __nv_bfloat16* __restrict__ Ah, const __nv_bfloat16* __restrict__ Al,
              const __nv_bfloat16* __restrict__ Bh, const __nv_bfloat16* __restrict__ Bl,
              float* __restrict__ C, int ldc)
{
    extern __shared__ char dsm[];
    const uint32_t sbase = smem_u32(dsm);

    const int tid = threadIdx.x;
    const int wid = tid >> 5, lane = tid & 31;
    const int m0 = blockIdx.y * 128;
    const int n0 = blockIdx.x * 128;

    const int tt  = tid >> 6;
    const int t6  = tid & 63;
    const int lch = t6 & 3;
    const int lr0 = t6 >> 2;
    const __nv_bfloat16* gsrc;
    int row0;
    switch (tt) {
        case 0: gsrc = Ah; row0 = m0; break;
        case 1: gsrc = Al; row0 = m0; break;
        case 2: gsrc = Bh; row0 = n0; break;
        default: gsrc = Bl; row0 = n0; break;
    }

    auto load_chunk = [&](int ci, int st) {
        const uint32_t tb = sbase + st * STAGE_B + tt * TILE_B;
        #pragma unroll
        for (int i = 0; i < 8; i++) {
            const int r = lr0 + i * 16;
            const uint32_t dst = tb + r * 64 + ((uint32_t)(lch ^ ((r >> 1) & 3)) << 4);
            cp_async16(dst, gsrc + (size_t)(row0 + r) * 2048 + ci * KCH + lch * 8);
        }
        asm volatile("cp.async.commit_group;\n" ::: "memory");
    };

    const int warp_m = wid & 1;
    const int warp_n = wid >> 1;
    const int m0w = warp_m * 64;
    const int n0w = warp_n * 32;

    const int a_row = lane & 15;
    const int a_kh  = lane >> 4;
    const int b_row = (lane & 7) + ((lane >> 4) & 1) * 8;
    const int b_kh  = (lane >> 3) & 1;

    float acc[4][4][4];
    #pragma unroll
    for (int i = 0; i < 4; i++)
        #pragma unroll
        for (int j = 0; j < 4; j++)
            #pragma unroll
            for (int q = 0; q < 4; q++) acc[i][j][q] = 0.0f;

    load_chunk(0, 0);

    for (int ci = 0; ci < NCHUNKS; ci++) {
        const int st = ci & 1;
        if (ci + 1 < NCHUNKS) load_chunk(ci + 1, (ci + 1) & 1);
        if (ci + 1 < NCHUNKS) asm volatile("cp.async.wait_group 1;\n" ::: "memory");
        else                  asm volatile("cp.async.wait_group 0;\n" ::: "memory");
        __syncthreads();

        const uint32_t ah_b = sbase + st * STAGE_B;
        const uint32_t al_b = ah_b + TILE_B;
        const uint32_t bh_b = ah_b + 2 * TILE_B;
        const uint32_t bl_b = ah_b + 3 * TILE_B;

        #pragma unroll
        for (int ks = 0; ks < 2; ks++) {
            uint32_t ah[4][4], al[4][4];
            #pragma unroll
            for (int mi = 0; mi < 4; mi++) {
                const int r = m0w + mi * 16 + a_row;
                const int c = ks * 2 + a_kh;
                const uint32_t off = r * 64 + ((uint32_t)(c ^ ((r >> 1) & 3)) << 4);
                ldsm_x4(ah[mi][0], ah[mi][1], ah[mi][2], ah[mi][3], ah_b + off);
                ldsm_x4(al[mi][0], al[mi][1], al[mi][2], al[mi][3], al_b + off);
            }
            uint32_t bh[4][2], bl[4][2];
            #pragma unroll
            for (int jb = 0; jb < 2; jb++) {
                const int r = n0w + jb * 16 + b_row;
                const int c = ks * 2 + b_kh;
                const uint32_t off = r * 64 + ((uint32_t)(c ^ ((r >> 1) & 3)) << 4);
                ldsm_x4(bh[2*jb][0], bh[2*jb][1], bh[2*jb+1][0], bh[2*jb+1][1], bh_b + off);
                ldsm_x4(bl[2*jb][0], bl[2*jb][1], bl[2*jb+1][0], bl[2*jb+1][1], bl_b + off);
            }
            #pragma unroll
            for (int mi = 0; mi < 4; mi++)
                #pragma unroll
                for (int nj = 0; nj < 4; nj++) {
                    float* cc = acc[mi][nj];
                    mma16816(cc[0], cc[1], cc[2], cc[3],
                             ah[mi][0], ah[mi][1], ah[mi][2], ah[mi][3],
                             bh[nj][0], bh[nj][1]);
                    mma16816(cc[0], cc[1], cc[2], cc[3],
                             ah[mi][0], ah[mi][1], ah[mi][2], ah[mi][3],
                             bl[nj][0], bl[nj][1]);
                    mma16816(cc[0], cc[1], cc[2], cc[3],
                             al[mi][0], al[mi][1], al[mi][2], al[mi][3],
                             bh[nj][0], bh[nj][1]);
                }
        }
        __syncthreads();
    }

    const int er = lane >> 2;
    const int ec = (lane & 3) * 2;
    #pragma unroll
    for (int mi = 0; mi < 4; mi++) {
        const int row_a = m0 + m0w + mi * 16 + er;
        #pragma unroll
        for (int nj = 0; nj < 4; nj++) {
            const int col = n0 + n0w + nj * 8 + ec;
            float* cc = acc[mi][nj];
            *reinterpret_cast<float2*>(C + (size_t)row_a * ldc + col) =
                make_float2(cc[0], cc[1]);
            *reinterpret_cast<float2*>(C + (size_t)(row_a + 8) * ldc + col) =
                make_float2(cc[2], cc[3]);
        }
    }
}

// ---------------------------------------------------------------------------
// RoPE: table + fused apply/scale/split
// ---------------------------------------------------------------------------
__global__ void rope_table_kernel()
{
    int idx = blockIdx.x * blockDim.x + threadIdx.x;
    if (idx >= SEQ * 64) return;
    int pos = idx >> 6, i = idx & 63;
    double inv = exp2(-(double)i * (13.287712379549449 / 64.0));
    double ang = (double)pos * inv;
    const double twopi = 6.283185307179586476925286766559;
    ang -= floor(ang * (1.0 / twopi)) * twopi;
    if (ang > 3.14159265358979323846) ang -= twopi;
    float s, c;
    sincosf((float)ang, &s, &c);
    g_cos[idx] = c;
    g_sin[idx] = s;
}

__global__ void rope_split_kernel(const float* __restrict__ buf,
                                  __nv_bfloat16* __restrict__ oh,
                                  __nv_bfloat16* __restrict__ ol,
                                  int heads, int npairs, float scale)
{
    int idx = blockIdx.x * blockDim.x + threadIdx.x;
    if (idx >= npairs) return;
    int i    = idx & 63;
    int hp   = idx >> 6;
    int head = hp % heads;
    int row  = hp / heads;
    int pos  = row & (SEQ - 1);
    size_t base = (size_t)row * heads * HDIM + head * HDIM + i;
    float c = g_cos[pos*64 + i];
    float s = g_sin[pos*64 + i];
    float x1 = buf[base];
    float x2 = buf[base + 64];
    float y1 = (x1 * c - x2 * s) * scale;
    float y2 = (x2 * c + x1 * s) * scale;
    __nv_bfloat16 h1 = __float2bfloat16_rn(y1);
    __nv_bfloat16 h2 = __float2bfloat16_rn(y2);
    oh[base]      = h1;
    oh[base + 64] = h2;
    ol[base]      = __float2bfloat16_rn(y1 - __bfloat162float(h1));
    ol[base + 64] = __float2bfloat16_rn(y2 - __bfloat162float(h2));
}

// ---------------------------------------------------------------------------
// Flash attention on tensor cores (hi/lo 3-product for both QK^T and PV).
// CTA: 128 Q-rows x head x batch. 8 warps x 16 rows. K-tile 64 keys.
// Smem: Qh,Ql [128][128]bf16 + 2 stages x {Kh,Kl,Vh,Vl}[64][128]bf16 = 192KB.
// Writes ctx directly as bf16 hi/lo (A operand of the output projection).
// ---------------------------------------------------------------------------
#define FQT 128
#define FKT 64
#define FQ_B    32768           // 128*256
#define FTILE_B 16384           // 64*256
#define FKV_B   (4*FTILE_B)     // 64KB per stage
#define FLASH_SMEM (2*FQ_B + 2*FKV_B)   // 192KB

__global__ __launch_bounds__(256, 1)
void flash_mma(const __nv_bfloat16* __restrict__ Qh_g, const __nv_bfloat16* __restrict__ Ql_g,
               const __nv_bfloat16* __restrict__ Kh_g, const __nv_bfloat16* __restrict__ Kl_g,
               const __nv_bfloat16* __restrict__ Vh_g, const __nv_bfloat16* __restrict__ Vl_g,
               __nv_bfloat16* __restrict__ Ch_g, __nv_bfloat16* __restrict__ Cl_g)
{
    extern __shared__ char dsm[];
    const uint32_t sb = smem_u32(dsm);
    const uint32_t Qh_s = sb, Ql_s = sb + FQ_B;
    const uint32_t KV_s = sb + 2 * FQ_B;

    const int tid = threadIdx.x;
    const int w = tid >> 5, lane = tid & 31;
    const int qt = blockIdx.x, h = blockIdx.y, b = blockIdx.z;
    const int kvh = h >> 2;
    const int qrow0 = b * SEQ + qt * FQT;
    const int nkt = 2 * qt + 2;

    // ---- Q load (once): 128 rows x 16 chunks, both hi and lo ----
    {
        const int c = tid & 15, r0 = tid >> 4;
        #pragma unroll
        for (int i = 0; i < 8; i++) {
            const int r = r0 + i * 16;
            const size_t go = (size_t)(qrow0 + r) * QCOLS + h * HDIM + c * 8;
            cp_async16(Qh_s + SW(r, c), Qh_g + go);
            cp_async16(Ql_s + SW(r, c), Ql_g + go);
        }
    }

    // KV stage loader
    auto load_kv = [&](int kt, int st) {
        const int c = tid & 15, r0 = tid >> 4;
        const uint32_t base = KV_s + st * FKV_B;
        const int krow0 = b * SEQ + kt * FKT;
        #pragma unroll
        for (int i = 0; i < 4; i++) {
            const int r = r0 + i * 16;
            const size_t go = (size_t)(krow0 + r) * KCOLS + kvh * HDIM + c * 8;
            cp_async16(base +             SW(r, c), Kh_g + go);
            cp_async16(base +   FTILE_B + SW(r, c), Kl_g + go);
            cp_async16(base + 2*FTILE_B + SW(r, c), Vh_g + go);
            cp_async16(base + 3*FTILE_B + SW(r, c), Vl_g + go);
        }
        asm volatile("cp.async.commit_group;\n" ::: "memory");
    };

    load_kv(0, 0);
    asm volatile("cp.async.commit_group;\n" ::: "memory");  // empty group (Q rides group 0)

    // lane mappings
    const int er = lane >> 2, ec = lane & 3;
    const int a_row = w * 16 + (lane & 15);
    const int a_kh  = lane >> 4;
    const int b_n   = (lane & 7) + ((lane >> 4) & 1) * 8;
    const int b_kh  = (lane >> 3) & 1;
    const int v_key = (lane & 7) + ((lane >> 3) & 1) * 8;
    const int v_dc  = lane >> 4;

    const int rg0 = qt * FQT + w * 16 + er;   // global q position, row half 0
    const int rg1 = rg0 + 8;

    float o[16][4];
    #pragma unroll
    for (int j = 0; j < 16; j++)
        #pragma unroll
        for (int q = 0; q < 4; q++) o[j][q] = 0.0f;
    float m0 = -1e30f, m1 = -1e30f, l0 = 0.0f, l1 = 0.0f;

    for (int kt = 0; kt < nkt; kt++) {
        const int st = kt & 1;
        if (kt + 1 < nkt) {
            load_kv(kt + 1, (kt + 1) & 1);
            asm volatile("cp.async.wait_group 1;\n" ::: "memory");
        } else {
            asm volatile("cp.async.wait_group 0;\n" ::: "memory");
        }
        __syncthreads();

        const uint32_t Kh_s = KV_s + st * FKV_B;
        const uint32_t Kl_s = Kh_s + FTILE_B;
        const uint32_t Vh_s = Kh_s + 2 * FTILE_B;
        const uint32_t Vl_s = Kh_s + 3 * FTILE_B;

        // ---- S = Q K^T (16 rows x 64 keys per warp) ----
        float s[8][4];
        #pragma unroll
        for (int f = 0; f < 8; f++)
            #pragma unroll
            for (int q = 0; q < 4; q++) s[f][q] = 0.0f;

        #pragma unroll
        for (int ks = 0; ks < 8; ks++) {
            uint32_t qah[4], qal[4];
            ldsm_x4(qah[0], qah[1], qah[2], qah[3], Qh_s + SW(a_row, ks*2 + a_kh));
            ldsm_x4(qal[0], qal[1], qal[2], qal[3], Ql_s + SW(a_row, ks*2 + a_kh));
            #pragma unroll
            for (int ng = 0; ng < 4; ng++) {
                uint32_t kh0, kh1, kh2, kh3, kl0, kl1, kl2, kl3;
                ldsm_x4(kh0, kh1, kh2, kh3, Kh_s + SW(ng*16 + b_n, ks*2 + b_kh));
                ldsm_x4(kl0, kl1, kl2, kl3, Kl_s + SW(ng*16 + b_n, ks*2 + b_kh));
                float* s0 = s[ng*2];
                float* s1 = s[ng*2 + 1];
                mma16816(s0[0], s0[1], s0[2], s0[3], qah[0], qah[1], qah[2], qah[3], kh0, kh1);
                mma16816(s0[0], s0[1], s0[2], s0[3], qah[0], qah[1], qah[2], qah[3], kl0, kl1);
                mma16816(s0[0], s0[1], s0[2], s0[3], qal[0], qal[1], qal[2], qal[3], kh0, kh1);
                mma16816(s1[0], s1[1], s1[2], s1[3], qah[0], qah[1], qah[2], qah[3], kh2, kh3);
                mma16816(s1[0], s1[1], s1[2], s1[3], qah[0], qah[1], qah[2], qah[3], kl2, kl3);
                mma16816(s1[0], s1[1], s1[2], s1[3], qal[0], qal[1], qal[2], qal[3], kh2, kh3);
            }
        }

        // ---- causal mask (only last two K-tiles can clip) ----
        if (kt >= 2 * qt) {
            #pragma unroll
            for (int f = 0; f < 8; f++) {
                const int key0 = kt * FKT + f * 8 + ec * 2;
                if (key0     > rg0) s[f][0] = -1e30f;
                if (key0 + 1 > rg0) s[f][1] = -1e30f;
                if (key0     > rg1) s[f][2] = -1e30f;
                if (key0 + 1 > rg1) s[f][3] = -1e30f;
            }
        }

        // ---- online softmax ----
        float nm0 = -1e30f, nm1 = -1e30f;
        #pragma unroll
        for (int f = 0; f < 8; f++) {
            nm0 = fmaxf(nm0, fmaxf(s[f][0], s[f][1]));
            nm1 = fmaxf(nm1, fmaxf(s[f][2], s[f][3]));
        }
        nm0 = fmaxf(nm0, __shfl_xor_sync(0xffffffffu, nm0, 1));
        nm0 = fmaxf(nm0, __shfl_xor_sync(0xffffffffu, nm0, 2));
        nm1 = fmaxf(nm1, __shfl_xor_sync(0xffffffffu, nm1, 1));
        nm1 = fmaxf(nm1, __shfl_xor_sync(0xffffffffu, nm1, 2));
        nm0 = fmaxf(nm0, m0);
        nm1 = fmaxf(nm1, m1);
        const float corr0 = __expf(m0 - nm0);
        const float corr1 = __expf(m1 - nm1);
        m0 = nm0;
        m1 = nm1;

        float rs0 = 0.0f, rs1 = 0.0f;
        #pragma unroll
        for (int f = 0; f < 8; f++) {
            s[f][0] = __expf(s[f][0] - nm0);
            s[f][1] = __expf(s[f][1] - nm0);
            s[f][2] = __expf(s[f][2] - nm1);
            s[f][3] = __expf(s[f][3] - nm1);
            rs0 += s[f][0] + s[f][1];
            rs1 += s[f][2] + s[f][3];
        }
        rs0 += __shfl_xor_sync(0xffffffffu, rs0, 1);
        rs0 += __shfl_xor_sync(0xffffffffu, rs0, 2);
        rs1 += __shfl_xor_sync(0xffffffffu, rs1, 1);
        rs1 += __shfl_xor_sync(0xffffffffu, rs1, 2);
        l0 = l0 * corr0 + rs0;
        l1 = l1 * corr1 + rs1;
        #pragma unroll
        for (int j = 0; j < 16; j++) {
            o[j][0] *= corr0; o[j][1] *= corr0;
            o[j][2] *= corr1; o[j][3] *= corr1;
        }

        // ---- O += P V ----
        #pragma unroll
        for (int kp = 0; kp < 4; kp++) {
            // pack P hi/lo A-fragments from S frags 2kp, 2kp+1
            const float* f0 = s[2*kp];
            const float* f1 = s[2*kp + 1];
            uint32_t pah[4], pal[4];
            float r0a, r0b, r1a, r1b, r2a, r2b, r3a, r3b;
            __nv_bfloat162 h;
            h = __floats2bfloat162_rn(f0[0], f0[1]);
            r0a = f0[0] - __low2float(h); r0b = f0[1] - __high2float(h);
            pah[0] = *reinterpret_cast<uint32_t*>(&h);
            h = __floats2bfloat162_rn(f0[2], f0[3]);
            r1a = f0[2] - __low2float(h); r1b = f0[3] - __high2float(h);
            pah[1] = *reinterpret_cast<uint32_t*>(&h);
            h = __floats2bfloat162_rn(f1[0], f1[1]);
            r2a = f1[0] - __low2float(h); r2b = f1[1] - __high2float(h);
            pah[2] = *reinterpret_cast<uint32_t*>(&h);
            h = __floats2bfloat162_rn(f1[2], f1[3]);
            r3a = f1[2] - __low2float(h); r3b = f1[3] - __high2float(h);
            pah[3] = *reinterpret_cast<uint32_t*>(&h);
            h = __floats2bfloat162_rn(r0a, r0b); pal[0] = *reinterpret_cast<uint32_t*>(&h);
            h = __floats2bfloat162_rn(r1a, r1b); pal[1] = *reinterpret_cast<uint32_t*>(&h);
            h = __floats2bfloat162_rn(r2a, r2b); pal[2] = *reinterpret_cast<uint32_t*>(&h);
            h = __floats2bfloat162_rn(r3a, r3b); pal[3] = *reinterpret_cast<uint32_t*>(&h);

            #pragma unroll
            for (int nd = 0; nd < 8; nd++) {
                uint32_t vh0, vh1, vh2, vh3, vl0, vl1, vl2, vl3;
                ldsm_x4t(vh0, vh1, vh2, vh3, Vh_s + SW(kp*16 + v_key, nd*2 + v_dc));
                ldsm_x4t(vl0, vl1, vl2, vl3, Vl_s + SW(kp*16 + v_key, nd*2 + v_dc));
                float* o0 = o[nd*2];
                float* o1 = o[nd*2 + 1];
                mma16816(o0[0], o0[1], o0[2], o0[3], pah[0], pah[1], pah[2], pah[3], vh0, vh1);
                mma16816(o0[0], o0[1], o0[2], o0[3], pah[0], pah[1], pah[2], pah[3], vl0, vl1);
                mma16816(o0[0], o0[1], o0[2], o0[3], pal[0], pal[1], pal[2], pal[3], vh0, vh1);
                mma16816(o1[0], o1[1], o1[2], o1[3], pah[0], pah[1], pah[2], pah[3], vh2, vh3);
                mma16816(o1[0], o1[1], o1[2], o1[3], pah[0], pah[1], pah[2], pah[3], vl2, vl3);
                mma16816(o1[0], o1[1], o1[2], o1[3], pal[0], pal[1], pal[2], pal[3], vh2, vh3);
            }
        }
        __syncthreads();
    }

    // ---- epilogue: normalize, split hi/lo, store ----
    const float inv0 = 1.0f / l0;
    const float inv1 = 1.0f / l1;
    const size_t row0 = (size_t)(qrow0 + w * 16 + er);
    const size_t row1 = row0 + 8;
    #pragma unroll
    for (int j = 0; j < 16; j++) {
        const int col = h * HDIM + j * 8 + ec * 2;
        float x0 = o[j][0] * inv0, x1 = o[j][1] * inv0;
        float x2 = o[j][2] * inv1, x3 = o[j][3] * inv1;
        __nv_bfloat162 h01 = __floats2bfloat162_rn(x0, x1);
        __nv_bfloat162 h23 = __floats2bfloat162_rn(x2, x3);
        __nv_bfloat162 l01 = __floats2bfloat162_rn(x0 - __low2float(h01), x1 - __high2float(h01));
        __nv_bfloat162 l23 = __floats2bfloat162_rn(x2 - __low2float(h23), x3 - __high2float(h23));
        *reinterpret_cast<__nv_bfloat162*>(Ch_g + row0 * QCOLS + col) = h01;
        *reinterpret_cast<__nv_bfloat162*>(Cl_g + row0 * QCOLS + col) = l01;
        *reinterpret_cast<__nv_bfloat162*>(Ch_g + row1 * QCOLS + col) = h23;
        *reinterpret_cast<__nv_bfloat162*>(Cl_g + row1 * QCOLS + col) = l23;
    }
}

// ---------------------------------------------------------------------------
extern "C" void kernel_launch(void* const* d_in, const int* in_sizes, int n_in,
                              void* d_out, int out_size)
{
    const float* hidden = (const float*)d_in[0];
    const float* Wq = (const float*)d_in[1];
    const float* Wk = (const float*)d_in[2];
    const float* Wv = (const float*)d_in[3];
    const float* Wo = (const float*)d_in[4];
    float* out = (float*)d_out;

    float *qb, *kb, *vb;
    __nv_bfloat16 *ah, *al, *ch, *cl, *qh, *ql, *kh, *kl, *vh, *vl;
    __nv_bfloat16 *wqh, *wql, *wkh, *wkl, *wvh, *wvl, *woh, *wol;
    cudaGetSymbolAddress((void**)&qb, g_q);
    cudaGetSymbolAddress((void**)&kb, g_k);
    cudaGetSymbolAddress((void**)&vb, g_v);
    cudaGetSymbolAddress((void**)&ah, g_ah);  cudaGetSymbolAddress((void**)&al, g_al);
    cudaGetSymbolAddress((void**)&ch, g_ch);  cudaGetSymbolAddress((void**)&cl, g_cl);
    cudaGetSymbolAddress((void**)&qh, g_qh);  cudaGetSymbolAddress((void**)&ql, g_ql);
    cudaGetSymbolAddress((void**)&kh, g_kh);  cudaGetSymbolAddress((void**)&kl, g_kl);
    cudaGetSymbolAddress((void**)&vh, g_vh);  cudaGetSymbolAddress((void**)&vl, g_vl);
    cudaGetSymbolAddress((void**)&wqh, g_wqh); cudaGetSymbolAddress((void**)&wql, g_wql);
    cudaGetSymbolAddress((void**)&wkh, g_wkh); cudaGetSymbolAddress((void**)&wkl, g_wkl);
    cudaGetSymbolAddress((void**)&wvh, g_wvh); cudaGetSymbolAddress((void**)&wvl, g_wvl);
    cudaGetSymbolAddress((void**)&woh, g_woh); cudaGetSymbolAddress((void**)&wol, g_wol);

    cudaFuncSetAttribute(gemm_mma,
                         cudaFuncAttributeMaxDynamicSharedMemorySize, GEMM_SMEM);
    cudaFuncSetAttribute(flash_mma,
                         cudaFuncAttributeMaxDynamicSharedMemorySize, FLASH_SMEM);

    // Split/transpose inputs to bf16 hi/lo
    split_kernel<<<(ROWS*HID/4 + 255)/256, 256>>>(hidden, ah, al, ROWS*HID/4);
    tsplit_kernel<<<dim3(QCOLS/32, HID/32), dim3(32,8)>>>(Wq, wqh, wql, HID, QCOLS);
    tsplit_kernel<<<dim3(KCOLS/32, HID/32), dim3(32,8)>>>(Wk, wkh, wkl, HID, KCOLS);
    tsplit_kernel<<<dim3(KCOLS/32, HID/32), dim3(32,8)>>>(Wv, wvh, wvl, HID, KCOLS);
    tsplit_kernel<<<dim3(HID/32, QCOLS/32), dim3(32,8)>>>(Wo, woh, wol, QCOLS, HID);

    // QKV projections (tensor cores)
    gemm_mma<<<dim3(QCOLS/128, ROWS/128), 256, GEMM_SMEM>>>(ah, al, wqh, wql, qb, QCOLS);
    gemm_mma<<<dim3(KCOLS/128, ROWS/128), 256, GEMM_SMEM>>>(ah, al, wkh, wkl, kb, KCOLS);
    gemm_mma<<<dim3(KCOLS/128, ROWS/128), 256, GEMM_SMEM>>>(ah, al, wvh, wvl, vb, KCOLS);

    // RoPE + bf16 hi/lo split (scale folded into Q)
    rope_table_kernel<<<(SEQ*64 + 255)/256, 256>>>();
    const float att_scale = 0.08838834764831845f;   // 1/sqrt(128)
    rope_split_kernel<<<(ROWS*NHQ*64 + 255)/256, 256>>>(qb, qh, ql, NHQ, ROWS*NHQ*64, att_scale);
    rope_split_kernel<<<(ROWS*NKV*64 + 255)/256, 256>>>(kb, kh, kl, NKV, ROWS*NKV*64, 1.0f);
    split_kernel<<<(ROWS*KCOLS/4 + 255)/256, 256>>>(vb, vh, vl, ROWS*KCOLS/4);

    // Attention (tensor cores), writes ctx hi/lo directly
    flash_mma<<<dim3(SEQ/FQT, NHQ, BATCH), 256, FLASH_SMEM>>>(qh, ql, kh, kl, vh, vl, ch, cl);

    // Output projection (tensor cores)
    gemm_mma<<<dim3(HID/128, ROWS/128), 256, GEMM_SMEM>>>(ch, cl, woh, wol, out, HID);
}

// round 6
// speedup vs baseline: 3.1311x; 1.0986x over previous
#include <cuda_runtime.h>
#include <cuda_bf16.h>
#include <math.h>
#include <stdint.h>

// Problem constants
#define BATCH 2
#define SEQ   2048
#define HID   2048
#define NHQ   16
#define NKV   4
#define HDIM  128
#define ROWS  (BATCH*SEQ)          // 4096
#define QCOLS (NHQ*HDIM)           // 2048
#define KCOLS (NKV*HDIM)           // 512
#define QKVC  (QCOLS + 2*KCOLS)    // 3072

// ---------------------------------------------------------------------------
// Device scratch (static — no allocation allowed)
// ---------------------------------------------------------------------------
__device__ float g_qkv[ROWS*QKVC];      // merged QKV projection output
__device__ float g_cos[SEQ*64];
__device__ float g_sin[SEQ*64];

__device__ __nv_bfloat16 g_ah[ROWS*HID],    g_al[ROWS*HID];     // hidden
__device__ __nv_bfloat16 g_ch[ROWS*QCOLS],  g_cl[ROWS*QCOLS];   // ctx (flash out)
__device__ __nv_bfloat16 g_qh[ROWS*QCOLS],  g_ql[ROWS*QCOLS];   // q (rope+scale)
__device__ __nv_bfloat16 g_kh[ROWS*KCOLS],  g_kl[ROWS*KCOLS];   // k (rope)
__device__ __nv_bfloat16 g_vh[ROWS*KCOLS],  g_vl[ROWS*KCOLS];   // v
__device__ __nv_bfloat16 g_wh[QKVC*HID],    g_wl[QKVC*HID];     // [Wq;Wk;Wv]^T merged
__device__ __nv_bfloat16 g_woh[HID*QCOLS],  g_wol[HID*QCOLS];   // Wo^T

// ---------------------------------------------------------------------------
// Helpers
// ---------------------------------------------------------------------------
__device__ __forceinline__ uint32_t smem_u32(const void* p) {
    uint32_t a;
    asm("{ .reg .u64 t; cvta.to.shared.u64 t, %1; cvt.u32.u64 %0, t; }" : "=r"(a) : "l"(p));
    return a;
}
__device__ __forceinline__ void cp_async16(uint32_t dst, const void* src) {
    asm volatile("cp.async.cg.shared.global [%0], [%1], 16;\n" :: "r"(dst), "l"(src) : "memory");
}
__device__ __forceinline__ void ldsm_x4(uint32_t& r0, uint32_t& r1, uint32_t& r2, uint32_t& r3,
                                        uint32_t addr) {
    asm volatile("ldmatrix.sync.aligned.m8n8.x4.shared.b16 {%0,%1,%2,%3}, [%4];"
                 : "=r"(r0), "=r"(r1), "=r"(r2), "=r"(r3) : "r"(addr));
}
__device__ __forceinline__ void ldsm_x4t(uint32_t& r0, uint32_t& r1, uint32_t& r2, uint32_t& r3,
                                         uint32_t addr) {
    asm volatile("ldmatrix.sync.aligned.m8n8.x4.trans.shared.b16 {%0,%1,%2,%3}, [%4];"
                 : "=r"(r0), "=r"(r1), "=r"(r2), "=r"(r3) : "r"(addr));
}
__device__ __forceinline__ void mma16816(float& c0, float& c1, float& c2, float& c3,
                                         uint32_t a0, uint32_t a1, uint32_t a2, uint32_t a3,
                                         uint32_t b0, uint32_t b1) {
    asm volatile(
        "mma.sync.aligned.m16n8k16.row.col.f32.bf16.bf16.f32 "
        "{%0,%1,%2,%3}, {%4,%5,%6,%7}, {%8,%9}, {%0,%1,%2,%3};"
        : "+f"(c0), "+f"(c1), "+f"(c2), "+f"(c3)
        : "r"(a0), "r"(a1), "r"(a2), "r"(a3), "r"(b0), "r"(b1));
}
// swizzled smem offset for flash: row r (256B rows of bf16[128]), 16B chunk c
#define SW(r, c) ((uint32_t)((r) * 256 + (((c) ^ ((r) & 7)) << 4)))

// ---------------------------------------------------------------------------
// fp32 -> bf16 hi/lo split (row-major, same layout)
// ---------------------------------------------------------------------------
__global__ void split_kernel(const float* __restrict__ in,
                             __nv_bfloat16* __restrict__ hi,
                             __nv_bfloat16* __restrict__ lo, int n4)
{
    int i = blockIdx.x * blockDim.x + threadIdx.x;
    if (i >= n4) return;
    float4 v = reinterpret_cast<const float4*>(in)[i];
    __nv_bfloat16 h0 = __float2bfloat16_rn(v.x);
    __nv_bfloat16 h1 = __float2bfloat16_rn(v.y);
    __nv_bfloat16 h2 = __float2bfloat16_rn(v.z);
    __nv_bfloat16 h3 = __float2bfloat16_rn(v.w);
    __nv_bfloat16 l0 = __float2bfloat16_rn(v.x - __bfloat162float(h0));
    __nv_bfloat16 l1 = __float2bfloat16_rn(v.y - __bfloat162float(h1));
    __nv_bfloat16 l2 = __float2bfloat16_rn(v.z - __bfloat162float(h2));
    __nv_bfloat16 l3 = __float2bfloat16_rn(v.w - __bfloat162float(h3));
    __nv_bfloat162* hp = reinterpret_cast<__nv_bfloat162*>(hi);
    __nv_bfloat162* lp = reinterpret_cast<__nv_bfloat162*>(lo);
    hp[2*i]   = __nv_bfloat162(h0, h1);
    hp[2*i+1] = __nv_bfloat162(h2, h3);
    lp[2*i]   = __nv_bfloat162(l0, l1);
    lp[2*i+1] = __nv_bfloat162(l2, l3);
}

// strided variant: V region of merged QKV [4096][3072] cols 2560..3071 -> [4096][512]
__global__ void vsplit_kernel(const float* __restrict__ qkv,
                              __nv_bfloat16* __restrict__ hi,
                              __nv_bfloat16* __restrict__ lo, int n4)
{
    int i = blockIdx.x * blockDim.x + threadIdx.x;
    if (i >= n4) return;
    int row = i >> 7;            // 128 float4 per 512-col row
    int c   = (i & 127) * 4;
    float4 v = *reinterpret_cast<const float4*>(qkv + (size_t)row * QKVC + (QCOLS + KCOLS) + c);
    __nv_bfloat16 h0 = __float2bfloat16_rn(v.x);
    __nv_bfloat16 h1 = __float2bfloat16_rn(v.y);
    __nv_bfloat16 h2 = __float2bfloat16_rn(v.z);
    __nv_bfloat16 h3 = __float2bfloat16_rn(v.w);
    __nv_bfloat16 l0 = __float2bfloat16_rn(v.x - __bfloat162float(h0));
    __nv_bfloat16 l1 = __float2bfloat16_rn(v.y - __bfloat162float(h1));
    __nv_bfloat16 l2 = __float2bfloat16_rn(v.z - __bfloat162float(h2));
    __nv_bfloat16 l3 = __float2bfloat16_rn(v.w - __bfloat162float(h3));
    size_t o = (size_t)row * KCOLS + c;
    *reinterpret_cast<__nv_bfloat162*>(hi + o)     = __nv_bfloat162(h0, h1);
    *reinterpret_cast<__nv_bfloat162*>(hi + o + 2) = __nv_bfloat162(h2, h3);
    *reinterpret_cast<__nv_bfloat162*>(lo + o)     = __nv_bfloat162(l0, l1);
    *reinterpret_cast<__nv_bfloat162*>(lo + o + 2) = __nv_bfloat162(l2, l3);
}

// fp32 [Kin][Nin] -> transposed bf16 hi/lo [Nin][Kin]
__global__ void tsplit_kernel(const float* __restrict__ in,
                              __nv_bfloat16* __restrict__ hiT,
                              __nv_bfloat16* __restrict__ loT, int Kin, int Nin)
{
    __shared__ float t[32][33];
    const int tx = threadIdx.x, ty = threadIdx.y;
    const int n0 = blockIdx.x * 32, k0 = blockIdx.y * 32;
    #pragma unroll
    for (int j = 0; j < 32; j += 8)
        t[ty + j][tx] = in[(size_t)(k0 + ty + j) * Nin + n0 + tx];
    __syncthreads();
    #pragma unroll
    for (int j = 0; j < 32; j += 8) {
        float x = t[tx][ty + j];
        __nv_bfloat16 h = __float2bfloat16_rn(x);
        __nv_bfloat16 l = __float2bfloat16_rn(x - __bfloat162float(h));
        size_t o = (size_t)(n0 + ty + j) * Kin + k0 + tx;
        hiT[o] = h;
        loT[o] = l;
    }
}

// ---------------------------------------------------------------------------
// GEMM via mma.sync (bf16 hi/lo 3-product), 3-stage cp.async pipeline,
// single __syncthreads per K-chunk.
// C[4096, ldc] = A[4096, 2048] @ B^T  (B stored [ldc][2048] K-major).
// ---------------------------------------------------------------------------
#define KCH       32
#define NCHUNKS   64
#define TILE_B    8192
#define STAGE_B   (4*TILE_B)    // 32 KB
#define NSTG      3
#define GEMM_SMEM (NSTG*STAGE_B)  // 96 KB

__global__ __launch_bounds__(256)
void gemm_mma(const __nv_bfloat16* __restrict__ Ah, const __nv_bfloat16* __restrict__ Al,
              const __nv_bfloat16* __restrict__ Bh, const __nv_bfloat16* __restrict__ Bl,
              float* __restrict__ C, int ldc)
{
    extern __shared__ char dsm[];
    const uint32_t sbase = smem_u32(dsm);

    const int tid = threadIdx.x;
    const int wid = tid >> 5, lane = tid & 31;
    const int m0 = blockIdx.y * 128;
    const int n0 = blockIdx.x * 128;

    const int tt  = tid >> 6;          // 0:Ah 1:Al 2:Bh 3:Bl
    const int t6  = tid & 63;
    const int lch = t6 & 3;
    const int lr0 = t6 >> 2;
    const __nv_bfloat16* gsrc;
    int row0;
    switch (tt) {
        case 0: gsrc = Ah; row0 = m0; break;
        case 1: gsrc = Al; row0 = m0; break;
        case 2: gsrc = Bh; row0 = n0; break;
        default: gsrc = Bl; row0 = n0; break;
    }

    auto load_chunk = [&](int ci, int st) {
        const uint32_t tb = sbase + st * STAGE_B + tt * TILE_B;
        #pragma unroll
        for (int i = 0; i < 8; i++) {
            const int r = lr0 + i * 16;
            const uint32_t dst = tb + r * 64 + ((uint32_t)(lch ^ ((r >> 1) & 3)) << 4);
            cp_async16(dst, gsrc + (size_t)(row0 + r) * 2048 + ci * KCH + lch * 8);
        }
        asm volatile("cp.async.commit_group;\n" ::: "memory");
    };

    const int warp_m = wid & 1;
    const int warp_n = wid >> 1;
    const int m0w = warp_m * 64;
    const int n0w = warp_n * 32;

    const int a_row = lane & 15;
    const int a_kh  = lane >> 4;
    const int b_row = (lane & 7) + ((lane >> 4) & 1) * 8;
    const int b_kh  = (lane >> 3) & 1;

    float acc[4][4][4];
    #pragma unroll
    for (int i = 0; i < 4; i++)
        #pragma unroll
        for (int j = 0; j < 4; j++)
            #pragma unroll
            for (int q = 0; q < 4; q++) acc[i][j][q] = 0.0f;

    load_chunk(0, 0);
    load_chunk(1, 1);

    for (int ci = 0; ci < NCHUNKS; ci++) {
        if (ci + 1 < NCHUNKS) asm volatile("cp.async.wait_group 1;\n" ::: "memory");
        else                  asm volatile("cp.async.wait_group 0;\n" ::: "memory");
        __syncthreads();
        if (ci + 2 < NCHUNKS) load_chunk(ci + 2, (ci + 2) % NSTG);

        const int st = ci % NSTG;
        const uint32_t ah_b = sbase + st * STAGE_B;
        const uint32_t al_b = ah_b + TILE_B;
        const uint32_t bh_b = ah_b + 2 * TILE_B;
        const uint32_t bl_b = ah_b + 3 * TILE_B;

        #pragma unroll
        for (int ks = 0; ks < 2; ks++) {
            uint32_t ah[4][4], al[4][4];
            #pragma unroll
            for (int mi = 0; mi < 4; mi++) {
                const int r = m0w + mi * 16 + a_row;
                const int c = ks * 2 + a_kh;
                const uint32_t off = r * 64 + ((uint32_t)(c ^ ((r >> 1) & 3)) << 4);
                ldsm_x4(ah[mi][0], ah[mi][1], ah[mi][2], ah[mi][3], ah_b + off);
                ldsm_x4(al[mi][0], al[mi][1], al[mi][2], al[mi][3], al_b + off);
            }
            uint32_t bh[4][2], bl[4][2];
            #pragma unroll
            for (int jb = 0; jb < 2; jb++) {
                const int r = n0w + jb * 16 + b_row;
                const int c = ks * 2 + b_kh;
                const uint32_t off = r * 64 + ((uint32_t)(c ^ ((r >> 1) & 3)) << 4);
                ldsm_x4(bh[2*jb][0], bh[2*jb][1], bh[2*jb+1][0], bh[2*jb+1][1], bh_b + off);
                ldsm_x4(bl[2*jb][0], bl[2*jb][1], bl[2*jb+1][0], bl[2*jb+1][1], bl_b + off);
            }
            #pragma unroll
            for (int mi = 0; mi < 4; mi++)
                #pragma unroll
                for (int nj = 0; nj < 4; nj++) {
                    float* cc = acc[mi][nj];
                    mma16816(cc[0], cc[1], cc[2], cc[3],
                             ah[mi][0], ah[mi][1], ah[mi][2], ah[mi][3],
                             bh[nj][0], bh[nj][1]);
                    mma16816(cc[0], cc[1], cc[2], cc[3],
                             ah[mi][0], ah[mi][1], ah[mi][2], ah[mi][3],
                             bl[nj][0], bl[nj][1]);
                    mma16816(cc[0], cc[1], cc[2], cc[3],
                             al[mi][0], al[mi][1], al[mi][2], al[mi][3],
                             bh[nj][0], bh[nj][1]);
                }
        }
    }

    const int er = lane >> 2;
    const int ec = (lane & 3) * 2;
    #pragma unroll
    for (int mi = 0; mi < 4; mi++) {
        const int row_a = m0 + m0w + mi * 16 + er;
        #pragma unroll
        for (int nj = 0; nj < 4; nj++) {
            const int col = n0 + n0w + nj * 8 + ec;
            float* cc = acc[mi][nj];
            *reinterpret_cast<float2*>(C + (size_t)row_a * ldc + col) =
                make_float2(cc[0], cc[1]);
            *reinterpret_cast<float2*>(C + (size_t)(row_a + 8) * ldc + col) =
                make_float2(cc[2], cc[3]);
        }
    }
}

// ---------------------------------------------------------------------------
// RoPE: table + fused apply/scale/split (reads strided merged QKV)
// ---------------------------------------------------------------------------
__global__ void rope_table_kernel()
{
    int idx = blockIdx.x * blockDim.x + threadIdx.x;
    if (idx >= SEQ * 64) return;
    int pos = idx >> 6, i = idx & 63;
    double inv = exp2(-(double)i * (13.287712379549449 / 64.0));
    double ang = (double)pos * inv;
    const double twopi = 6.283185307179586476925286766559;
    ang -= floor(ang * (1.0 / twopi)) * twopi;
    if (ang > 3.14159265358979323846) ang -= twopi;
    float s, c;
    sincosf((float)ang, &s, &c);
    g_cos[idx] = c;
    g_sin[idx] = s;
}

__global__ void rope_split_kernel(const float* __restrict__ buf, int ldin,
                                  __nv_bfloat16* __restrict__ oh,
                                  __nv_bfloat16* __restrict__ ol,
                                  int heads, int npairs, float scale)
{
    int idx = blockIdx.x * blockDim.x + threadIdx.x;
    if (idx >= npairs) return;
    int i    = idx & 63;
    int hp   = idx >> 6;
    int head = hp % heads;
    int row  = hp / heads;
    int pos  = row & (SEQ - 1);
    size_t bi = (size_t)row * ldin + head * HDIM + i;
    size_t bo = (size_t)row * heads * HDIM + head * HDIM + i;
    float c = g_cos[pos*64 + i];
    float s = g_sin[pos*64 + i];
    float x1 = buf[bi];
    float x2 = buf[bi + 64];
    float y1 = (x1 * c - x2 * s) * scale;
    float y2 = (x2 * c + x1 * s) * scale;
    __nv_bfloat16 h1 = __float2bfloat16_rn(y1);
    __nv_bfloat16 h2 = __float2bfloat16_rn(y2);
    oh[bo]      = h1;
    oh[bo + 64] = h2;
    ol[bo]      = __float2bfloat16_rn(y1 - __bfloat162float(h1));
    ol[bo + 64] = __float2bfloat16_rn(y2 - __bfloat162float(h2));
}

// ---------------------------------------------------------------------------
// Flash attention on tensor cores (hi/lo 3-product), qt processed descending.
// ---------------------------------------------------------------------------
#define FQT 128
#define FKT 64
#define FQ_B    32768
#define FTILE_B 16384
#define FKV_B   (4*FTILE_B)
#define FLASH_SMEM (2*FQ_B + 2*FKV_B)   // 192KB

__global__ __launch_bounds__(256, 1)
void flash_mma(const __nv_bfloat16* __restrict__ Qh_g, const __nv_bfloat16* __restrict__ Ql_g,
               const __nv_bfloat16* __restrict__ Kh_g, const __nv_bfloat16* __restrict__ Kl_g,
               const __nv_bfloat16* __restrict__ Vh_g, const __nv_bfloat16* __restrict__ Vl_g,
               __nv_bfloat16* __restrict__ Ch_g, __nv_bfloat16* __restrict__ Cl_g)
{
    extern __shared__ char dsm[];
    const uint32_t sb = smem_u32(dsm);
    const uint32_t Qh_s = sb, Ql_s = sb + FQ_B;
    const uint32_t KV_s = sb + 2 * FQ_B;

    const int tid = threadIdx.x;
    const int w = tid >> 5, lane = tid & 31;
    const int qt = gridDim.x - 1 - blockIdx.x;    // heavy tiles first
    const int h = blockIdx.y, b = blockIdx.z;
    const int kvh = h >> 2;
    const int qrow0 = b * SEQ + qt * FQT;
    const int nkt = 2 * qt + 2;

    {
        const int c = tid & 15, r0 = tid >> 4;
        #pragma unroll
        for (int i = 0; i < 8; i++) {
            const int r = r0 + i * 16;
            const size_t go = (size_t)(qrow0 + r) * QCOLS + h * HDIM + c * 8;
            cp_async16(Qh_s + SW(r, c), Qh_g + go);
            cp_async16(Ql_s + SW(r, c), Ql_g + go);
        }
    }

    auto load_kv = [&](int kt, int st) {
        const int c = tid & 15, r0 = tid >> 4;
        const uint32_t base = KV_s + st * FKV_B;
        const int krow0 = b * SEQ + kt * FKT;
        #pragma unroll
        for (int i = 0; i < 4; i++) {
            const int r = r0 + i * 16;
            const size_t go = (size_t)(krow0 + r) * KCOLS + kvh * HDIM + c * 8;
            cp_async16(base +             SW(r, c), Kh_g + go);
            cp_async16(base +   FTILE_B + SW(r, c), Kl_g + go);
            cp_async16(base + 2*FTILE_B + SW(r, c), Vh_g + go);
            cp_async16(base + 3*FTILE_B + SW(r, c), Vl_g + go);
        }
        asm volatile("cp.async.commit_group;\n" ::: "memory");
    };

    load_kv(0, 0);
    asm volatile("cp.async.commit_group;\n" ::: "memory");

    const int er = lane >> 2, ec = lane & 3;
    const int a_row = w * 16 + (lane & 15);
    const int a_kh  = lane >> 4;
    const int b_n   = (lane & 7) + ((lane >> 4) & 1) * 8;
    const int b_kh  = (lane >> 3) & 1;
    const int v_key = (lane & 7) + ((lane >> 3) & 1) * 8;
    const int v_dc  = lane >> 4;

    const int rg0 = qt * FQT + w * 16 + er;
    const int rg1 = rg0 + 8;

    float o[16][4];
    #pragma unroll
    for (int j = 0; j < 16; j++)
        #pragma unroll
        for (int q = 0; q < 4; q++) o[j][q] = 0.0f;
    float m0 = -1e30f, m1 = -1e30f, l0 = 0.0f, l1 = 0.0f;

    for (int kt = 0; kt < nkt; kt++) {
        const int st = kt & 1;
        if (kt + 1 < nkt) {
            load_kv(kt + 1, (kt + 1) & 1);
            asm volatile("cp.async.wait_group 1;\n" ::: "memory");
        } else {
            asm volatile("cp.async.wait_group 0;\n" ::: "memory");
        }
        __syncthreads();

        const uint32_t Kh_s = KV_s + st * FKV_B;
        const uint32_t Kl_s = Kh_s + FTILE_B;
        const uint32_t Vh_s = Kh_s + 2 * FTILE_B;
        const uint32_t Vl_s = Kh_s + 3 * FTILE_B;

        float s[8][4];
        #pragma unroll
        for (int f = 0; f < 8; f++)
            #pragma unroll
            for (int q = 0; q < 4; q++) s[f][q] = 0.0f;

        #pragma unroll
        for (int ks = 0; ks < 8; ks++) {
            uint32_t qah[4], qal[4];
            ldsm_x4(qah[0], qah[1], qah[2], qah[3], Qh_s + SW(a_row, ks*2 + a_kh));
            ldsm_x4(qal[0], qal[1], qal[2], qal[3], Ql_s + SW(a_row, ks*2 + a_kh));
            #pragma unroll
            for (int ng = 0; ng < 4; ng++) {
                uint32_t kh0, kh1, kh2, kh3, kl0, kl1, kl2, kl3;
                ldsm_x4(kh0, kh1, kh2, kh3, Kh_s + SW(ng*16 + b_n, ks*2 + b_kh));
                ldsm_x4(kl0, kl1, kl2, kl3, Kl_s + SW(ng*16 + b_n, ks*2 + b_kh));
                float* s0 = s[ng*2];
                float* s1 = s[ng*2 + 1];
                mma16816(s0[0], s0[1], s0[2], s0[3], qah[0], qah[1], qah[2], qah[3], kh0, kh1);
                mma16816(s0[0], s0[1], s0[2], s0[3], qah[0], qah[1], qah[2], qah[3], kl0, kl1);
                mma16816(s0[0], s0[1], s0[2], s0[3], qal[0], qal[1], qal[2], qal[3], kh0, kh1);
                mma16816(s1[0], s1[1], s1[2], s1[3], qah[0], qah[1], qah[2], qah[3], kh2, kh3);
                mma16816(s1[0], s1[1], s1[2], s1[3], qah[0], qah[1], qah[2], qah[3], kl2, kl3);
                mma16816(s1[0], s1[1], s1[2], s1[3], qal[0], qal[1], qal[2], qal[3], kh2, kh3);
            }
        }

        if (kt >= 2 * qt) {
            #pragma unroll
            for (int f = 0; f < 8; f++) {
                const int key0 = kt * FKT + f * 8 + ec * 2;
                if (key0     > rg0) s[f][0] = -1e30f;
                if (key0 + 1 > rg0) s[f][1] = -1e30f;
                if (key0     > rg1) s[f][2] = -1e30f;
                if (key0 + 1 > rg1) s[f][3] = -1e30f;
            }
        }

        float nm0 = -1e30f, nm1 = -1e30f;
        #pragma unroll
        for (int f = 0; f < 8; f++) {
            nm0 = fmaxf(nm0, fmaxf(s[f][0], s[f][1]));
            nm1 = fmaxf(nm1, fmaxf(s[f][2], s[f][3]));
        }
        nm0 = fmaxf(nm0, __shfl_xor_sync(0xffffffffu, nm0, 1));
        nm0 = fmaxf(nm0, __shfl_xor_sync(0xffffffffu, nm0, 2));
        nm1 = fmaxf(nm1, __shfl_xor_sync(0xffffffffu, nm1, 1));
        nm1 = fmaxf(nm1, __shfl_xor_sync(0xffffffffu, nm1, 2));
        nm0 = fmaxf(nm0, m0);
        nm1 = fmaxf(nm1, m1);
        const float corr0 = __expf(m0 - nm0);
        const float corr1 = __expf(m1 - nm1);
        m0 = nm0;
        m1 = nm1;

        float rs0 = 0.0f, rs1 = 0.0f;
        #pragma unroll
        for (int f = 0; f < 8; f++) {
            s[f][0] = __expf(s[f][0] - nm0);
            s[f][1] = __expf(s[f][1] - nm0);
            s[f][2] = __expf(s[f][2] - nm1);
            s[f][3] = __expf(s[f][3] - nm1);
            rs0 += s[f][0] + s[f][1];
            rs1 += s[f][2] + s[f][3];
        }
        rs0 += __shfl_xor_sync(0xffffffffu, rs0, 1);
        rs0 += __shfl_xor_sync(0xffffffffu, rs0, 2);
        rs1 += __shfl_xor_sync(0xffffffffu, rs1, 1);
        rs1 += __shfl_xor_sync(0xffffffffu, rs1, 2);
        l0 = l0 * corr0 + rs0;
        l1 = l1 * corr1 + rs1;
        #pragma unroll
        for (int j = 0; j < 16; j++) {
            o[j][0] *= corr0; o[j][1] *= corr0;
            o[j][2] *= corr1; o[j][3] *= corr1;
        }

        #pragma unroll
        for (int kp = 0; kp < 4; kp++) {
            const float* f0 = s[2*kp];
            const float* f1 = s[2*kp + 1];
            uint32_t pah[4], pal[4];
            float r0a, r0b, r1a, r1b, r2a, r2b, r3a, r3b;
            __nv_bfloat162 h2v;
            h2v = __floats2bfloat162_rn(f0[0], f0[1]);
            r0a = f0[0] - __low2float(h2v); r0b = f0[1] - __high2float(h2v);
            pah[0] = *reinterpret_cast<uint32_t*>(&h2v);
            h2v = __floats2bfloat162_rn(f0[2], f0[3]);
            r1a = f0[2] - __low2float(h2v); r1b = f0[3] - __high2float(h2v);
            pah[1] = *reinterpret_cast<uint32_t*>(&h2v);
            h2v = __floats2bfloat162_rn(f1[0], f1[1]);
            r2a = f1[0] - __low2float(h2v); r2b = f1[1] - __high2float(h2v);
            pah[2] = *reinterpret_cast<uint32_t*>(&h2v);
            h2v = __floats2bfloat162_rn(f1[2], f1[3]);
            r3a = f1[2] - __low2float(h2v); r3b = f1[3] - __high2float(h2v);
            pah[3] = *reinterpret_cast<uint32_t*>(&h2v);
            h2v = __floats2bfloat162_rn(r0a, r0b); pal[0] = *reinterpret_cast<uint32_t*>(&h2v);
            h2v = __floats2bfloat162_rn(r1a, r1b); pal[1] = *reinterpret_cast<uint32_t*>(&h2v);
            h2v = __floats2bfloat162_rn(r2a, r2b); pal[2] = *reinterpret_cast<uint32_t*>(&h2v);
            h2v = __floats2bfloat162_rn(r3a, r3b); pal[3] = *reinterpret_cast<uint32_t*>(&h2v);

            #pragma unroll
            for (int nd = 0; nd < 8; nd++) {
                uint32_t vh0, vh1, vh2, vh3, vl0, vl1, vl2, vl3;
                ldsm_x4t(vh0, vh1, vh2, vh3, Vh_s + SW(kp*16 + v_key, nd*2 + v_dc));
                ldsm_x4t(vl0, vl1, vl2, vl3, Vl_s + SW(kp*16 + v_key, nd*2 + v_dc));
                float* o0 = o[nd*2];
                float* o1 = o[nd*2 + 1];
                mma16816(o0[0], o0[1], o0[2], o0[3], pah[0], pah[1], pah[2], pah[3], vh0, vh1);
                mma16816(o0[0], o0[1], o0[2], o0[3], pah[0], pah[1], pah[2], pah[3], vl0, vl1);
                mma16816(o0[0], o0[1], o0[2], o0[3], pal[0], pal[1], pal[2], pal[3], vh0, vh1);
                mma16816(o1[0], o1[1], o1[2], o1[3], pah[0], pah[1], pah[2], pah[3], vh2, vh3);
                mma16816(o1[0], o1[1], o1[2], o1[3], pah[0], pah[1], pah[2], pah[3], vl2, vl3);
                mma16816(o1[0], o1[1], o1[2], o1[3], pal[0], pal[1], pal[2], pal[3], vh2, vh3);
            }
        }
        __syncthreads();
    }

    const float inv0 = 1.0f / l0;
    const float inv1 = 1.0f / l1;
    const size_t row0 = (size_t)(qrow0 + w * 16 + er);
    const size_t row1 = row0 + 8;
    #pragma unroll
    for (int j = 0; j < 16; j++) {
        const int col = h * HDIM + j * 8 + ec * 2;
        float x0 = o[j][0] * inv0, x1 = o[j][1] * inv0;
        float x2 = o[j][2] * inv1, x3 = o[j][3] * inv1;
        __nv_bfloat162 h01 = __floats2bfloat162_rn(x0, x1);
        __nv_bfloat162 h23 = __floats2bfloat162_rn(x2, x3);
        __nv_bfloat162 l01 = __floats2bfloat162_rn(x0 - __low2float(h01), x1 - __high2float(h01));
        __nv_bfloat162 l23 = __floats2bfloat162_rn(x2 - __low2float(h23), x3 - __high2float(h23));
        *reinterpret_cast<__nv_bfloat162*>(Ch_g + row0 * QCOLS + col) = h01;
        *reinterpret_cast<__nv_bfloat162*>(Cl_g + row0 * QCOLS + col) = l01;
        *reinterpret_cast<__nv_bfloat162*>(Ch_g + row1 * QCOLS + col) = h23;
        *reinterpret_cast<__nv_bfloat162*>(Cl_g + row1 * QCOLS + col) = l23;
    }
}

// ---------------------------------------------------------------------------
extern "C" void kernel_launch(void* const* d_in, const int* in_sizes, int n_in,
                              void* d_out, int out_size)
{
    const float* hidden = (const float*)d_in[0];
    const float* Wq = (const float*)d_in[1];
    const float* Wk = (const float*)d_in[2];
    const float* Wv = (const float*)d_in[3];
    const float* Wo = (const float*)d_in[4];
    float* out = (float*)d_out;

    float *qkv;
    __nv_bfloat16 *ah, *al, *ch, *cl, *qh, *ql, *kh, *kl, *vh, *vl;
    __nv_bfloat16 *wh, *wl, *woh, *wol;
    cudaGetSymbolAddress((void**)&qkv, g_qkv);
    cudaGetSymbolAddress((void**)&ah, g_ah);  cudaGetSymbolAddress((void**)&al, g_al);
    cudaGetSymbolAddress((void**)&ch, g_ch);  cudaGetSymbolAddress((void**)&cl, g_cl);
    cudaGetSymbolAddress((void**)&qh, g_qh);  cudaGetSymbolAddress((void**)&ql, g_ql);
    cudaGetSymbolAddress((void**)&kh, g_kh);  cudaGetSymbolAddress((void**)&kl, g_kl);
    cudaGetSymbolAddress((void**)&vh, g_vh);  cudaGetSymbolAddress((void**)&vl, g_vl);
    cudaGetSymbolAddress((void**)&wh, g_wh);  cudaGetSymbolAddress((void**)&wl, g_wl);
    cudaGetSymbolAddress((void**)&woh, g_woh); cudaGetSymbolAddress((void**)&wol, g_wol);

    cudaFuncSetAttribute(gemm_mma,
                         cudaFuncAttributeMaxDynamicSharedMemorySize, GEMM_SMEM);
    cudaFuncSetAttribute(flash_mma,
                         cudaFuncAttributeMaxDynamicSharedMemorySize, FLASH_SMEM);

    // Split/transpose inputs to bf16 hi/lo (weights into merged [3072][2048])
    split_kernel<<<(ROWS*HID/4 + 255)/256, 256>>>(hidden, ah, al, ROWS*HID/4);
    tsplit_kernel<<<dim3(QCOLS/32, HID/32), dim3(32,8)>>>(Wq, wh, wl, HID, QCOLS);
    tsplit_kernel<<<dim3(KCOLS/32, HID/32), dim3(32,8)>>>(Wk, wh + (size_t)QCOLS*HID,
                                                          wl + (size_t)QCOLS*HID, HID, KCOLS);
    tsplit_kernel<<<dim3(KCOLS/32, HID/32), dim3(32,8)>>>(Wv, wh + (size_t)(QCOLS+KCOLS)*HID,
                                                          wl + (size_t)(QCOLS+KCOLS)*HID, HID, KCOLS);
    tsplit_kernel<<<dim3(HID/32, QCOLS/32), dim3(32,8)>>>(Wo, woh, wol, QCOLS, HID);

    // Merged QKV projection (one launch, N=3072)
    gemm_mma<<<dim3(QKVC/128, ROWS/128), 256, GEMM_SMEM>>>(ah, al, wh, wl, qkv, QKVC);

    // RoPE + bf16 hi/lo split (scale folded into Q); V strided split
    rope_table_kernel<<<(SEQ*64 + 255)/256, 256>>>();
    const float att_scale = 0.08838834764831845f;   // 1/sqrt(128)
    rope_split_kernel<<<(ROWS*NHQ*64 + 255)/256, 256>>>(qkv, QKVC, qh, ql, NHQ, ROWS*NHQ*64, att_scale);
    rope_split_kernel<<<(ROWS*NKV*64 + 255)/256, 256>>>(qkv + QCOLS, QKVC, kh, kl, NKV, ROWS*NKV*64, 1.0f);
    vsplit_kernel<<<(ROWS*KCOLS/4 + 255)/256, 256>>>(qkv, vh, vl, ROWS*KCOLS/4);

    // Attention (tensor cores), writes ctx hi/lo directly
    flash_mma<<<dim3(SEQ/FQT, NHQ, BATCH), 256, FLASH_SMEM>>>(qh, ql, kh, kl, vh, vl, ch, cl);

    // Output projection
    gemm_mma<<<dim3(HID/128, ROWS/128), 256, GEMM_SMEM>>>(ch, cl, woh, wol, out, HID);
}

// round 7
// speedup vs baseline: 3.1642x; 1.0106x over previous
#include <cuda_runtime.h>
#include <cuda_bf16.h>
#include <math.h>
#include <stdint.h>

// Problem constants
#define BATCH 2
#define SEQ   2048
#define HID   2048
#define NHQ   16
#define NKV   4
#define HDIM  128
#define ROWS  (BATCH*SEQ)          // 4096
#define QCOLS (NHQ*HDIM)           // 2048
#define KCOLS (NKV*HDIM)           // 512
#define QKVC  (QCOLS + 2*KCOLS)    // 3072

// ---------------------------------------------------------------------------
// Device scratch (static — no allocation allowed)
// ---------------------------------------------------------------------------
__device__ float g_cos[SEQ*64];
__device__ float g_sin[SEQ*64];

__device__ __nv_bfloat16 g_ah[ROWS*HID],    g_al[ROWS*HID];     // hidden
__device__ __nv_bfloat16 g_ch[ROWS*QCOLS],  g_cl[ROWS*QCOLS];   // ctx (flash out)
__device__ __nv_bfloat16 g_qh[ROWS*QCOLS],  g_ql[ROWS*QCOLS];   // q (rope+scale)
__device__ __nv_bfloat16 g_kh[ROWS*KCOLS],  g_kl[ROWS*KCOLS];   // k (rope)
__device__ __nv_bfloat16 g_vh[ROWS*KCOLS],  g_vl[ROWS*KCOLS];   // v
__device__ __nv_bfloat16 g_wh[QKVC*HID],    g_wl[QKVC*HID];     // [Wq;Wk;Wv]^T merged
__device__ __nv_bfloat16 g_woh[HID*QCOLS],  g_wol[HID*QCOLS];   // Wo^T

// ---------------------------------------------------------------------------
// Helpers
// ---------------------------------------------------------------------------
__device__ __forceinline__ uint32_t smem_u32(const void* p) {
    uint32_t a;
    asm("{ .reg .u64 t; cvta.to.shared.u64 t, %1; cvt.u32.u64 %0, t; }" : "=r"(a) : "l"(p));
    return a;
}
__device__ __forceinline__ void cp_async16(uint32_t dst, const void* src) {
    asm volatile("cp.async.cg.shared.global [%0], [%1], 16;\n" :: "r"(dst), "l"(src) : "memory");
}
__device__ __forceinline__ void ldsm_x4(uint32_t& r0, uint32_t& r1, uint32_t& r2, uint32_t& r3,
                                        uint32_t addr) {
    asm volatile("ldmatrix.sync.aligned.m8n8.x4.shared.b16 {%0,%1,%2,%3}, [%4];"
                 : "=r"(r0), "=r"(r1), "=r"(r2), "=r"(r3) : "r"(addr));
}
__device__ __forceinline__ void ldsm_x4t(uint32_t& r0, uint32_t& r1, uint32_t& r2, uint32_t& r3,
                                         uint32_t addr) {
    asm volatile("ldmatrix.sync.aligned.m8n8.x4.trans.shared.b16 {%0,%1,%2,%3}, [%4];"
                 : "=r"(r0), "=r"(r1), "=r"(r2), "=r"(r3) : "r"(addr));
}
__device__ __forceinline__ void mma16816(float& c0, float& c1, float& c2, float& c3,
                                         uint32_t a0, uint32_t a1, uint32_t a2, uint32_t a3,
                                         uint32_t b0, uint32_t b1) {
    asm volatile(
        "mma.sync.aligned.m16n8k16.row.col.f32.bf16.bf16.f32 "
        "{%0,%1,%2,%3}, {%4,%5,%6,%7}, {%8,%9}, {%0,%1,%2,%3};"
        : "+f"(c0), "+f"(c1), "+f"(c2), "+f"(c3)
        : "r"(a0), "r"(a1), "r"(a2), "r"(a3), "r"(b0), "r"(b1));
}
// swizzled smem offset for flash: row r (256B rows of bf16[128]), 16B chunk c
#define SW(r, c) ((uint32_t)((r) * 256 + (((c) ^ ((r) & 7)) << 4)))

// ---------------------------------------------------------------------------
// fp32 -> bf16 hi/lo split (row-major, same layout)
// ---------------------------------------------------------------------------
__global__ void split_kernel(const float* __restrict__ in,
                             __nv_bfloat16* __restrict__ hi,
                             __nv_bfloat16* __restrict__ lo, int n4)
{
    int i = blockIdx.x * blockDim.x + threadIdx.x;
    if (i >= n4) return;
    float4 v = reinterpret_cast<const float4*>(in)[i];
    __nv_bfloat16 h0 = __float2bfloat16_rn(v.x);
    __nv_bfloat16 h1 = __float2bfloat16_rn(v.y);
    __nv_bfloat16 h2 = __float2bfloat16_rn(v.z);
    __nv_bfloat16 h3 = __float2bfloat16_rn(v.w);
    __nv_bfloat16 l0 = __float2bfloat16_rn(v.x - __bfloat162float(h0));
    __nv_bfloat16 l1 = __float2bfloat16_rn(v.y - __bfloat162float(h1));
    __nv_bfloat16 l2 = __float2bfloat16_rn(v.z - __bfloat162float(h2));
    __nv_bfloat16 l3 = __float2bfloat16_rn(v.w - __bfloat162float(h3));
    __nv_bfloat162* hp = reinterpret_cast<__nv_bfloat162*>(hi);
    __nv_bfloat162* lp = reinterpret_cast<__nv_bfloat162*>(lo);
    hp[2*i]   = __nv_bfloat162(h0, h1);
    hp[2*i+1] = __nv_bfloat162(h2, h3);
    lp[2*i]   = __nv_bfloat162(l0, l1);
    lp[2*i+1] = __nv_bfloat162(l2, l3);
}

// fp32 [Kin][Nin] -> transposed bf16 hi/lo [Nin][Kin]
__global__ void tsplit_kernel(const float* __restrict__ in,
                              __nv_bfloat16* __restrict__ hiT,
                              __nv_bfloat16* __restrict__ loT, int Kin, int Nin)
{
    __shared__ float t[32][33];
    const int tx = threadIdx.x, ty = threadIdx.y;
    const int n0 = blockIdx.x * 32, k0 = blockIdx.y * 32;
    #pragma unroll
    for (int j = 0; j < 32; j += 8)
        t[ty + j][tx] = in[(size_t)(k0 + ty + j) * Nin + n0 + tx];
    __syncthreads();
    #pragma unroll
    for (int j = 0; j < 32; j += 8) {
        float x = t[tx][ty + j];
        __nv_bfloat16 h = __float2bfloat16_rn(x);
        __nv_bfloat16 l = __float2bfloat16_rn(x - __bfloat162float(h));
        size_t o = (size_t)(n0 + ty + j) * Kin + k0 + tx;
        hiT[o] = h;
        loT[o] = l;
    }
}

// ---------------------------------------------------------------------------
// RoPE table
// ---------------------------------------------------------------------------
__global__ void rope_table_kernel()
{
    int idx = blockIdx.x * blockDim.x + threadIdx.x;
    if (idx >= SEQ * 64) return;
    int pos = idx >> 6, i = idx & 63;
    double inv = exp2(-(double)i * (13.287712379549449 / 64.0));
    double ang = (double)pos * inv;
    const double twopi = 6.283185307179586476925286766559;
    ang -= floor(ang * (1.0 / twopi)) * twopi;
    if (ang > 3.14159265358979323846) ang -= twopi;
    float s, c;
    sincosf((float)ang, &s, &c);
    g_cos[idx] = c;
    g_sin[idx] = s;
}

// ---------------------------------------------------------------------------
// Shared GEMM mainloop (macro-free duplication kept readable):
// 128x128 CTA tile, bf16 hi/lo 3-product, 3-stage cp.async, one sync/chunk.
// ---------------------------------------------------------------------------
#define KCH       32
#define NCHUNKS   64
#define TILE_B    8192
#define STAGE_B   (4*TILE_B)    // 32 KB
#define NSTG      3
#define GEMM_SMEM (NSTG*STAGE_B)  // 96 KB

// Mainloop body as a __device__ function operating on caller-provided state.
struct GemmCtx {
    uint32_t sbase;
    const __nv_bfloat16* gsrc;
    int row0, tt, lch, lr0;
    int m0w, n0w;
    int a_row, a_kh, b_row, b_kh;
};

__device__ __forceinline__ void gemm_mainloop(
    const GemmCtx& cx, float acc[4][4][4])
{
    auto load_chunk = [&](int ci, int st) {
        const uint32_t tb = cx.sbase + st * STAGE_B + cx.tt * TILE_B;
        #pragma unroll
        for (int i = 0; i < 8; i++) {
            const int r = cx.lr0 + i * 16;
            const uint32_t dst = tb + r * 64 + ((uint32_t)(cx.lch ^ ((r >> 1) & 3)) << 4);
            cp_async16(dst, cx.gsrc + (size_t)(cx.row0 + r) * 2048 + ci * KCH + cx.lch * 8);
        }
        asm volatile("cp.async.commit_group;\n" ::: "memory");
    };

    load_chunk(0, 0);
    load_chunk(1, 1);

    for (int ci = 0; ci < NCHUNKS; ci++) {
        if (ci + 1 < NCHUNKS) asm volatile("cp.async.wait_group 1;\n" ::: "memory");
        else                  asm volatile("cp.async.wait_group 0;\n" ::: "memory");
        __syncthreads();
        if (ci + 2 < NCHUNKS) load_chunk(ci + 2, (ci + 2) % NSTG);

        const int st = ci % NSTG;
        const uint32_t ah_b = cx.sbase + st * STAGE_B;
        const uint32_t al_b = ah_b + TILE_B;
        const uint32_t bh_b = ah_b + 2 * TILE_B;
        const uint32_t bl_b = ah_b + 3 * TILE_B;

        #pragma unroll
        for (int ks = 0; ks < 2; ks++) {
            uint32_t ah[4][4], al[4][4];
            #pragma unroll
            for (int mi = 0; mi < 4; mi++) {
                const int r = cx.m0w + mi * 16 + cx.a_row;
                const int c = ks * 2 + cx.a_kh;
                const uint32_t off = r * 64 + ((uint32_t)(c ^ ((r >> 1) & 3)) << 4);
                ldsm_x4(ah[mi][0], ah[mi][1], ah[mi][2], ah[mi][3], ah_b + off);
                ldsm_x4(al[mi][0], al[mi][1], al[mi][2], al[mi][3], al_b + off);
            }
            uint32_t bh[4][2], bl[4][2];
            #pragma unroll
            for (int jb = 0; jb < 2; jb++) {
                const int r = cx.n0w + jb * 16 + cx.b_row;
                const int c = ks * 2 + cx.b_kh;
                const uint32_t off = r * 64 + ((uint32_t)(c ^ ((r >> 1) & 3)) << 4);
                ldsm_x4(bh[2*jb][0], bh[2*jb][1], bh[2*jb+1][0], bh[2*jb+1][1], bh_b + off);
                ldsm_x4(bl[2*jb][0], bl[2*jb][1], bl[2*jb+1][0], bl[2*jb+1][1], bl_b + off);
            }
            #pragma unroll
            for (int mi = 0; mi < 4; mi++)
                #pragma unroll
                for (int nj = 0; nj < 4; nj++) {
                    float* cc = acc[mi][nj];
                    mma16816(cc[0], cc[1], cc[2], cc[3],
                             ah[mi][0], ah[mi][1], ah[mi][2], ah[mi][3],
                             bh[nj][0], bh[nj][1]);
                    mma16816(cc[0], cc[1], cc[2], cc[3],
                             ah[mi][0], ah[mi][1], ah[mi][2], ah[mi][3],
                             bl[nj][0], bl[nj][1]);
                    mma16816(cc[0], cc[1], cc[2], cc[3],
                             al[mi][0], al[mi][1], al[mi][2], al[mi][3],
                             bh[nj][0], bh[nj][1]);
                }
        }
    }
}

__device__ __forceinline__ void gemm_init_ctx(
    GemmCtx& cx, uint32_t sbase, int tid, int m0, int n0,
    const __nv_bfloat16* Ah, const __nv_bfloat16* Al,
    const __nv_bfloat16* Bh, const __nv_bfloat16* Bl)
{
    cx.sbase = sbase;
    cx.tt  = tid >> 6;
    const int t6 = tid & 63;
    cx.lch = t6 & 3;
    cx.lr0 = t6 >> 2;
    switch (cx.tt) {
        case 0: cx.gsrc = Ah; cx.row0 = m0; break;
        case 1: cx.gsrc = Al; cx.row0 = m0; break;
        case 2: cx.gsrc = Bh; cx.row0 = n0; break;
        default: cx.gsrc = Bl; cx.row0 = n0; break;
    }
    const int wid = tid >> 5, lane = tid & 31;
    cx.m0w = (wid & 1) * 64;
    cx.n0w = (wid >> 1) * 32;
    cx.a_row = lane & 15;
    cx.a_kh  = lane >> 4;
    cx.b_row = (lane & 7) + ((lane >> 4) & 1) * 8;
    cx.b_kh  = (lane >> 3) & 1;
}

// ---------------------------------------------------------------------------
// Plain GEMM (fp32 C output) — used for the output projection.
// ---------------------------------------------------------------------------
__global__ __launch_bounds__(256)
void gemm_mma(const __nv_bfloat16* __restrict__ Ah, const __nv_bfloat16* __restrict__ Al,
              const __nv_bfloat16* __restrict__ Bh, const __nv_bfloat16* __restrict__ Bl,
              float* __restrict__ C, int ldc)
{
    extern __shared__ char dsm[];
    const int tid = threadIdx.x;
    const int lane = tid & 31;
    const int m0 = blockIdx.y * 128;
    const int n0 = blockIdx.x * 128;

    GemmCtx cx;
    gemm_init_ctx(cx, smem_u32(dsm), tid, m0, n0, Ah, Al, Bh, Bl);

    float acc[4][4][4];
    #pragma unroll
    for (int i = 0; i < 4; i++)
        #pragma unroll
        for (int j = 0; j < 4; j++)
            #pragma unroll
            for (int q = 0; q < 4; q++) acc[i][j][q] = 0.0f;

    gemm_mainloop(cx, acc);

    const int er = lane >> 2;
    const int ec = (lane & 3) * 2;
    #pragma unroll
    for (int mi = 0; mi < 4; mi++) {
        const int row_a = m0 + cx.m0w + mi * 16 + er;
        #pragma unroll
        for (int nj = 0; nj < 4; nj++) {
            const int col = n0 + cx.n0w + nj * 8 + ec;
            float* cc = acc[mi][nj];
            *reinterpret_cast<float2*>(C + (size_t)row_a * ldc + col) =
                make_float2(cc[0], cc[1]);
            *reinterpret_cast<float2*>(C + (size_t)(row_a + 8) * ldc + col) =
                make_float2(cc[2], cc[3]);
        }
    }
}

// ---------------------------------------------------------------------------
// QKV GEMM with fused RoPE + scale + hi/lo split epilogue.
// n-tile == one head (128 cols), so RoPE pairs (i, i+64) stay in-CTA.
// ---------------------------------------------------------------------------
__global__ __launch_bounds__(256)
void gemm_qkv_fused(const __nv_bfloat16* __restrict__ Ah, const __nv_bfloat16* __restrict__ Al,
                    const __nv_bfloat16* __restrict__ Bh, const __nv_bfloat16* __restrict__ Bl,
                    __nv_bfloat16* __restrict__ Qh, __nv_bfloat16* __restrict__ Ql,
                    __nv_bfloat16* __restrict__ Kh, __nv_bfloat16* __restrict__ Kl,
                    __nv_bfloat16* __restrict__ Vh, __nv_bfloat16* __restrict__ Vl)
{
    extern __shared__ char dsm[];
    const int tid = threadIdx.x;
    const int lane = tid & 31;
    const int m0 = blockIdx.y * 128;
    const int n0 = blockIdx.x * 128;

    GemmCtx cx;
    gemm_init_ctx(cx, smem_u32(dsm), tid, m0, n0, Ah, Al, Bh, Bl);

    float acc[4][4][4];
    #pragma unroll
    for (int i = 0; i < 4; i++)
        #pragma unroll
        for (int j = 0; j < 4; j++)
            #pragma unroll
            for (int q = 0; q < 4; q++) acc[i][j][q] = 0.0f;

    gemm_mainloop(cx, acc);

    // ---- stage fp32 tile to smem [128][132] ----
    __syncthreads();   // all warps done reading pipeline stages
    float* ft = reinterpret_cast<float*>(dsm);
    const int er = lane >> 2;
    const int ec = (lane & 3) * 2;
    #pragma unroll
    for (int mi = 0; mi < 4; mi++) {
        const int r = cx.m0w + mi * 16 + er;
        #pragma unroll
        for (int nj = 0; nj < 4; nj++) {
            const int c = cx.n0w + nj * 8 + ec;
            float* cc = acc[mi][nj];
            *reinterpret_cast<float2*>(ft + r * 132 + c)       = make_float2(cc[0], cc[1]);
            *reinterpret_cast<float2*>(ft + (r + 8) * 132 + c) = make_float2(cc[2], cc[3]);
        }
    }
    __syncthreads();

    // ---- fused epilogue by region ----
    if (n0 < QCOLS) {
        // Q head: rope + scale + split
        const int head = n0 >> 7;
        const float scale = 0.08838834764831845f;
        for (int it = 0; it < 32; it++) {
            const int idx = tid + it * 256;      // 8192 = 128 rows x 64 pairs
            const int r = idx >> 6, i = idx & 63;
            const int grow = m0 + r;
            const int pos = grow & (SEQ - 1);
            const float x1 = ft[r * 132 + i];
            const float x2 = ft[r * 132 + i + 64];
            const float c = g_cos[pos * 64 + i];
            const float s = g_sin[pos * 64 + i];
            const float y1 = (x1 * c - x2 * s) * scale;
            const float y2 = (x2 * c + x1 * s) * scale;
            const __nv_bfloat16 h1 = __float2bfloat16_rn(y1);
            const __nv_bfloat16 h2 = __float2bfloat16_rn(y2);
            const size_t o = (size_t)grow * QCOLS + head * HDIM + i;
            Qh[o]      = h1;
            Qh[o + 64] = h2;
            Ql[o]      = __float2bfloat16_rn(y1 - __bfloat162float(h1));
            Ql[o + 64] = __float2bfloat16_rn(y2 - __bfloat162float(h2));
        }
    } else if (n0 < QCOLS + KCOLS) {
        // K head: rope + split
        const int head = (n0 - QCOLS) >> 7;
        for (int it = 0; it < 32; it++) {
            const int idx = tid + it * 256;
            const int r = idx >> 6, i = idx & 63;
            const int grow = m0 + r;
            const int pos = grow & (SEQ - 1);
            const float x1 = ft[r * 132 + i];
            const float x2 = ft[r * 132 + i + 64];
            const float c = g_cos[pos * 64 + i];
            const float s = g_sin[pos * 64 + i];
            const float y1 = x1 * c - x2 * s;
            const float y2 = x2 * c + x1 * s;
            const __nv_bfloat16 h1 = __float2bfloat16_rn(y1);
            const __nv_bfloat16 h2 = __float2bfloat16_rn(y2);
            const size_t o = (size_t)grow * KCOLS + head * HDIM + i;
            Kh[o]      = h1;
            Kh[o + 64] = h2;
            Kl[o]      = __float2bfloat16_rn(y1 - __bfloat162float(h1));
            Kl[o + 64] = __float2bfloat16_rn(y2 - __bfloat162float(h2));
        }
    } else {
        // V head: plain split
        const int cbase = n0 - (QCOLS + KCOLS);
        for (int it = 0; it < 64; it++) {
            const int idx = tid + it * 256;      // 16384 = 128 x 128
            const int r = idx >> 7, c = idx & 127;
            const int grow = m0 + r;
            const float x = ft[r * 132 + c];
            const __nv_bfloat16 h = __float2bfloat16_rn(x);
            const size_t o = (size_t)grow * KCOLS + cbase + c;
            Vh[o] = h;
            Vl[o] = __float2bfloat16_rn(x - __bfloat162float(h));
        }
    }
}

// ---------------------------------------------------------------------------
// Flash attention on tensor cores (hi/lo 3-product), qt processed descending.
// ---------------------------------------------------------------------------
#define FQT 128
#define FKT 64
#define FQ_B    32768
#define FTILE_B 16384
#define FKV_B   (4*FTILE_B)
#define FLASH_SMEM (2*FQ_B + 2*FKV_B)   // 192KB

__global__ __launch_bounds__(256, 1)
void flash_mma(const __nv_bfloat16* __restrict__ Qh_g, const __nv_bfloat16* __restrict__ Ql_g,
               const __nv_bfloat16* __restrict__ Kh_g, const __nv_bfloat16* __restrict__ Kl_g,
               const __nv_bfloat16* __restrict__ Vh_g, const __nv_bfloat16* __restrict__ Vl_g,
               __nv_bfloat16* __restrict__ Ch_g, __nv_bfloat16* __restrict__ Cl_g)
{
    extern __shared__ char dsm[];
    const uint32_t sb = smem_u32(dsm);
    const uint32_t Qh_s = sb, Ql_s = sb + FQ_B;
    const uint32_t KV_s = sb + 2 * FQ_B;

    const int tid = threadIdx.x;
    const int w = tid >> 5, lane = tid & 31;
    const int qt = gridDim.x - 1 - blockIdx.x;    // heavy tiles first
    const int h = blockIdx.y, b = blockIdx.z;
    const int kvh = h >> 2;
    const int qrow0 = b * SEQ + qt * FQT;
    const int nkt = 2 * qt + 2;

    {
        const int c = tid & 15, r0 = tid >> 4;
        #pragma unroll
        for (int i = 0; i < 8; i++) {
            const int r = r0 + i * 16;
            const size_t go = (size_t)(qrow0 + r) * QCOLS + h * HDIM + c * 8;
            cp_async16(Qh_s + SW(r, c), Qh_g + go);
            cp_async16(Ql_s + SW(r, c), Ql_g + go);
        }
    }

    auto load_kv = [&](int kt, int st) {
        const int c = tid & 15, r0 = tid >> 4;
        const uint32_t base = KV_s + st * FKV_B;
        const int krow0 = b * SEQ + kt * FKT;
        #pragma unroll
        for (int i = 0; i < 4; i++) {
            const int r = r0 + i * 16;
            const size_t go = (size_t)(krow0 + r) * KCOLS + kvh * HDIM + c * 8;
            cp_async16(base +             SW(r, c), Kh_g + go);
            cp_async16(base +   FTILE_B + SW(r, c), Kl_g + go);
            cp_async16(base + 2*FTILE_B + SW(r, c), Vh_g + go);
            cp_async16(base + 3*FTILE_B + SW(r, c), Vl_g + go);
        }
        asm volatile("cp.async.commit_group;\n" ::: "memory");
    };

    load_kv(0, 0);
    asm volatile("cp.async.commit_group;\n" ::: "memory");

    const int er = lane >> 2, ec = lane & 3;
    const int a_row = w * 16 + (lane & 15);
    const int a_kh  = lane >> 4;
    const int b_n   = (lane & 7) + ((lane >> 4) & 1) * 8;
    const int b_kh  = (lane >> 3) & 1;
    const int v_key = (lane & 7) + ((lane >> 3) & 1) * 8;
    const int v_dc  = lane >> 4;

    const int rg0 = qt * FQT + w * 16 + er;
    const int rg1 = rg0 + 8;

    float o[16][4];
    #pragma unroll
    for (int j = 0; j < 16; j++)
        #pragma unroll
        for (int q = 0; q < 4; q++) o[j][q] = 0.0f;
    float m0 = -1e30f, m1 = -1e30f, l0 = 0.0f, l1 = 0.0f;

    for (int kt = 0; kt < nkt; kt++) {
        const int st = kt & 1;
        if (kt + 1 < nkt) {
            load_kv(kt + 1, (kt + 1) & 1);
            asm volatile("cp.async.wait_group 1;\n" ::: "memory");
        } else {
            asm volatile("cp.async.wait_group 0;\n" ::: "memory");
        }
        __syncthreads();

        const uint32_t Kh_s = KV_s + st * FKV_B;
        const uint32_t Kl_s = Kh_s + FTILE_B;
        const uint32_t Vh_s = Kh_s + 2 * FTILE_B;
        const uint32_t Vl_s = Kh_s + 3 * FTILE_B;

        float s[8][4];
        #pragma unroll
        for (int f = 0; f < 8; f++)
            #pragma unroll
            for (int q = 0; q < 4; q++) s[f][q] = 0.0f;

        #pragma unroll
        for (int ks = 0; ks < 8; ks++) {
            uint32_t qah[4], qal[4];
            ldsm_x4(qah[0], qah[1], qah[2], qah[3], Qh_s + SW(a_row, ks*2 + a_kh));
            ldsm_x4(qal[0], qal[1], qal[2], qal[3], Ql_s + SW(a_row, ks*2 + a_kh));
            #pragma unroll
            for (int ng = 0; ng < 4; ng++) {
                uint32_t kh0, kh1, kh2, kh3, kl0, kl1, kl2, kl3;
                ldsm_x4(kh0, kh1, kh2, kh3, Kh_s + SW(ng*16 + b_n, ks*2 + b_kh));
                ldsm_x4(kl0, kl1, kl2, kl3, Kl_s + SW(ng*16 + b_n, ks*2 + b_kh));
                float* s0 = s[ng*2];
                float* s1 = s[ng*2 + 1];
                mma16816(s0[0], s0[1], s0[2], s0[3], qah[0], qah[1], qah[2], qah[3], kh0, kh1);
                mma16816(s0[0], s0[1], s0[2], s0[3], qah[0], qah[1], qah[2], qah[3], kl0, kl1);
                mma16816(s0[0], s0[1], s0[2], s0[3], qal[0], qal[1], qal[2], qal[3], kh0, kh1);
                mma16816(s1[0], s1[1], s1[2], s1[3], qah[0], qah[1], qah[2], qah[3], kh2, kh3);
                mma16816(s1[0], s1[1], s1[2], s1[3], qah[0], qah[1], qah[2], qah[3], kl2, kl3);
                mma16816(s1[0], s1[1], s1[2], s1[3], qal[0], qal[1], qal[2], qal[3], kh2, kh3);
            }
        }

        if (kt >= 2 * qt) {
            #pragma unroll
            for (int f = 0; f < 8; f++) {
                const int key0 = kt * FKT + f * 8 + ec * 2;
                if (key0     > rg0) s[f][0] = -1e30f;
                if (key0 + 1 > rg0) s[f][1] = -1e30f;
                if (key0     > rg1) s[f][2] = -1e30f;
                if (key0 + 1 > rg1) s[f][3] = -1e30f;
            }
        }

        float nm0 = -1e30f, nm1 = -1e30f;
        #pragma unroll
        for (int f = 0; f < 8; f++) {
            nm0 = fmaxf(nm0, fmaxf(s[f][0], s[f][1]));
            nm1 = fmaxf(nm1, fmaxf(s[f][2], s[f][3]));
        }
        nm0 = fmaxf(nm0, __shfl_xor_sync(0xffffffffu, nm0, 1));
        nm0 = fmaxf(nm0, __shfl_xor_sync(0xffffffffu, nm0, 2));
        nm1 = fmaxf(nm1, __shfl_xor_sync(0xffffffffu, nm1, 1));
        nm1 = fmaxf(nm1, __shfl_xor_sync(0xffffffffu, nm1, 2));
        nm0 = fmaxf(nm0, m0);
        nm1 = fmaxf(nm1, m1);
        const float corr0 = __expf(m0 - nm0);
        const float corr1 = __expf(m1 - nm1);
        m0 = nm0;
        m1 = nm1;

        float rs0 = 0.0f, rs1 = 0.0f;
        #pragma unroll
        for (int f = 0; f < 8; f++) {
            s[f][0] = __expf(s[f][0] - nm0);
            s[f][1] = __expf(s[f][1] - nm0);
            s[f][2] = __expf(s[f][2] - nm1);
            s[f][3] = __expf(s[f][3] - nm1);
            rs0 += s[f][0] + s[f][1];
            rs1 += s[f][2] + s[f][3];
        }
        rs0 += __shfl_xor_sync(0xffffffffu, rs0, 1);
        rs0 += __shfl_xor_sync(0xffffffffu, rs0, 2);
        rs1 += __shfl_xor_sync(0xffffffffu, rs1, 1);
        rs1 += __shfl_xor_sync(0xffffffffu, rs1, 2);
        l0 = l0 * corr0 + rs0;
        l1 = l1 * corr1 + rs1;
        #pragma unroll
        for (int j = 0; j < 16; j++) {
            o[j][0] *= corr0; o[j][1] *= corr0;
            o[j][2] *= corr1; o[j][3] *= corr1;
        }

        #pragma unroll
        for (int kp = 0; kp < 4; kp++) {
            const float* f0 = s[2*kp];
            const float* f1 = s[2*kp + 1];
            uint32_t pah[4], pal[4];
            float r0a, r0b, r1a, r1b, r2a, r2b, r3a, r3b;
            __nv_bfloat162 h2v;
            h2v = __floats2bfloat162_rn(f0[0], f0[1]);
            r0a = f0[0] - __low2float(h2v); r0b = f0[1] - __high2float(h2v);
            pah[0] = *reinterpret_cast<uint32_t*>(&h2v);
            h2v = __floats2bfloat162_rn(f0[2], f0[3]);
            r1a = f0[2] - __low2float(h2v); r1b = f0[3] - __high2float(h2v);
            pah[1] = *reinterpret_cast<uint32_t*>(&h2v);
            h2v = __floats2bfloat162_rn(f1[0], f1[1]);
            r2a = f1[0] - __low2float(h2v); r2b = f1[1] - __high2float(h2v);
            pah[2] = *reinterpret_cast<uint32_t*>(&h2v);
            h2v = __floats2bfloat162_rn(f1[2], f1[3]);
            r3a = f1[2] - __low2float(h2v); r3b = f1[3] - __high2float(h2v);
            pah[3] = *reinterpret_cast<uint32_t*>(&h2v);
            h2v = __floats2bfloat162_rn(r0a, r0b); pal[0] = *reinterpret_cast<uint32_t*>(&h2v);
            h2v = __floats2bfloat162_rn(r1a, r1b); pal[1] = *reinterpret_cast<uint32_t*>(&h2v);
            h2v = __floats2bfloat162_rn(r2a, r2b); pal[2] = *reinterpret_cast<uint32_t*>(&h2v);
            h2v = __floats2bfloat162_rn(r3a, r3b); pal[3] = *reinterpret_cast<uint32_t*>(&h2v);

            #pragma unroll
            for (int nd = 0; nd < 8; nd++) {
                uint32_t vh0, vh1, vh2, vh3, vl0, vl1, vl2, vl3;
                ldsm_x4t(vh0, vh1, vh2, vh3, Vh_s + SW(kp*16 + v_key, nd*2 + v_dc));
                ldsm_x4t(vl0, vl1, vl2, vl3, Vl_s + SW(kp*16 + v_key, nd*2 + v_dc));
                float* o0 = o[nd*2];
                float* o1 = o[nd*2 + 1];
                mma16816(o0[0], o0[1], o0[2], o0[3], pah[0], pah[1], pah[2], pah[3], vh0, vh1);
                mma16816(o0[0], o0[1], o0[2], o0[3], pah[0], pah[1], pah[2], pah[3], vl0, vl1);
                mma16816(o0[0], o0[1], o0[2], o0[3], pal[0], pal[1], pal[2], pal[3], vh0, vh1);
                mma16816(o1[0], o1[1], o1[2], o1[3], pah[0], pah[1], pah[2], pah[3], vh2, vh3);
                mma16816(o1[0], o1[1], o1[2], o1[3], pah[0], pah[1], pah[2], pah[3], vl2, vl3);
                mma16816(o1[0], o1[1], o1[2], o1[3], pal[0], pal[1], pal[2], pal[3], vh2, vh3);
            }
        }
        __syncthreads();
    }

    const float inv0 = 1.0f / l0;
    const float inv1 = 1.0f / l1;
    const size_t row0 = (size_t)(qrow0 + w * 16 + er);
    const size_t row1 = row0 + 8;
    #pragma unroll
    for (int j = 0; j < 16; j++) {
        const int col = h * HDIM + j * 8 + ec * 2;
        float x0 = o[j][0] * inv0, x1 = o[j][1] * inv0;
        float x2 = o[j][2] * inv1, x3 = o[j][3] * inv1;
        __nv_bfloat162 h01 = __floats2bfloat162_rn(x0, x1);
        __nv_bfloat162 h23 = __floats2bfloat162_rn(x2, x3);
        __nv_bfloat162 l01 = __floats2bfloat162_rn(x0 - __low2float(h01), x1 - __high2float(h01));
        __nv_bfloat162 l23 = __floats2bfloat162_rn(x2 - __low2float(h23), x3 - __high2float(h23));
        *reinterpret_cast<__nv_bfloat162*>(Ch_g + row0 * QCOLS + col) = h01;
        *reinterpret_cast<__nv_bfloat162*>(Cl_g + row0 * QCOLS + col) = l01;
        *reinterpret_cast<__nv_bfloat162*>(Ch_g + row1 * QCOLS + col) = h23;
        *reinterpret_cast<__nv_bfloat162*>(Cl_g + row1 * QCOLS + col) = l23;
    }
}

// ---------------------------------------------------------------------------
extern "C" void kernel_launch(void* const* d_in, const int* in_sizes, int n_in,
                              void* d_out, int out_size)
{
    const float* hidden = (const float*)d_in[0];
    const float* Wq = (const float*)d_in[1];
    const float* Wk = (const float*)d_in[2];
    const float* Wv = (const float*)d_in[3];
    const float* Wo = (const float*)d_in[4];
    float* out = (float*)d_out;

    __nv_bfloat16 *ah, *al, *ch, *cl, *qh, *ql, *kh, *kl, *vh, *vl;
    __nv_bfloat16 *wh, *wl, *woh, *wol;
    cudaGetSymbolAddress((void**)&ah, g_ah);  cudaGetSymbolAddress((void**)&al, g_al);
    cudaGetSymbolAddress((void**)&ch, g_ch);  cudaGetSymbolAddress((void**)&cl, g_cl);
    cudaGetSymbolAddress((void**)&qh, g_qh);  cudaGetSymbolAddress((void**)&ql, g_ql);
    cudaGetSymbolAddress((void**)&kh, g_kh);  cudaGetSymbolAddress((void**)&kl, g_kl);
    cudaGetSymbolAddress((void**)&vh, g_vh);  cudaGetSymbolAddress((void**)&vl, g_vl);
    cudaGetSymbolAddress((void**)&wh, g_wh);  cudaGetSymbolAddress((void**)&wl, g_wl);
    cudaGetSymbolAddress((void**)&woh, g_woh); cudaGetSymbolAddress((void**)&wol, g_wol);

    cudaFuncSetAttribute(gemm_mma,
                         cudaFuncAttributeMaxDynamicSharedMemorySize, GEMM_SMEM);
    cudaFuncSetAttribute(gemm_qkv_fused,
                         cudaFuncAttributeMaxDynamicSharedMemorySize, GEMM_SMEM);
    cudaFuncSetAttribute(flash_mma,
                         cudaFuncAttributeMaxDynamicSharedMemorySize, FLASH_SMEM);

    // Split/transpose inputs to bf16 hi/lo (weights into merged [3072][2048])
    split_kernel<<<(ROWS*HID/4 + 255)/256, 256>>>(hidden, ah, al, ROWS*HID/4);
    tsplit_kernel<<<dim3(QCOLS/32, HID/32), dim3(32,8)>>>(Wq, wh, wl, HID, QCOLS);
    tsplit_kernel<<<dim3(KCOLS/32, HID/32), dim3(32,8)>>>(Wk, wh + (size_t)QCOLS*HID,
                                                          wl + (size_t)QCOLS*HID, HID, KCOLS);
    tsplit_kernel<<<dim3(KCOLS/32, HID/32), dim3(32,8)>>>(Wv, wh + (size_t)(QCOLS+KCOLS)*HID,
                                                          wl + (size_t)(QCOLS+KCOLS)*HID, HID, KCOLS);
    tsplit_kernel<<<dim3(HID/32, QCOLS/32), dim3(32,8)>>>(Wo, woh, wol, QCOLS, HID);

    // RoPE table (needed by fused epilogue)
    rope_table_kernel<<<(SEQ*64 + 255)/256, 256>>>();

    // Merged QKV projection with fused RoPE/scale/split epilogue
    gemm_qkv_fused<<<dim3(QKVC/128, ROWS/128), 256, GEMM_SMEM>>>(
        ah, al, wh, wl, qh, ql, kh, kl, vh, vl);

    // Attention (tensor cores), writes ctx hi/lo directly
    flash_mma<<<dim3(SEQ/FQT, NHQ, BATCH), 256, FLASH_SMEM>>>(qh, ql, kh, kl, vh, vl, ch, cl);

    // Output projection
    gemm_mma<<<dim3(HID/128, ROWS/128), 256, GEMM_SMEM>>>(ch, cl, woh, wol, out, HID);
}

// round 8
// speedup vs baseline: 3.1883x; 1.0076x over previous
#include <cuda_runtime.h>
#include <cuda_bf16.h>
#include <math.h>
#include <stdint.h>

// Problem constants
#define BATCH 2
#define SEQ   2048
#define HID   2048
#define NHQ   16
#define NKV   4
#define HDIM  128
#define ROWS  (BATCH*SEQ)          // 4096
#define QCOLS (NHQ*HDIM)           // 2048
#define KCOLS (NKV*HDIM)           // 512
#define QKVC  (QCOLS + 2*KCOLS)    // 3072

// ---------------------------------------------------------------------------
// Device scratch (static — no allocation allowed)
// ---------------------------------------------------------------------------
__device__ float g_cos[SEQ*64];
__device__ float g_sin[SEQ*64];

__device__ __nv_bfloat16 g_ah[ROWS*HID],    g_al[ROWS*HID];     // hidden
__device__ __nv_bfloat16 g_ch[ROWS*QCOLS],  g_cl[ROWS*QCOLS];   // ctx (flash out)
__device__ __nv_bfloat16 g_qh[ROWS*QCOLS],  g_ql[ROWS*QCOLS];   // q (rope+scale)
__device__ __nv_bfloat16 g_kh[ROWS*KCOLS],  g_kl[ROWS*KCOLS];   // k (rope)
__device__ __nv_bfloat16 g_vh[ROWS*KCOLS],  g_vl[ROWS*KCOLS];   // v
__device__ __nv_bfloat16 g_wh[QKVC*HID],    g_wl[QKVC*HID];     // [Wq;Wk;Wv]^T merged
__device__ __nv_bfloat16 g_woh[HID*QCOLS],  g_wol[HID*QCOLS];   // Wo^T

// ---------------------------------------------------------------------------
// Helpers
// ---------------------------------------------------------------------------
__device__ __forceinline__ uint32_t smem_u32(const void* p) {
    uint32_t a;
    asm("{ .reg .u64 t; cvta.to.shared.u64 t, %1; cvt.u32.u64 %0, t; }" : "=r"(a) : "l"(p));
    return a;
}
__device__ __forceinline__ void cp_async16(uint32_t dst, const void* src) {
    asm volatile("cp.async.cg.shared.global [%0], [%1], 16;\n" :: "r"(dst), "l"(src) : "memory");
}
__device__ __forceinline__ void ldsm_x4(uint32_t& r0, uint32_t& r1, uint32_t& r2, uint32_t& r3,
                                        uint32_t addr) {
    asm volatile("ldmatrix.sync.aligned.m8n8.x4.shared.b16 {%0,%1,%2,%3}, [%4];"
                 : "=r"(r0), "=r"(r1), "=r"(r2), "=r"(r3) : "r"(addr));
}
__device__ __forceinline__ void ldsm_x4t(uint32_t& r0, uint32_t& r1, uint32_t& r2, uint32_t& r3,
                                         uint32_t addr) {
    asm volatile("ldmatrix.sync.aligned.m8n8.x4.trans.shared.b16 {%0,%1,%2,%3}, [%4];"
                 : "=r"(r0), "=r"(r1), "=r"(r2), "=r"(r3) : "r"(addr));
}
__device__ __forceinline__ void mma16816(float& c0, float& c1, float& c2, float& c3,
                                         uint32_t a0, uint32_t a1, uint32_t a2, uint32_t a3,
                                         uint32_t b0, uint32_t b1) {
    asm volatile(
        "mma.sync.aligned.m16n8k16.row.col.f32.bf16.bf16.f32 "
        "{%0,%1,%2,%3}, {%4,%5,%6,%7}, {%8,%9}, {%0,%1,%2,%3};"
        : "+f"(c0), "+f"(c1), "+f"(c2), "+f"(c3)
        : "r"(a0), "r"(a1), "r"(a2), "r"(a3), "r"(b0), "r"(b1));
}
// swizzled smem offset for flash: row r (256B rows of bf16[128]), 16B chunk c
#define SW(r, c) ((uint32_t)((r) * 256 + (((c) ^ ((r) & 7)) << 4)))

// ---------------------------------------------------------------------------
// fp32 -> bf16 hi/lo split (row-major, same layout)
// ---------------------------------------------------------------------------
__global__ void split_kernel(const float* __restrict__ in,
                             __nv_bfloat16* __restrict__ hi,
                             __nv_bfloat16* __restrict__ lo, int n4)
{
    int i = blockIdx.x * blockDim.x + threadIdx.x;
    if (i >= n4) return;
    float4 v = reinterpret_cast<const float4*>(in)[i];
    __nv_bfloat16 h0 = __float2bfloat16_rn(v.x);
    __nv_bfloat16 h1 = __float2bfloat16_rn(v.y);
    __nv_bfloat16 h2 = __float2bfloat16_rn(v.z);
    __nv_bfloat16 h3 = __float2bfloat16_rn(v.w);
    __nv_bfloat16 l0 = __float2bfloat16_rn(v.x - __bfloat162float(h0));
    __nv_bfloat16 l1 = __float2bfloat16_rn(v.y - __bfloat162float(h1));
    __nv_bfloat16 l2 = __float2bfloat16_rn(v.z - __bfloat162float(h2));
    __nv_bfloat16 l3 = __float2bfloat16_rn(v.w - __bfloat162float(h3));
    __nv_bfloat162* hp = reinterpret_cast<__nv_bfloat162*>(hi);
    __nv_bfloat162* lp = reinterpret_cast<__nv_bfloat162*>(lo);
    hp[2*i]   = __nv_bfloat162(h0, h1);
    hp[2*i+1] = __nv_bfloat162(h2, h3);
    lp[2*i]   = __nv_bfloat162(l0, l1);
    lp[2*i+1] = __nv_bfloat162(l2, l3);
}

// All four weight transposes+splits in ONE launch (region-dispatched).
// Wq: blocks [0,4096), Wk: [4096,5120), Wv: [5120,6144), Wo: [6144,10240).
// All sources have 2048 rows (Kin contiguous after transpose = 2048).
__global__ void tsplit_all_kernel(const float* __restrict__ Wq, const float* __restrict__ Wk,
                                  const float* __restrict__ Wv, const float* __restrict__ Wo,
                                  __nv_bfloat16* __restrict__ wh, __nv_bfloat16* __restrict__ wl,
                                  __nv_bfloat16* __restrict__ woh, __nv_bfloat16* __restrict__ wol)
{
    __shared__ float t[32][33];
    const int bid = blockIdx.x;
    const float* src;
    __nv_bfloat16 *dh, *dl;
    int Nin, nbx, tile;
    if (bid < 4096)      { src = Wq; dh = wh; dl = wl; Nin = 2048; nbx = 64; tile = bid; }
    else if (bid < 5120) { src = Wk; dh = wh + (size_t)QCOLS*HID; dl = wl + (size_t)QCOLS*HID;
                           Nin = 512; nbx = 16; tile = bid - 4096; }
    else if (bid < 6144) { src = Wv; dh = wh + (size_t)(QCOLS+KCOLS)*HID; dl = wl + (size_t)(QCOLS+KCOLS)*HID;
                           Nin = 512; nbx = 16; tile = bid - 5120; }
    else                 { src = Wo; dh = woh; dl = wol; Nin = 2048; nbx = 64; tile = bid - 6144; }

    const int tx = threadIdx.x, ty = threadIdx.y;
    const int n0 = (tile % nbx) * 32, k0 = (tile / nbx) * 32;
    #pragma unroll
    for (int j = 0; j < 32; j += 8)
        t[ty + j][tx] = src[(size_t)(k0 + ty + j) * Nin + n0 + tx];
    __syncthreads();
    #pragma unroll
    for (int j = 0; j < 32; j += 8) {
        float x = t[tx][ty + j];
        __nv_bfloat16 h = __float2bfloat16_rn(x);
        __nv_bfloat16 l = __float2bfloat16_rn(x - __bfloat162float(h));
        size_t o = (size_t)(n0 + ty + j) * 2048 + k0 + tx;
        dh[o] = h;
        dl[o] = l;
    }
}

// ---------------------------------------------------------------------------
// RoPE table
// ---------------------------------------------------------------------------
__global__ void rope_table_kernel()
{
    int idx = blockIdx.x * blockDim.x + threadIdx.x;
    if (idx >= SEQ * 64) return;
    int pos = idx >> 6, i = idx & 63;
    double inv = exp2(-(double)i * (13.287712379549449 / 64.0));
    double ang = (double)pos * inv;
    const double twopi = 6.283185307179586476925286766559;
    ang -= floor(ang * (1.0 / twopi)) * twopi;
    if (ang > 3.14159265358979323846) ang -= twopi;
    float s, c;
    sincosf((float)ang, &s, &c);
    g_cos[idx] = c;
    g_sin[idx] = s;
}

// ---------------------------------------------------------------------------
// Shared GEMM mainloop: 128x128 CTA tile, bf16 hi/lo 3-product,
// 3-stage cp.async, one sync per K-chunk. 2 CTAs/SM (192KB smem total).
// ---------------------------------------------------------------------------
#define KCH       32
#define NCHUNKS   64
#define TILE_B    8192
#define STAGE_B   (4*TILE_B)    // 32 KB
#define NSTG      3
#define GEMM_SMEM (NSTG*STAGE_B)  // 96 KB

struct GemmCtx {
    uint32_t sbase;
    const __nv_bfloat16* gsrc;
    int row0, tt, lch, lr0;
    int m0w, n0w;
    int a_row, a_kh, b_row, b_kh;
};

__device__ __forceinline__ void gemm_mainloop(
    const GemmCtx& cx, float acc[4][4][4])
{
    auto load_chunk = [&](int ci, int st) {
        const uint32_t tb = cx.sbase + st * STAGE_B + cx.tt * TILE_B;
        #pragma unroll
        for (int i = 0; i < 8; i++) {
            const int r = cx.lr0 + i * 16;
            const uint32_t dst = tb + r * 64 + ((uint32_t)(cx.lch ^ ((r >> 1) & 3)) << 4);
            cp_async16(dst, cx.gsrc + (size_t)(cx.row0 + r) * 2048 + ci * KCH + cx.lch * 8);
        }
        asm volatile("cp.async.commit_group;\n" ::: "memory");
    };

    load_chunk(0, 0);
    load_chunk(1, 1);

    for (int ci = 0; ci < NCHUNKS; ci++) {
        if (ci + 1 < NCHUNKS) asm volatile("cp.async.wait_group 1;\n" ::: "memory");
        else                  asm volatile("cp.async.wait_group 0;\n" ::: "memory");
        __syncthreads();
        if (ci + 2 < NCHUNKS) load_chunk(ci + 2, (ci + 2) % NSTG);

        const int st = ci % NSTG;
        const uint32_t ah_b = cx.sbase + st * STAGE_B;
        const uint32_t al_b = ah_b + TILE_B;
        const uint32_t bh_b = ah_b + 2 * TILE_B;
        const uint32_t bl_b = ah_b + 3 * TILE_B;

        #pragma unroll
        for (int ks = 0; ks < 2; ks++) {
            uint32_t ah[4][4], al[4][4];
            #pragma unroll
            for (int mi = 0; mi < 4; mi++) {
                const int r = cx.m0w + mi * 16 + cx.a_row;
                const int c = ks * 2 + cx.a_kh;
                const uint32_t off = r * 64 + ((uint32_t)(c ^ ((r >> 1) & 3)) << 4);
                ldsm_x4(ah[mi][0], ah[mi][1], ah[mi][2], ah[mi][3], ah_b + off);
                ldsm_x4(al[mi][0], al[mi][1], al[mi][2], al[mi][3], al_b + off);
            }
            uint32_t bh[4][2], bl[4][2];
            #pragma unroll
            for (int jb = 0; jb < 2; jb++) {
                const int r = cx.n0w + jb * 16 + cx.b_row;
                const int c = ks * 2 + cx.b_kh;
                const uint32_t off = r * 64 + ((uint32_t)(c ^ ((r >> 1) & 3)) << 4);
                ldsm_x4(bh[2*jb][0], bh[2*jb][1], bh[2*jb+1][0], bh[2*jb+1][1], bh_b + off);
                ldsm_x4(bl[2*jb][0], bl[2*jb][1], bl[2*jb+1][0], bl[2*jb+1][1], bl_b + off);
            }
            #pragma unroll
            for (int mi = 0; mi < 4; mi++)
                #pragma unroll
                for (int nj = 0; nj < 4; nj++) {
                    float* cc = acc[mi][nj];
                    mma16816(cc[0], cc[1], cc[2], cc[3],
                             ah[mi][0], ah[mi][1], ah[mi][2], ah[mi][3],
                             bh[nj][0], bh[nj][1]);
                    mma16816(cc[0], cc[1], cc[2], cc[3],
                             ah[mi][0], ah[mi][1], ah[mi][2], ah[mi][3],
                             bl[nj][0], bl[nj][1]);
                    mma16816(cc[0], cc[1], cc[2], cc[3],
                             al[mi][0], al[mi][1], al[mi][2], al[mi][3],
                             bh[nj][0], bh[nj][1]);
                }
        }
    }
}

__device__ __forceinline__ void gemm_init_ctx(
    GemmCtx& cx, uint32_t sbase, int tid, int m0, int n0,
    const __nv_bfloat16* Ah, const __nv_bfloat16* Al,
    const __nv_bfloat16* Bh, const __nv_bfloat16* Bl)
{
    cx.sbase = sbase;
    cx.tt  = tid >> 6;
    const int t6 = tid & 63;
    cx.lch = t6 & 3;
    cx.lr0 = t6 >> 2;
    switch (cx.tt) {
        case 0: cx.gsrc = Ah; cx.row0 = m0; break;
        case 1: cx.gsrc = Al; cx.row0 = m0; break;
        case 2: cx.gsrc = Bh; cx.row0 = n0; break;
        default: cx.gsrc = Bl; cx.row0 = n0; break;
    }
    const int wid = tid >> 5, lane = tid & 31;
    cx.m0w = (wid & 1) * 64;
    cx.n0w = (wid >> 1) * 32;
    cx.a_row = lane & 15;
    cx.a_kh  = lane >> 4;
    cx.b_row = (lane & 7) + ((lane >> 4) & 1) * 8;
    cx.b_kh  = (lane >> 3) & 1;
}

// ---------------------------------------------------------------------------
// Plain GEMM (fp32 C output) — output projection. 2 CTAs/SM target.
// ---------------------------------------------------------------------------
__global__ __launch_bounds__(256, 2)
void gemm_mma(const __nv_bfloat16* __restrict__ Ah, const __nv_bfloat16* __restrict__ Al,
              const __nv_bfloat16* __restrict__ Bh, const __nv_bfloat16* __restrict__ Bl,
              float* __restrict__ C, int ldc)
{
    extern __shared__ char dsm[];
    const int tid = threadIdx.x;
    const int lane = tid & 31;
    const int m0 = blockIdx.y * 128;
    const int n0 = blockIdx.x * 128;

    GemmCtx cx;
    gemm_init_ctx(cx, smem_u32(dsm), tid, m0, n0, Ah, Al, Bh, Bl);

    float acc[4][4][4];
    #pragma unroll
    for (int i = 0; i < 4; i++)
        #pragma unroll
        for (int j = 0; j < 4; j++)
            #pragma unroll
            for (int q = 0; q < 4; q++) acc[i][j][q] = 0.0f;

    gemm_mainloop(cx, acc);

    const int er = lane >> 2;
    const int ec = (lane & 3) * 2;
    #pragma unroll
    for (int mi = 0; mi < 4; mi++) {
        const int row_a = m0 + cx.m0w + mi * 16 + er;
        #pragma unroll
        for (int nj = 0; nj < 4; nj++) {
            const int col = n0 + cx.n0w + nj * 8 + ec;
            float* cc = acc[mi][nj];
            *reinterpret_cast<float2*>(C + (size_t)row_a * ldc + col) =
                make_float2(cc[0], cc[1]);
            *reinterpret_cast<float2*>(C + (size_t)(row_a + 8) * ldc + col) =
                make_float2(cc[2], cc[3]);
        }
    }
}

// ---------------------------------------------------------------------------
// QKV GEMM with fused RoPE + scale + hi/lo split epilogue. 2 CTAs/SM target.
// ---------------------------------------------------------------------------
__global__ __launch_bounds__(256, 2)
void gemm_qkv_fused(const __nv_bfloat16* __restrict__ Ah, const __nv_bfloat16* __restrict__ Al,
                    const __nv_bfloat16* __restrict__ Bh, const __nv_bfloat16* __restrict__ Bl,
                    __nv_bfloat16* __restrict__ Qh, __nv_bfloat16* __restrict__ Ql,
                    __nv_bfloat16* __restrict__ Kh, __nv_bfloat16* __restrict__ Kl,
                    __nv_bfloat16* __restrict__ Vh, __nv_bfloat16* __restrict__ Vl)
{
    extern __shared__ char dsm[];
    const int tid = threadIdx.x;
    const int lane = tid & 31;
    const int m0 = blockIdx.y * 128;
    const int n0 = blockIdx.x * 128;

    GemmCtx cx;
    gemm_init_ctx(cx, smem_u32(dsm), tid, m0, n0, Ah, Al, Bh, Bl);

    float acc[4][4][4];
    #pragma unroll
    for (int i = 0; i < 4; i++)
        #pragma unroll
        for (int j = 0; j < 4; j++)
            #pragma unroll
            for (int q = 0; q < 4; q++) acc[i][j][q] = 0.0f;

    gemm_mainloop(cx, acc);

    // ---- stage fp32 tile to smem [128][132] ----
    __syncthreads();   // all warps done reading pipeline stages
    float* ft = reinterpret_cast<float*>(dsm);
    const int er = lane >> 2;
    const int ec = (lane & 3) * 2;
    #pragma unroll
    for (int mi = 0; mi < 4; mi++) {
        const int r = cx.m0w + mi * 16 + er;
        #pragma unroll
        for (int nj = 0; nj < 4; nj++) {
            const int c = cx.n0w + nj * 8 + ec;
            float* cc = acc[mi][nj];
            *reinterpret_cast<float2*>(ft + r * 132 + c)       = make_float2(cc[0], cc[1]);
            *reinterpret_cast<float2*>(ft + (r + 8) * 132 + c) = make_float2(cc[2], cc[3]);
        }
    }
    __syncthreads();

    // ---- fused epilogue by region ----
    if (n0 < QCOLS) {
        const int head = n0 >> 7;
        const float scale = 0.08838834764831845f;
        for (int it = 0; it < 32; it++) {
            const int idx = tid + it * 256;
            const int r = idx >> 6, i = idx & 63;
            const int grow = m0 + r;
            const int pos = grow & (SEQ - 1);
            const float x1 = ft[r * 132 + i];
            const float x2 = ft[r * 132 + i + 64];
            const float c = g_cos[pos * 64 + i];
            const float s = g_sin[pos * 64 + i];
            const float y1 = (x1 * c - x2 * s) * scale;
            const float y2 = (x2 * c + x1 * s) * scale;
            const __nv_bfloat16 h1 = __float2bfloat16_rn(y1);
            const __nv_bfloat16 h2 = __float2bfloat16_rn(y2);
            const size_t o = (size_t)grow * QCOLS + head * HDIM + i;
            Qh[o]      = h1;
            Qh[o + 64] = h2;
            Ql[o]      = __float2bfloat16_rn(y1 - __bfloat162float(h1));
            Ql[o + 64] = __float2bfloat16_rn(y2 - __bfloat162float(h2));
        }
    } else if (n0 < QCOLS + KCOLS) {
        const int head = (n0 - QCOLS) >> 7;
        for (int it = 0; it < 32; it++) {
            const int idx = tid + it * 256;
            const int r = idx >> 6, i = idx & 63;
            const int grow = m0 + r;
            const int pos = grow & (SEQ - 1);
            const float x1 = ft[r * 132 + i];
            const float x2 = ft[r * 132 + i + 64];
            const float c = g_cos[pos * 64 + i];
            const float s = g_sin[pos * 64 + i];
            const float y1 = x1 * c - x2 * s;
            const float y2 = x2 * c + x1 * s;
            const __nv_bfloat16 h1 = __float2bfloat16_rn(y1);
            const __nv_bfloat16 h2 = __float2bfloat16_rn(y2);
            const size_t o = (size_t)grow * KCOLS + head * HDIM + i;
            Kh[o]      = h1;
            Kh[o + 64] = h2;
            Kl[o]      = __float2bfloat16_rn(y1 - __bfloat162float(h1));
            Kl[o + 64] = __float2bfloat16_rn(y2 - __bfloat162float(h2));
        }
    } else {
        const int cbase = n0 - (QCOLS + KCOLS);
        for (int it = 0; it < 64; it++) {
            const int idx = tid + it * 256;
            const int r = idx >> 7, c = idx & 127;
            const int grow = m0 + r;
            const float x = ft[r * 132 + c];
            const __nv_bfloat16 h = __float2bfloat16_rn(x);
            const size_t o = (size_t)grow * KCOLS + cbase + c;
            Vh[o] = h;
            Vl[o] = __float2bfloat16_rn(x - __bfloat162float(h));
        }
    }
}

// ---------------------------------------------------------------------------
// Flash attention on tensor cores (hi/lo 3-product), qt processed descending.
// ---------------------------------------------------------------------------
#define FQT 128
#define FKT 64
#define FQ_B    32768
#define FTILE_B 16384
#define FKV_B   (4*FTILE_B)
#define FLASH_SMEM (2*FQ_B + 2*FKV_B)   // 192KB

__global__ __launch_bounds__(256, 1)
void flash_mma(const __nv_bfloat16* __restrict__ Qh_g, const __nv_bfloat16* __restrict__ Ql_g,
               const __nv_bfloat16* __restrict__ Kh_g, const __nv_bfloat16* __restrict__ Kl_g,
               const __nv_bfloat16* __restrict__ Vh_g, const __nv_bfloat16* __restrict__ Vl_g,
               __nv_bfloat16* __restrict__ Ch_g, __nv_bfloat16* __restrict__ Cl_g)
{
    extern __shared__ char dsm[];
    const uint32_t sb = smem_u32(dsm);
    const uint32_t Qh_s = sb, Ql_s = sb + FQ_B;
    const uint32_t KV_s = sb + 2 * FQ_B;

    const int tid = threadIdx.x;
    const int w = tid >> 5, lane = tid & 31;
    const int qt = gridDim.x - 1 - blockIdx.x;    // heavy tiles first
    const int h = blockIdx.y, b = blockIdx.z;
    const int kvh = h >> 2;
    const int qrow0 = b * SEQ + qt * FQT;
    const int nkt = 2 * qt + 2;

    {
        const int c = tid & 15, r0 = tid >> 4;
        #pragma unroll
        for (int i = 0; i < 8; i++) {
            const int r = r0 + i * 16;
            const size_t go = (size_t)(qrow0 + r) * QCOLS + h * HDIM + c * 8;
            cp_async16(Qh_s + SW(r, c), Qh_g + go);
            cp_async16(Ql_s + SW(r, c), Ql_g + go);
        }
    }

    auto load_kv = [&](int kt, int st) {
        const int c = tid & 15, r0 = tid >> 4;
        const uint32_t base = KV_s + st * FKV_B;
        const int krow0 = b * SEQ + kt * FKT;
        #pragma unroll
        for (int i = 0; i < 4; i++) {
            const int r = r0 + i * 16;
            const size_t go = (size_t)(krow0 + r) * KCOLS + kvh * HDIM + c * 8;
            cp_async16(base +             SW(r, c), Kh_g + go);
            cp_async16(base +   FTILE_B + SW(r, c), Kl_g + go);
            cp_async16(base + 2*FTILE_B + SW(r, c), Vh_g + go);
            cp_async16(base + 3*FTILE_B + SW(r, c), Vl_g + go);
        }
        asm volatile("cp.async.commit_group;\n" ::: "memory");
    };

    load_kv(0, 0);
    asm volatile("cp.async.commit_group;\n" ::: "memory");

    const int er = lane >> 2, ec = lane & 3;
    const int a_row = w * 16 + (lane & 15);
    const int a_kh  = lane >> 4;
    const int b_n   = (lane & 7) + ((lane >> 4) & 1) * 8;
    const int b_kh  = (lane >> 3) & 1;
    const int v_key = (lane & 7) + ((lane >> 3) & 1) * 8;
    const int v_dc  = lane >> 4;

    const int rg0 = qt * FQT + w * 16 + er;
    const int rg1 = rg0 + 8;

    float o[16][4];
    #pragma unroll
    for (int j = 0; j < 16; j++)
        #pragma unroll
        for (int q = 0; q < 4; q++) o[j][q] = 0.0f;
    float m0 = -1e30f, m1 = -1e30f, l0 = 0.0f, l1 = 0.0f;

    for (int kt = 0; kt < nkt; kt++) {
        const int st = kt & 1;
        if (kt + 1 < nkt) {
            load_kv(kt + 1, (kt + 1) & 1);
            asm volatile("cp.async.wait_group 1;\n" ::: "memory");
        } else {
            asm volatile("cp.async.wait_group 0;\n" ::: "memory");
        }
        __syncthreads();

        const uint32_t Kh_s = KV_s + st * FKV_B;
        const uint32_t Kl_s = Kh_s + FTILE_B;
        const uint32_t Vh_s = Kh_s + 2 * FTILE_B;
        const uint32_t Vl_s = Kh_s + 3 * FTILE_B;

        float s[8][4];
        #pragma unroll
        for (int f = 0; f < 8; f++)
            #pragma unroll
            for (int q = 0; q < 4; q++) s[f][q] = 0.0f;

        #pragma unroll
        for (int ks = 0; ks < 8; ks++) {
            uint32_t qah[4], qal[4];
            ldsm_x4(qah[0], qah[1], qah[2], qah[3], Qh_s + SW(a_row, ks*2 + a_kh));
            ldsm_x4(qal[0], qal[1], qal[2], qal[3], Ql_s + SW(a_row, ks*2 + a_kh));
            #pragma unroll
            for (int ng = 0; ng < 4; ng++) {
                uint32_t kh0, kh1, kh2, kh3, kl0, kl1, kl2, kl3;
                ldsm_x4(kh0, kh1, kh2, kh3, Kh_s + SW(ng*16 + b_n, ks*2 + b_kh));
                ldsm_x4(kl0, kl1, kl2, kl3, Kl_s + SW(ng*16 + b_n, ks*2 + b_kh));
                float* s0 = s[ng*2];
                float* s1 = s[ng*2 + 1];
                mma16816(s0[0], s0[1], s0[2], s0[3], qah[0], qah[1], qah[2], qah[3], kh0, kh1);
                mma16816(s0[0], s0[1], s0[2], s0[3], qah[0], qah[1], qah[2], qah[3], kl0, kl1);
                mma16816(s0[0], s0[1], s0[2], s0[3], qal[0], qal[1], qal[2], qal[3], kh0, kh1);
                mma16816(s1[0], s1[1], s1[2], s1[3], qah[0], qah[1], qah[2], qah[3], kh2, kh3);
                mma16816(s1[0], s1[1], s1[2], s1[3], qah[0], qah[1], qah[2], qah[3], kl2, kl3);
                mma16816(s1[0], s1[1], s1[2], s1[3], qal[0], qal[1], qal[2], qal[3], kh2, kh3);
            }
        }

        if (kt >= 2 * qt) {
            #pragma unroll
            for (int f = 0; f < 8; f++) {
                const int key0 = kt * FKT + f * 8 + ec * 2;
                if (key0     > rg0) s[f][0] = -1e30f;
                if (key0 + 1 > rg0) s[f][1] = -1e30f;
                if (key0     > rg1) s[f][2] = -1e30f;
                if (key0 + 1 > rg1) s[f][3] = -1e30f;
            }
        }

        float nm0 = -1e30f, nm1 = -1e30f;
        #pragma unroll
        for (int f = 0; f < 8; f++) {
            nm0 = fmaxf(nm0, fmaxf(s[f][0], s[f][1]));
            nm1 = fmaxf(nm1, fmaxf(s[f][2], s[f][3]));
        }
        nm0 = fmaxf(nm0, __shfl_xor_sync(0xffffffffu, nm0, 1));
        nm0 = fmaxf(nm0, __shfl_xor_sync(0xffffffffu, nm0, 2));
        nm1 = fmaxf(nm1, __shfl_xor_sync(0xffffffffu, nm1, 1));
        nm1 = fmaxf(nm1, __shfl_xor_sync(0xffffffffu, nm1, 2));
        nm0 = fmaxf(nm0, m0);
        nm1 = fmaxf(nm1, m1);
        const float corr0 = __expf(m0 - nm0);
        const float corr1 = __expf(m1 - nm1);
        m0 = nm0;
        m1 = nm1;

        float rs0 = 0.0f, rs1 = 0.0f;
        #pragma unroll
        for (int f = 0; f < 8; f++) {
            s[f][0] = __expf(s[f][0] - nm0);
            s[f][1] = __expf(s[f][1] - nm0);
            s[f][2] = __expf(s[f][2] - nm1);
            s[f][3] = __expf(s[f][3] - nm1);
            rs0 += s[f][0] + s[f][1];
            rs1 += s[f][2] + s[f][3];
        }
        rs0 += __shfl_xor_sync(0xffffffffu, rs0, 1);
        rs0 += __shfl_xor_sync(0xffffffffu, rs0, 2);
        rs1 += __shfl_xor_sync(0xffffffffu, rs1, 1);
        rs1 += __shfl_xor_sync(0xffffffffu, rs1, 2);
        l0 = l0 * corr0 + rs0;
        l1 = l1 * corr1 + rs1;
        #pragma unroll
        for (int j = 0; j < 16; j++) {
            o[j][0] *= corr0; o[j][1] *= corr0;
            o[j][2] *= corr1; o[j][3] *= corr1;
        }

        #pragma unroll
        for (int kp = 0; kp < 4; kp++) {
            const float* f0 = s[2*kp];
            const float* f1 = s[2*kp + 1];
            uint32_t pah[4], pal[4];
            float r0a, r0b, r1a, r1b, r2a, r2b, r3a, r3b;
            __nv_bfloat162 h2v;
            h2v = __floats2bfloat162_rn(f0[0], f0[1]);
            r0a = f0[0] - __low2float(h2v); r0b = f0[1] - __high2float(h2v);
            pah[0] = *reinterpret_cast<uint32_t*>(&h2v);
            h2v = __floats2bfloat162_rn(f0[2], f0[3]);
            r1a = f0[2] - __low2float(h2v); r1b = f0[3] - __high2float(h2v);
            pah[1] = *reinterpret_cast<uint32_t*>(&h2v);
            h2v = __floats2bfloat162_rn(f1[0], f1[1]);
            r2a = f1[0] - __low2float(h2v); r2b = f1[1] - __high2float(h2v);
            pah[2] = *reinterpret_cast<uint32_t*>(&h2v);
            h2v = __floats2bfloat162_rn(f1[2], f1[3]);
            r3a = f1[2] - __low2float(h2v); r3b = f1[3] - __high2float(h2v);
            pah[3] = *reinterpret_cast<uint32_t*>(&h2v);
            h2v = __floats2bfloat162_rn(r0a, r0b); pal[0] = *reinterpret_cast<uint32_t*>(&h2v);
            h2v = __floats2bfloat162_rn(r1a, r1b); pal[1] = *reinterpret_cast<uint32_t*>(&h2v);
            h2v = __floats2bfloat162_rn(r2a, r2b); pal[2] = *reinterpret_cast<uint32_t*>(&h2v);
            h2v = __floats2bfloat162_rn(r3a, r3b); pal[3] = *reinterpret_cast<uint32_t*>(&h2v);

            #pragma unroll
            for (int nd = 0; nd < 8; nd++) {
                uint32_t vh0, vh1, vh2, vh3, vl0, vl1, vl2, vl3;
                ldsm_x4t(vh0, vh1, vh2, vh3, Vh_s + SW(kp*16 + v_key, nd*2 + v_dc));
                ldsm_x4t(vl0, vl1, vl2, vl3, Vl_s + SW(kp*16 + v_key, nd*2 + v_dc));
                float* o0 = o[nd*2];
                float* o1 = o[nd*2 + 1];
                mma16816(o0[0], o0[1], o0[2], o0[3], pah[0], pah[1], pah[2], pah[3], vh0, vh1);
                mma16816(o0[0], o0[1], o0[2], o0[3], pah[0], pah[1], pah[2], pah[3], vl0, vl1);
                mma16816(o0[0], o0[1], o0[2], o0[3], pal[0], pal[1], pal[2], pal[3], vh0, vh1);
                mma16816(o1[0], o1[1], o1[2], o1[3], pah[0], pah[1], pah[2], pah[3], vh2, vh3);
                mma16816(o1[0], o1[1], o1[2], o1[3], pah[0], pah[1], pah[2], pah[3], vl2, vl3);
                mma16816(o1[0], o1[1], o1[2], o1[3], pal[0], pal[1], pal[2], pal[3], vh2, vh3);
            }
        }
        __syncthreads();
    }

    const float inv0 = 1.0f / l0;
    const float inv1 = 1.0f / l1;
    const size_t row0 = (size_t)(qrow0 + w * 16 + er);
    const size_t row1 = row0 + 8;
    #pragma unroll
    for (int j = 0; j < 16; j++) {
        const int col = h * HDIM + j * 8 + ec * 2;
        float x0 = o[j][0] * inv0, x1 = o[j][1] * inv0;
        float x2 = o[j][2] * inv1, x3 = o[j][3] * inv1;
        __nv_bfloat162 h01 = __floats2bfloat162_rn(x0, x1);
        __nv_bfloat162 h23 = __floats2bfloat162_rn(x2, x3);
        __nv_bfloat162 l01 = __floats2bfloat162_rn(x0 - __low2float(h01), x1 - __high2float(h01));
        __nv_bfloat162 l23 = __floats2bfloat162_rn(x2 - __low2float(h23), x3 - __high2float(h23));
        *reinterpret_cast<__nv_bfloat162*>(Ch_g + row0 * QCOLS + col) = h01;
        *reinterpret_cast<__nv_bfloat162*>(Cl_g + row0 * QCOLS + col) = l01;
        *reinterpret_cast<__nv_bfloat162*>(Ch_g + row1 * QCOLS + col) = h23;
        *reinterpret_cast<__nv_bfloat162*>(Cl_g + row1 * QCOLS + col) = l23;
    }
}

// ---------------------------------------------------------------------------
extern "C" void kernel_launch(void* const* d_in, const int* in_sizes, int n_in,
                              void* d_out, int out_size)
{
    const float* hidden = (const float*)d_in[0];
    const float* Wq = (const float*)d_in[1];
    const float* Wk = (const float*)d_in[2];
    const float* Wv = (const float*)d_in[3];
    const float* Wo = (const float*)d_in[4];
    float* out = (float*)d_out;

    __nv_bfloat16 *ah, *al, *ch, *cl, *qh, *ql, *kh, *kl, *vh, *vl;
    __nv_bfloat16 *wh, *wl, *woh, *wol;
    cudaGetSymbolAddress((void**)&ah, g_ah);  cudaGetSymbolAddress((void**)&al, g_al);
    cudaGetSymbolAddress((void**)&ch, g_ch);  cudaGetSymbolAddress((void**)&cl, g_cl);
    cudaGetSymbolAddress((void**)&qh, g_qh);  cudaGetSymbolAddress((void**)&ql, g_ql);
    cudaGetSymbolAddress((void**)&kh, g_kh);  cudaGetSymbolAddress((void**)&kl, g_kl);
    cudaGetSymbolAddress((void**)&vh, g_vh);  cudaGetSymbolAddress((void**)&vl, g_vl);
    cudaGetSymbolAddress((void**)&wh, g_wh);  cudaGetSymbolAddress((void**)&wl, g_wl);
    cudaGetSymbolAddress((void**)&woh, g_woh); cudaGetSymbolAddress((void**)&wol, g_wol);

    cudaFuncSetAttribute(gemm_mma,
                         cudaFuncAttributeMaxDynamicSharedMemorySize, GEMM_SMEM);
    cudaFuncSetAttribute(gemm_qkv_fused,
                         cudaFuncAttributeMaxDynamicSharedMemorySize, GEMM_SMEM);
    cudaFuncSetAttribute(flash_mma,
                         cudaFuncAttributeMaxDynamicSharedMemorySize, FLASH_SMEM);

    // 1) RoPE table, 2) hidden split, 3) all weight transposes (one launch)
    rope_table_kernel<<<(SEQ*64 + 255)/256, 256>>>();
    split_kernel<<<(ROWS*HID/4 + 255)/256, 256>>>(hidden, ah, al, ROWS*HID/4);
    tsplit_all_kernel<<<10240, dim3(32,8)>>>(Wq, Wk, Wv, Wo, wh, wl, woh, wol);

    // 4) Merged QKV projection with fused RoPE/scale/split epilogue
    gemm_qkv_fused<<<dim3(QKVC/128, ROWS/128), 256, GEMM_SMEM>>>(
        ah, al, wh, wl, qh, ql, kh, kl, vh, vl);

    // 5) Attention (tensor cores), writes ctx hi/lo directly
    flash_mma<<<dim3(SEQ/FQT, NHQ, BATCH), 256, FLASH_SMEM>>>(qh, ql, kh, kl, vh, vl, ch, cl);

    // 6) Output projection
    gemm_mma<<<dim3(HID/128, ROWS/128), 256, GEMM_SMEM>>>(ch, cl, woh, wol, out, HID);
}

// round 9
// speedup vs baseline: 3.1916x; 1.0010x over previous
#include <cuda_runtime.h>
#include <cuda_bf16.h>
#include <math.h>
#include <stdint.h>

// Problem constants
#define BATCH 2
#define SEQ   2048
#define HID   2048
#define NHQ   16
#define NKV   4
#define HDIM  128
#define ROWS  (BATCH*SEQ)          // 4096
#define QCOLS (NHQ*HDIM)           // 2048
#define KCOLS (NKV*HDIM)           // 512
#define QKVC  (QCOLS + 2*KCOLS)    // 3072

// ---------------------------------------------------------------------------
// Device scratch (static — no allocation allowed)
// ---------------------------------------------------------------------------
__device__ float g_cos[SEQ*64];
__device__ float g_sin[SEQ*64];

__device__ __nv_bfloat16 g_ah[ROWS*HID],    g_al[ROWS*HID];     // hidden
__device__ __nv_bfloat16 g_ch[ROWS*QCOLS],  g_cl[ROWS*QCOLS];   // ctx (flash out)
__device__ __nv_bfloat16 g_qh[ROWS*QCOLS],  g_ql[ROWS*QCOLS];   // q (rope+scale)
__device__ __nv_bfloat16 g_kh[ROWS*KCOLS],  g_kl[ROWS*KCOLS];   // k (rope)
__device__ __nv_bfloat16 g_vh[ROWS*KCOLS],  g_vl[ROWS*KCOLS];   // v
__device__ __nv_bfloat16 g_wh[QKVC*HID],    g_wl[QKVC*HID];     // [Wq;Wk;Wv]^T merged
__device__ __nv_bfloat16 g_woh[HID*QCOLS],  g_wol[HID*QCOLS];   // Wo^T

// ---------------------------------------------------------------------------
// Helpers
// ---------------------------------------------------------------------------
__device__ __forceinline__ uint32_t smem_u32(const void* p) {
    uint32_t a;
    asm("{ .reg .u64 t; cvta.to.shared.u64 t, %1; cvt.u32.u64 %0, t; }" : "=r"(a) : "l"(p));
    return a;
}
__device__ __forceinline__ void cp_async16(uint32_t dst, const void* src) {
    asm volatile("cp.async.cg.shared.global [%0], [%1], 16;\n" :: "r"(dst), "l"(src) : "memory");
}
__device__ __forceinline__ void ldsm_x4(uint32_t& r0, uint32_t& r1, uint32_t& r2, uint32_t& r3,
                                        uint32_t addr) {
    asm volatile("ldmatrix.sync.aligned.m8n8.x4.shared.b16 {%0,%1,%2,%3}, [%4];"
                 : "=r"(r0), "=r"(r1), "=r"(r2), "=r"(r3) : "r"(addr));
}
__device__ __forceinline__ void ldsm_x4t(uint32_t& r0, uint32_t& r1, uint32_t& r2, uint32_t& r3,
                                         uint32_t addr) {
    asm volatile("ldmatrix.sync.aligned.m8n8.x4.trans.shared.b16 {%0,%1,%2,%3}, [%4];"
                 : "=r"(r0), "=r"(r1), "=r"(r2), "=r"(r3) : "r"(addr));
}
__device__ __forceinline__ void mma16816(float& c0, float& c1, float& c2, float& c3,
                                         uint32_t a0, uint32_t a1, uint32_t a2, uint32_t a3,
                                         uint32_t b0, uint32_t b1) {
    asm volatile(
        "mma.sync.aligned.m16n8k16.row.col.f32.bf16.bf16.f32 "
        "{%0,%1,%2,%3}, {%4,%5,%6,%7}, {%8,%9}, {%0,%1,%2,%3};"
        : "+f"(c0), "+f"(c1), "+f"(c2), "+f"(c3)
        : "r"(a0), "r"(a1), "r"(a2), "r"(a3), "r"(b0), "r"(b1));
}
// swizzled smem offset for flash: row r (256B rows of bf16[128]), 16B chunk c
#define SW(r, c) ((uint32_t)((r) * 256 + (((c) ^ ((r) & 7)) << 4)))

// ---------------------------------------------------------------------------
// fp32 -> bf16 hi/lo split (row-major, same layout)
// ---------------------------------------------------------------------------
__global__ void split_kernel(const float* __restrict__ in,
                             __nv_bfloat16* __restrict__ hi,
                             __nv_bfloat16* __restrict__ lo, int n4)
{
    int i = blockIdx.x * blockDim.x + threadIdx.x;
    if (i >= n4) return;
    float4 v = reinterpret_cast<const float4*>(in)[i];
    __nv_bfloat16 h0 = __float2bfloat16_rn(v.x);
    __nv_bfloat16 h1 = __float2bfloat16_rn(v.y);
    __nv_bfloat16 h2 = __float2bfloat16_rn(v.z);
    __nv_bfloat16 h3 = __float2bfloat16_rn(v.w);
    __nv_bfloat16 l0 = __float2bfloat16_rn(v.x - __bfloat162float(h0));
    __nv_bfloat16 l1 = __float2bfloat16_rn(v.y - __bfloat162float(h1));
    __nv_bfloat16 l2 = __float2bfloat16_rn(v.z - __bfloat162float(h2));
    __nv_bfloat16 l3 = __float2bfloat16_rn(v.w - __bfloat162float(h3));
    __nv_bfloat162* hp = reinterpret_cast<__nv_bfloat162*>(hi);
    __nv_bfloat162* lp = reinterpret_cast<__nv_bfloat162*>(lo);
    hp[2*i]   = __nv_bfloat162(h0, h1);
    hp[2*i+1] = __nv_bfloat162(h2, h3);
    lp[2*i]   = __nv_bfloat162(l0, l1);
    lp[2*i+1] = __nv_bfloat162(l2, l3);
}

// All four weight transposes+splits in ONE launch (region-dispatched).
__global__ void tsplit_all_kernel(const float* __restrict__ Wq, const float* __restrict__ Wk,
                                  const float* __restrict__ Wv, const float* __restrict__ Wo,
                                  __nv_bfloat16* __restrict__ wh, __nv_bfloat16* __restrict__ wl,
                                  __nv_bfloat16* __restrict__ woh, __nv_bfloat16* __restrict__ wol)
{
    __shared__ float t[32][33];
    const int bid = blockIdx.x;
    const float* src;
    __nv_bfloat16 *dh, *dl;
    int Nin, nbx, tile;
    if (bid < 4096)      { src = Wq; dh = wh; dl = wl; Nin = 2048; nbx = 64; tile = bid; }
    else if (bid < 5120) { src = Wk; dh = wh + (size_t)QCOLS*HID; dl = wl + (size_t)QCOLS*HID;
                           Nin = 512; nbx = 16; tile = bid - 4096; }
    else if (bid < 6144) { src = Wv; dh = wh + (size_t)(QCOLS+KCOLS)*HID; dl = wl + (size_t)(QCOLS+KCOLS)*HID;
                           Nin = 512; nbx = 16; tile = bid - 5120; }
    else                 { src = Wo; dh = woh; dl = wol; Nin = 2048; nbx = 64; tile = bid - 6144; }

    const int tx = threadIdx.x, ty = threadIdx.y;
    const int n0 = (tile % nbx) * 32, k0 = (tile / nbx) * 32;
    #pragma unroll
    for (int j = 0; j < 32; j += 8)
        t[ty + j][tx] = src[(size_t)(k0 + ty + j) * Nin + n0 + tx];
    __syncthreads();
    #pragma unroll
    for (int j = 0; j < 32; j += 8) {
        float x = t[tx][ty + j];
        __nv_bfloat16 h = __float2bfloat16_rn(x);
        __nv_bfloat16 l = __float2bfloat16_rn(x - __bfloat162float(h));
        size_t o = (size_t)(n0 + ty + j) * 2048 + k0 + tx;
        dh[o] = h;
        dl[o] = l;
    }
}

// ---------------------------------------------------------------------------
// RoPE table
// ---------------------------------------------------------------------------
__global__ void rope_table_kernel()
{
    int idx = blockIdx.x * blockDim.x + threadIdx.x;
    if (idx >= SEQ * 64) return;
    int pos = idx >> 6, i = idx & 63;
    double inv = exp2(-(double)i * (13.287712379549449 / 64.0));
    double ang = (double)pos * inv;
    const double twopi = 6.283185307179586476925286766559;
    ang -= floor(ang * (1.0 / twopi)) * twopi;
    if (ang > 3.14159265358979323846) ang -= twopi;
    float s, c;
    sincosf((float)ang, &s, &c);
    g_cos[idx] = c;
    g_sin[idx] = s;
}

// ---------------------------------------------------------------------------
// Shared GEMM mainloop: 128x128 CTA tile, bf16 hi/lo 3-product,
// 3-stage cp.async, one sync per K-chunk, 2 CTAs/SM.
// MMAs issued in 3 passes (hh, hl, lh) so dependent accumulator reuse is
// 16 issues apart — keeps the HMMA pipe saturated.
// ---------------------------------------------------------------------------
#define KCH       32
#define NCHUNKS   64
#define TILE_B    8192
#define STAGE_B   (4*TILE_B)    // 32 KB
#define NSTG      3
#define GEMM_SMEM (NSTG*STAGE_B)  // 96 KB

struct GemmCtx {
    uint32_t sbase;
    const __nv_bfloat16* gsrc;
    int row0, tt, lch, lr0;
    int m0w, n0w;
    int a_row, a_kh, b_row, b_kh;
};

__device__ __forceinline__ void gemm_mainloop(
    const GemmCtx& cx, float acc[4][4][4])
{
    auto load_chunk = [&](int ci, int st) {
        const uint32_t tb = cx.sbase + st * STAGE_B + cx.tt * TILE_B;
        #pragma unroll
        for (int i = 0; i < 8; i++) {
            const int r = cx.lr0 + i * 16;
            const uint32_t dst = tb + r * 64 + ((uint32_t)(cx.lch ^ ((r >> 1) & 3)) << 4);
            cp_async16(dst, cx.gsrc + (size_t)(cx.row0 + r) * 2048 + ci * KCH + cx.lch * 8);
        }
        asm volatile("cp.async.commit_group;\n" ::: "memory");
    };

    load_chunk(0, 0);
    load_chunk(1, 1);

    for (int ci = 0; ci < NCHUNKS; ci++) {
        if (ci + 1 < NCHUNKS) asm volatile("cp.async.wait_group 1;\n" ::: "memory");
        else                  asm volatile("cp.async.wait_group 0;\n" ::: "memory");
        __syncthreads();
        if (ci + 2 < NCHUNKS) load_chunk(ci + 2, (ci + 2) % NSTG);

        const int st = ci % NSTG;
        const uint32_t ah_b = cx.sbase + st * STAGE_B;
        const uint32_t al_b = ah_b + TILE_B;
        const uint32_t bh_b = ah_b + 2 * TILE_B;
        const uint32_t bl_b = ah_b + 3 * TILE_B;

        #pragma unroll
        for (int ks = 0; ks < 2; ks++) {
            uint32_t ah[4][4], al[4][4];
            #pragma unroll
            for (int mi = 0; mi < 4; mi++) {
                const int r = cx.m0w + mi * 16 + cx.a_row;
                const int c = ks * 2 + cx.a_kh;
                const uint32_t off = r * 64 + ((uint32_t)(c ^ ((r >> 1) & 3)) << 4);
                ldsm_x4(ah[mi][0], ah[mi][1], ah[mi][2], ah[mi][3], ah_b + off);
                ldsm_x4(al[mi][0], al[mi][1], al[mi][2], al[mi][3], al_b + off);
            }
            uint32_t bh[4][2], bl[4][2];
            #pragma unroll
            for (int jb = 0; jb < 2; jb++) {
                const int r = cx.n0w + jb * 16 + cx.b_row;
                const int c = ks * 2 + cx.b_kh;
                const uint32_t off = r * 64 + ((uint32_t)(c ^ ((r >> 1) & 3)) << 4);
                ldsm_x4(bh[2*jb][0], bh[2*jb][1], bh[2*jb+1][0], bh[2*jb+1][1], bh_b + off);
                ldsm_x4(bl[2*jb][0], bl[2*jb][1], bl[2*jb+1][0], bl[2*jb+1][1], bl_b + off);
            }
            // Pass 1: hi*hi for all 16 tiles (independent accumulators)
            #pragma unroll
            for (int mi = 0; mi < 4; mi++)
                #pragma unroll
                for (int nj = 0; nj < 4; nj++) {
                    float* cc = acc[mi][nj];
                    mma16816(cc[0], cc[1], cc[2], cc[3],
                             ah[mi][0], ah[mi][1], ah[mi][2], ah[mi][3],
                             bh[nj][0], bh[nj][1]);
                }
            // Pass 2: hi*lo
            #pragma unroll
            for (int mi = 0; mi < 4; mi++)
                #pragma unroll
                for (int nj = 0; nj < 4; nj++) {
                    float* cc = acc[mi][nj];
                    mma16816(cc[0], cc[1], cc[2], cc[3],
                             ah[mi][0], ah[mi][1], ah[mi][2], ah[mi][3],
                             bl[nj][0], bl[nj][1]);
                }
            // Pass 3: lo*hi
            #pragma unroll
            for (int mi = 0; mi < 4; mi++)
                #pragma unroll
                for (int nj = 0; nj < 4; nj++) {
                    float* cc = acc[mi][nj];
                    mma16816(cc[0], cc[1], cc[2], cc[3],
                             al[mi][0], al[mi][1], al[mi][2], al[mi][3],
                             bh[nj][0], bh[nj][1]);
                }
        }
    }
}

__device__ __forceinline__ void gemm_init_ctx(
    GemmCtx& cx, uint32_t sbase, int tid, int m0, int n0,
    const __nv_bfloat16* Ah, const __nv_bfloat16* Al,
    const __nv_bfloat16* Bh, const __nv_bfloat16* Bl)
{
    cx.sbase = sbase;
    cx.tt  = tid >> 6;
    const int t6 = tid & 63;
    cx.lch = t6 & 3;
    cx.lr0 = t6 >> 2;
    switch (cx.tt) {
        case 0: cx.gsrc = Ah; cx.row0 = m0; break;
        case 1: cx.gsrc = Al; cx.row0 = m0; break;
        case 2: cx.gsrc = Bh; cx.row0 = n0; break;
        default: cx.gsrc = Bl; cx.row0 = n0; break;
    }
    const int wid = tid >> 5, lane = tid & 31;
    cx.m0w = (wid & 1) * 64;
    cx.n0w = (wid >> 1) * 32;
    cx.a_row = lane & 15;
    cx.a_kh  = lane >> 4;
    cx.b_row = (lane & 7) + ((lane >> 4) & 1) * 8;
    cx.b_kh  = (lane >> 3) & 1;
}

// ---------------------------------------------------------------------------
// Plain GEMM (fp32 C output) — output projection.
// ---------------------------------------------------------------------------
__global__ __launch_bounds__(256, 2)
void gemm_mma(const __nv_bfloat16* __restrict__ Ah, const __nv_bfloat16* __restrict__ Al,
              const __nv_bfloat16* __restrict__ Bh, const __nv_bfloat16* __restrict__ Bl,
              float* __restrict__ C, int ldc)
{
    extern __shared__ char dsm[];
    const int tid = threadIdx.x;
    const int lane = tid & 31;
    const int m0 = blockIdx.y * 128;
    const int n0 = blockIdx.x * 128;

    GemmCtx cx;
    gemm_init_ctx(cx, smem_u32(dsm), tid, m0, n0, Ah, Al, Bh, Bl);

    float acc[4][4][4];
    #pragma unroll
    for (int i = 0; i < 4; i++)
        #pragma unroll
        for (int j = 0; j < 4; j++)
            #pragma unroll
            for (int q = 0; q < 4; q++) acc[i][j][q] = 0.0f;

    gemm_mainloop(cx, acc);

    const int er = lane >> 2;
    const int ec = (lane & 3) * 2;
    #pragma unroll
    for (int mi = 0; mi < 4; mi++) {
        const int row_a = m0 + cx.m0w + mi * 16 + er;
        #pragma unroll
        for (int nj = 0; nj < 4; nj++) {
            const int col = n0 + cx.n0w + nj * 8 + ec;
            float* cc = acc[mi][nj];
            *reinterpret_cast<float2*>(C + (size_t)row_a * ldc + col) =
                make_float2(cc[0], cc[1]);
            *reinterpret_cast<float2*>(C + (size_t)(row_a + 8) * ldc + col) =
                make_float2(cc[2], cc[3]);
        }
    }
}

// ---------------------------------------------------------------------------
// QKV GEMM with fused RoPE + scale + hi/lo split epilogue.
// ---------------------------------------------------------------------------
__global__ __launch_bounds__(256, 2)
void gemm_qkv_fused(const __nv_bfloat16* __restrict__ Ah, const __nv_bfloat16* __restrict__ Al,
                    const __nv_bfloat16* __restrict__ Bh, const __nv_bfloat16* __restrict__ Bl,
                    __nv_bfloat16* __restrict__ Qh, __nv_bfloat16* __restrict__ Ql,
                    __nv_bfloat16* __restrict__ Kh, __nv_bfloat16* __restrict__ Kl,
                    __nv_bfloat16* __restrict__ Vh, __nv_bfloat16* __restrict__ Vl)
{
    extern __shared__ char dsm[];
    const int tid = threadIdx.x;
    const int lane = tid & 31;
    const int m0 = blockIdx.y * 128;
    const int n0 = blockIdx.x * 128;

    GemmCtx cx;
    gemm_init_ctx(cx, smem_u32(dsm), tid, m0, n0, Ah, Al, Bh, Bl);

    float acc[4][4][4];
    #pragma unroll
    for (int i = 0; i < 4; i++)
        #pragma unroll
        for (int j = 0; j < 4; j++)
            #pragma unroll
            for (int q = 0; q < 4; q++) acc[i][j][q] = 0.0f;

    gemm_mainloop(cx, acc);

    // ---- stage fp32 tile to smem [128][132] ----
    __syncthreads();
    float* ft = reinterpret_cast<float*>(dsm);
    const int er = lane >> 2;
    const int ec = (lane & 3) * 2;
    #pragma unroll
    for (int mi = 0; mi < 4; mi++) {
        const int r = cx.m0w + mi * 16 + er;
        #pragma unroll
        for (int nj = 0; nj < 4; nj++) {
            const int c = cx.n0w + nj * 8 + ec;
            float* cc = acc[mi][nj];
            *reinterpret_cast<float2*>(ft + r * 132 + c)       = make_float2(cc[0], cc[1]);
            *reinterpret_cast<float2*>(ft + (r + 8) * 132 + c) = make_float2(cc[2], cc[3]);
        }
    }
    __syncthreads();

    // ---- fused epilogue by region ----
    if (n0 < QCOLS) {
        const int head = n0 >> 7;
        const float scale = 0.08838834764831845f;
        for (int it = 0; it < 32; it++) {
            const int idx = tid + it * 256;
            const int r = idx >> 6, i = idx & 63;
            const int grow = m0 + r;
            const int pos = grow & (SEQ - 1);
            const float x1 = ft[r * 132 + i];
            const float x2 = ft[r * 132 + i + 64];
            const float c = g_cos[pos * 64 + i];
            const float s = g_sin[pos * 64 + i];
            const float y1 = (x1 * c - x2 * s) * scale;
            const float y2 = (x2 * c + x1 * s) * scale;
            const __nv_bfloat16 h1 = __float2bfloat16_rn(y1);
            const __nv_bfloat16 h2 = __float2bfloat16_rn(y2);
            const size_t o = (size_t)grow * QCOLS + head * HDIM + i;
            Qh[o]      = h1;
            Qh[o + 64] = h2;
            Ql[o]      = __float2bfloat16_rn(y1 - __bfloat162float(h1));
            Ql[o + 64] = __float2bfloat16_rn(y2 - __bfloat162float(h2));
        }
    } else if (n0 < QCOLS + KCOLS) {
        const int head = (n0 - QCOLS) >> 7;
        for (int it = 0; it < 32; it++) {
            const int idx = tid + it * 256;
            const int r = idx >> 6, i = idx & 63;
            const int grow = m0 + r;
            const int pos = grow & (SEQ - 1);
            const float x1 = ft[r * 132 + i];
            const float x2 = ft[r * 132 + i + 64];
            const float c = g_cos[pos * 64 + i];
            const float s = g_sin[pos * 64 + i];
            const float y1 = x1 * c - x2 * s;
            const float y2 = x2 * c + x1 * s;
            const __nv_bfloat16 h1 = __float2bfloat16_rn(y1);
            const __nv_bfloat16 h2 = __float2bfloat16_rn(y2);
            const size_t o = (size_t)grow * KCOLS + head * HDIM + i;
            Kh[o]      = h1;
            Kh[o + 64] = h2;
            Kl[o]      = __float2bfloat16_rn(y1 - __bfloat162float(h1));
            Kl[o + 64] = __float2bfloat16_rn(y2 - __bfloat162float(h2));
        }
    } else {
        const int cbase = n0 - (QCOLS + KCOLS);
        for (int it = 0; it < 64; it++) {
            const int idx = tid + it * 256;
            const int r = idx >> 7, c = idx & 127;
            const int grow = m0 + r;
            const float x = ft[r * 132 + c];
            const __nv_bfloat16 h = __float2bfloat16_rn(x);
            const size_t o = (size_t)grow * KCOLS + cbase + c;
            Vh[o] = h;
            Vl[o] = __float2bfloat16_rn(x - __bfloat162float(h));
        }
    }
}

// ---------------------------------------------------------------------------
// Flash attention on tensor cores (hi/lo 3-product), qt processed descending.
// MMAs interleaved across s0/s1 (and o0/o1) so dependent issues are 2 apart.
// ---------------------------------------------------------------------------
#define FQT 128
#define FKT 64
#define FQ_B    32768
#define FTILE_B 16384
#define FKV_B   (4*FTILE_B)
#define FLASH_SMEM (2*FQ_B + 2*FKV_B)   // 192KB

__global__ __launch_bounds__(256, 1)
void flash_mma(const __nv_bfloat16* __restrict__ Qh_g, const __nv_bfloat16* __restrict__ Ql_g,
               const __nv_bfloat16* __restrict__ Kh_g, const __nv_bfloat16* __restrict__ Kl_g,
               const __nv_bfloat16* __restrict__ Vh_g, const __nv_bfloat16* __restrict__ Vl_g,
               __nv_bfloat16* __restrict__ Ch_g, __nv_bfloat16* __restrict__ Cl_g)
{
    extern __shared__ char dsm[];
    const uint32_t sb = smem_u32(dsm);
    const uint32_t Qh_s = sb, Ql_s = sb + FQ_B;
    const uint32_t KV_s = sb + 2 * FQ_B;

    const int tid = threadIdx.x;
    const int w = tid >> 5, lane = tid & 31;
    const int qt = gridDim.x - 1 - blockIdx.x;    // heavy tiles first
    const int h = blockIdx.y, b = blockIdx.z;
    const int kvh = h >> 2;
    const int qrow0 = b * SEQ + qt * FQT;
    const int nkt = 2 * qt + 2;

    {
        const int c = tid & 15, r0 = tid >> 4;
        #pragma unroll
        for (int i = 0; i < 8; i++) {
            const int r = r0 + i * 16;
            const size_t go = (size_t)(qrow0 + r) * QCOLS + h * HDIM + c * 8;
            cp_async16(Qh_s + SW(r, c), Qh_g + go);
            cp_async16(Ql_s + SW(r, c), Ql_g + go);
        }
    }

    auto load_kv = [&](int kt, int st) {
        const int c = tid & 15, r0 = tid >> 4;
        const uint32_t base = KV_s + st * FKV_B;
        const int krow0 = b * SEQ + kt * FKT;
        #pragma unroll
        for (int i = 0; i < 4; i++) {
            const int r = r0 + i * 16;
            const size_t go = (size_t)(krow0 + r) * KCOLS + kvh * HDIM + c * 8;
            cp_async16(base +             SW(r, c), Kh_g + go);
            cp_async16(base +   FTILE_B + SW(r, c), Kl_g + go);
            cp_async16(base + 2*FTILE_B + SW(r, c), Vh_g + go);
            cp_async16(base + 3*FTILE_B + SW(r, c), Vl_g + go);
        }
        asm volatile("cp.async.commit_group;\n" ::: "memory");
    };

    load_kv(0, 0);
    asm volatile("cp.async.commit_group;\n" ::: "memory");

    const int er = lane >> 2, ec = lane & 3;
    const int a_row = w * 16 + (lane & 15);
    const int a_kh  = lane >> 4;
    const int b_n   = (lane & 7) + ((lane >> 4) & 1) * 8;
    const int b_kh  = (lane >> 3) & 1;
    const int v_key = (lane & 7) + ((lane >> 3) & 1) * 8;
    const int v_dc  = lane >> 4;

    const int rg0 = qt * FQT + w * 16 + er;
    const int rg1 = rg0 + 8;

    float o[16][4];
    #pragma unroll
    for (int j = 0; j < 16; j++)
        #pragma unroll
        for (int q = 0; q < 4; q++) o[j][q] = 0.0f;
    float m0 = -1e30f, m1 = -1e30f, l0 = 0.0f, l1 = 0.0f;

    for (int kt = 0; kt < nkt; kt++) {
        const int st = kt & 1;
        if (kt + 1 < nkt) {
            load_kv(kt + 1, (kt + 1) & 1);
            asm volatile("cp.async.wait_group 1;\n" ::: "memory");
        } else {
            asm volatile("cp.async.wait_group 0;\n" ::: "memory");
        }
        __syncthreads();

        const uint32_t Kh_s = KV_s + st * FKV_B;
        const uint32_t Kl_s = Kh_s + FTILE_B;
        const uint32_t Vh_s = Kh_s + 2 * FTILE_B;
        const uint32_t Vl_s = Kh_s + 3 * FTILE_B;

        float s[8][4];
        #pragma unroll
        for (int f = 0; f < 8; f++)
            #pragma unroll
            for (int q = 0; q < 4; q++) s[f][q] = 0.0f;

        #pragma unroll
        for (int ks = 0; ks < 8; ks++) {
            uint32_t qah[4], qal[4];
            ldsm_x4(qah[0], qah[1], qah[2], qah[3], Qh_s + SW(a_row, ks*2 + a_kh));
            ldsm_x4(qal[0], qal[1], qal[2], qal[3], Ql_s + SW(a_row, ks*2 + a_kh));
            #pragma unroll
            for (int ng = 0; ng < 4; ng++) {
                uint32_t kh0, kh1, kh2, kh3, kl0, kl1, kl2, kl3;
                ldsm_x4(kh0, kh1, kh2, kh3, Kh_s + SW(ng*16 + b_n, ks*2 + b_kh));
                ldsm_x4(kl0, kl1, kl2, kl3, Kl_s + SW(ng*16 + b_n, ks*2 + b_kh));
                float* s0 = s[ng*2];
                float* s1 = s[ng*2 + 1];
                // interleaved: dependent reuse 2 issues apart
                mma16816(s0[0], s0[1], s0[2], s0[3], qah[0], qah[1], qah[2], qah[3], kh0, kh1);
                mma16816(s1[0], s1[1], s1[2], s1[3], qah[0], qah[1], qah[2], qah[3], kh2, kh3);
                mma16816(s0[0], s0[1], s0[2], s0[3], qah[0], qah[1], qah[2], qah[3], kl0, kl1);
                mma16816(s1[0], s1[1], s1[2], s1[3], qah[0], qah[1], qah[2], qah[3], kl2, kl3);
                mma16816(s0[0], s0[1], s0[2], s0[3], qal[0], qal[1], qal[2], qal[3], kh0, kh1);
                mma16816(s1[0], s1[1], s1[2], s1[3], qal[0], qal[1], qal[2], qal[3], kh2, kh3);
            }
        }

        if (kt >= 2 * qt) {
            #pragma unroll
            for (int f = 0; f < 8; f++) {
                const int key0 = kt * FKT + f * 8 + ec * 2;
                if (key0     > rg0) s[f][0] = -1e30f;
                if (key0 + 1 > rg0) s[f][1] = -1e30f;
                if (key0     > rg1) s[f][2] = -1e30f;
                if (key0 + 1 > rg1) s[f][3] = -1e30f;
            }
        }

        float nm0 = -1e30f, nm1 = -1e30f;
        #pragma unroll
        for (int f = 0; f < 8; f++) {
            nm0 = fmaxf(nm0, fmaxf(s[f][0], s[f][1]));
            nm1 = fmaxf(nm1, fmaxf(s[f][2], s[f][3]));
        }
        nm0 = fmaxf(nm0, __shfl_xor_sync(0xffffffffu, nm0, 1));
        nm0 = fmaxf(nm0, __shfl_xor_sync(0xffffffffu, nm0, 2));
        nm1 = fmaxf(nm1, __shfl_xor_sync(0xffffffffu, nm1, 1));
        nm1 = fmaxf(nm1, __shfl_xor_sync(0xffffffffu, nm1, 2));
        nm0 = fmaxf(nm0, m0);
        nm1 = fmaxf(nm1, m1);
        const float corr0 = __expf(m0 - nm0);
        const float corr1 = __expf(m1 - nm1);
        m0 = nm0;
        m1 = nm1;

        float rs0 = 0.0f, rs1 = 0.0f;
        #pragma unroll
        for (int f = 0; f < 8; f++) {
            s[f][0] = __expf(s[f][0] - nm0);
            s[f][1] = __expf(s[f][1] - nm0);
            s[f][2] = __expf(s[f][2] - nm1);
            s[f][3] = __expf(s[f][3] - nm1);
            rs0 += s[f][0] + s[f][1];
            rs1 += s[f][2] + s[f][3];
        }
        rs0 += __shfl_xor_sync(0xffffffffu, rs0, 1);
        rs0 += __shfl_xor_sync(0xffffffffu, rs0, 2);
        rs1 += __shfl_xor_sync(0xffffffffu, rs1, 1);
        rs1 += __shfl_xor_sync(0xffffffffu, rs1, 2);
        l0 = l0 * corr0 + rs0;
        l1 = l1 * corr1 + rs1;
        #pragma unroll
        for (int j = 0; j < 16; j++) {
            o[j][0] *= corr0; o[j][1] *= corr0;
            o[j][2] *= corr1; o[j][3] *= corr1;
        }

        #pragma unroll
        for (int kp = 0; kp < 4; kp++) {
            const float* f0 = s[2*kp];
            const float* f1 = s[2*kp + 1];
            uint32_t pah[4], pal[4];
            float r0a, r0b, r1a, r1b, r2a, r2b, r3a, r3b;
            __nv_bfloat162 h2v;
            h2v = __floats2bfloat162_rn(f0[0], f0[1]);
            r0a = f0[0] - __low2float(h2v); r0b = f0[1] - __high2float(h2v);
            pah[0] = *reinterpret_cast<uint32_t*>(&h2v);
            h2v = __floats2bfloat162_rn(f0[2], f0[3]);
            r1a = f0[2] - __low2float(h2v); r1b = f0[3] - __high2float(h2v);
            pah[1] = *reinterpret_cast<uint32_t*>(&h2v);
            h2v = __floats2bfloat162_rn(f1[0], f1[1]);
            r2a = f1[0] - __low2float(h2v); r2b = f1[1] - __high2float(h2v);
            pah[2] = *reinterpret_cast<uint32_t*>(&h2v);
            h2v = __floats2bfloat162_rn(f1[2], f1[3]);
            r3a = f1[2] - __low2float(h2v); r3b = f1[3] - __high2float(h2v);
            pah[3] = *reinterpret_cast<uint32_t*>(&h2v);
            h2v = __floats2bfloat162_rn(r0a, r0b); pal[0] = *reinterpret_cast<uint32_t*>(&h2v);
            h2v = __floats2bfloat162_rn(r1a, r1b); pal[1] = *reinterpret_cast<uint32_t*>(&h2v);
            h2v = __floats2bfloat162_rn(r2a, r2b); pal[2] = *reinterpret_cast<uint32_t*>(&h2v);
            h2v = __floats2bfloat162_rn(r3a, r3b); pal[3] = *reinterpret_cast<uint32_t*>(&h2v);

            #pragma unroll
            for (int nd = 0; nd < 8; nd++) {
                uint32_t vh0, vh1, vh2, vh3, vl0, vl1, vl2, vl3;
                ldsm_x4t(vh0, vh1, vh2, vh3, Vh_s + SW(kp*16 + v_key, nd*2 + v_dc));
                ldsm_x4t(vl0, vl1, vl2, vl3, Vl_s + SW(kp*16 + v_key, nd*2 + v_dc));
                float* o0 = o[nd*2];
                float* o1 = o[nd*2 + 1];
                // interleaved: dependent reuse 2 issues apart
                mma16816(o0[0], o0[1], o0[2], o0[3], pah[0], pah[1], pah[2], pah[3], vh0, vh1);
                mma16816(o1[0], o1[1], o1[2], o1[3], pah[0], pah[1], pah[2], pah[3], vh2, vh3);
                mma16816(o0[0], o0[1], o0[2], o0[3], pah[0], pah[1], pah[2], pah[3], vl0, vl1);
                mma16816(o1[0], o1[1], o1[2], o1[3], pah[0], pah[1], pah[2], pah[3], vl2, vl3);
                mma16816(o0[0], o0[1], o0[2], o0[3], pal[0], pal[1], pal[2], pal[3], vh0, vh1);
                mma16816(o1[0], o1[1], o1[2], o1[3], pal[0], pal[1], pal[2], pal[3], vh2, vh3);
            }
        }
        __syncthreads();
    }

    const float inv0 = 1.0f / l0;
    const float inv1 = 1.0f / l1;
    const size_t row0 = (size_t)(qrow0 + w * 16 + er);
    const size_t row1 = row0 + 8;
    #pragma unroll
    for (int j = 0; j < 16; j++) {
        const int col = h * HDIM + j * 8 + ec * 2;
        float x0 = o[j][0] * inv0, x1 = o[j][1] * inv0;
        float x2 = o[j][2] * inv1, x3 = o[j][3] * inv1;
        __nv_bfloat162 h01 = __floats2bfloat162_rn(x0, x1);
        __nv_bfloat162 h23 = __floats2bfloat162_rn(x2, x3);
        __nv_bfloat162 l01 = __floats2bfloat162_rn(x0 - __low2float(h01), x1 - __high2float(h01));
        __nv_bfloat162 l23 = __floats2bfloat162_rn(x2 - __low2float(h23), x3 - __high2float(h23));
        *reinterpret_cast<__nv_bfloat162*>(Ch_g + row0 * QCOLS + col) = h01;
        *reinterpret_cast<__nv_bfloat162*>(Cl_g + row0 * QCOLS + col) = l01;
        *reinterpret_cast<__nv_bfloat162*>(Ch_g + row1 * QCOLS + col) = h23;
        *reinterpret_cast<__nv_bfloat162*>(Cl_g + row1 * QCOLS + col) = l23;
    }
}

// ---------------------------------------------------------------------------
extern "C" void kernel_launch(void* const* d_in, const int* in_sizes, int n_in,
                              void* d_out, int out_size)
{
    const float* hidden = (const float*)d_in[0];
    const float* Wq = (const float*)d_in[1];
    const float* Wk = (const float*)d_in[2];
    const float* Wv = (const float*)d_in[3];
    const float* Wo = (const float*)d_in[4];
    float* out = (float*)d_out;

    __nv_bfloat16 *ah, *al, *ch, *cl, *qh, *ql, *kh, *kl, *vh, *vl;
    __nv_bfloat16 *wh, *wl, *woh, *wol;
    cudaGetSymbolAddress((void**)&ah, g_ah);  cudaGetSymbolAddress((void**)&al, g_al);
    cudaGetSymbolAddress((void**)&ch, g_ch);  cudaGetSymbolAddress((void**)&cl, g_cl);
    cudaGetSymbolAddress((void**)&qh, g_qh);  cudaGetSymbolAddress((void**)&ql, g_ql);
    cudaGetSymbolAddress((void**)&kh, g_kh);  cudaGetSymbolAddress((void**)&kl, g_kl);
    cudaGetSymbolAddress((void**)&vh, g_vh);  cudaGetSymbolAddress((void**)&vl, g_vl);
    cudaGetSymbolAddress((void**)&wh, g_wh);  cudaGetSymbolAddress((void**)&wl, g_wl);
    cudaGetSymbolAddress((void**)&woh, g_woh); cudaGetSymbolAddress((void**)&wol, g_wol);

    cudaFuncSetAttribute(gemm_mma,
                         cudaFuncAttributeMaxDynamicSharedMemorySize, GEMM_SMEM);
    cudaFuncSetAttribute(gemm_qkv_fused,
                         cudaFuncAttributeMaxDynamicSharedMemorySize, GEMM_SMEM);
    cudaFuncSetAttribute(flash_mma,
                         cudaFuncAttributeMaxDynamicSharedMemorySize, FLASH_SMEM);

    // 1) RoPE table, 2) hidden split, 3) all weight transposes (one launch)
    rope_table_kernel<<<(SEQ*64 + 255)/256, 256>>>();
    split_kernel<<<(ROWS*HID/4 + 255)/256, 256>>>(hidden, ah, al, ROWS*HID/4);
    tsplit_all_kernel<<<10240, dim3(32,8)>>>(Wq, Wk, Wv, Wo, wh, wl, woh, wol);

    // 4) Merged QKV projection with fused RoPE/scale/split epilogue
    gemm_qkv_fused<<<dim3(QKVC/128, ROWS/128), 256, GEMM_SMEM>>>(
        ah, al, wh, wl, qh, ql, kh, kl, vh, vl);

    // 5) Attention (tensor cores), writes ctx hi/lo directly
    flash_mma<<<dim3(SEQ/FQT, NHQ, BATCH), 256, FLASH_SMEM>>>(qh, ql, kh, kl, vh, vl, ch, cl);

    // 6) Output projection
    gemm_mma<<<dim3(HID/128, ROWS/128), 256, GEMM_SMEM>>>(ch, cl, woh, wol, out, HID);
}

// round 10
// speedup vs baseline: 4.4405x; 1.3913x over previous
#include <cuda_runtime.h>
#include <cuda_fp16.h>
#include <math.h>
#include <stdint.h>

// Problem constants
#define BATCH 2
#define SEQ   2048
#define HID   2048
#define NHQ   16
#define NKV   4
#define HDIM  128
#define ROWS  (BATCH*SEQ)          // 4096
#define QCOLS (NHQ*HDIM)           // 2048
#define KCOLS (NKV*HDIM)           // 512
#define QKVC  (QCOLS + 2*KCOLS)    // 3072

// ---------------------------------------------------------------------------
// Device scratch (static — no allocation allowed)
// A-side operands are fp16 hi-only; B-side operands are fp16 hi+lo.
// ---------------------------------------------------------------------------
__device__ float g_cos[SEQ*64];
__device__ float g_sin[SEQ*64];

__device__ __half g_ah[ROWS*HID];                       // hidden (hi only)
__device__ __half g_ch[ROWS*QCOLS];                     // ctx (hi only)
__device__ __half g_qh[ROWS*QCOLS];                     // q (hi only, rope+scale)
__device__ __half g_kh[ROWS*KCOLS], g_kl[ROWS*KCOLS];   // k hi/lo (rope)
__device__ __half g_vh[ROWS*KCOLS], g_vl[ROWS*KCOLS];   // v hi/lo
__device__ __half g_wh[QKVC*HID],   g_wl[QKVC*HID];     // [Wq;Wk;Wv]^T hi/lo
__device__ __half g_woh[HID*QCOLS], g_wol[HID*QCOLS];   // Wo^T hi/lo

// ---------------------------------------------------------------------------
// Helpers
// ---------------------------------------------------------------------------
__device__ __forceinline__ uint32_t smem_u32(const void* p) {
    uint32_t a;
    asm("{ .reg .u64 t; cvta.to.shared.u64 t, %1; cvt.u32.u64 %0, t; }" : "=r"(a) : "l"(p));
    return a;
}
__device__ __forceinline__ void cp_async16(uint32_t dst, const void* src) {
    asm volatile("cp.async.cg.shared.global [%0], [%1], 16;\n" :: "r"(dst), "l"(src) : "memory");
}
__device__ __forceinline__ void ldsm_x4(uint32_t& r0, uint32_t& r1, uint32_t& r2, uint32_t& r3,
                                        uint32_t addr) {
    asm volatile("ldmatrix.sync.aligned.m8n8.x4.shared.b16 {%0,%1,%2,%3}, [%4];"
                 : "=r"(r0), "=r"(r1), "=r"(r2), "=r"(r3) : "r"(addr));
}
__device__ __forceinline__ void ldsm_x4t(uint32_t& r0, uint32_t& r1, uint32_t& r2, uint32_t& r3,
                                         uint32_t addr) {
    asm volatile("ldmatrix.sync.aligned.m8n8.x4.trans.shared.b16 {%0,%1,%2,%3}, [%4];"
                 : "=r"(r0), "=r"(r1), "=r"(r2), "=r"(r3) : "r"(addr));
}
__device__ __forceinline__ void mma16816(float& c0, float& c1, float& c2, float& c3,
                                         uint32_t a0, uint32_t a1, uint32_t a2, uint32_t a3,
                                         uint32_t b0, uint32_t b1) {
    asm volatile(
        "mma.sync.aligned.m16n8k16.row.col.f32.f16.f16.f32 "
        "{%0,%1,%2,%3}, {%4,%5,%6,%7}, {%8,%9}, {%0,%1,%2,%3};"
        : "+f"(c0), "+f"(c1), "+f"(c2), "+f"(c3)
        : "r"(a0), "r"(a1), "r"(a2), "r"(a3), "r"(b0), "r"(b1));
}
// swizzled smem offset for flash: row r (256B rows of fp16[128]), 16B chunk c
#define SW(r, c) ((uint32_t)((r) * 256 + (((c) ^ ((r) & 7)) << 4)))

// ---------------------------------------------------------------------------
// fp32 -> fp16 hi (row-major, same layout)
// ---------------------------------------------------------------------------
__global__ void split_hi_kernel(const float* __restrict__ in,
                                __half* __restrict__ hi, int n4)
{
    int i = blockIdx.x * blockDim.x + threadIdx.x;
    if (i >= n4) return;
    float4 v = reinterpret_cast<const float4*>(in)[i];
    __half2* hp = reinterpret_cast<__half2*>(hi);
    hp[2*i]   = __floats2half2_rn(v.x, v.y);
    hp[2*i+1] = __floats2half2_rn(v.z, v.w);
}

// All four weight transposes+splits (fp16 hi/lo) in ONE launch.
__global__ void tsplit_all_kernel(const float* __restrict__ Wq, const float* __restrict__ Wk,
                                  const float* __restrict__ Wv, const float* __restrict__ Wo,
                                  __half* __restrict__ wh, __half* __restrict__ wl,
                                  __half* __restrict__ woh, __half* __restrict__ wol)
{
    __shared__ float t[32][33];
    const int bid = blockIdx.x;
    const float* src;
    __half *dh, *dl;
    int Nin, nbx, tile;
    if (bid < 4096)      { src = Wq; dh = wh; dl = wl; Nin = 2048; nbx = 64; tile = bid; }
    else if (bid < 5120) { src = Wk; dh = wh + (size_t)QCOLS*HID; dl = wl + (size_t)QCOLS*HID;
                           Nin = 512; nbx = 16; tile = bid - 4096; }
    else if (bid < 6144) { src = Wv; dh = wh + (size_t)(QCOLS+KCOLS)*HID; dl = wl + (size_t)(QCOLS+KCOLS)*HID;
                           Nin = 512; nbx = 16; tile = bid - 5120; }
    else                 { src = Wo; dh = woh; dl = wol; Nin = 2048; nbx = 64; tile = bid - 6144; }

    const int tx = threadIdx.x, ty = threadIdx.y;
    const int n0 = (tile % nbx) * 32, k0 = (tile / nbx) * 32;
    #pragma unroll
    for (int j = 0; j < 32; j += 8)
        t[ty + j][tx] = src[(size_t)(k0 + ty + j) * Nin + n0 + tx];
    __syncthreads();
    #pragma unroll
    for (int j = 0; j < 32; j += 8) {
        float x = t[tx][ty + j];
        __half h = __float2half_rn(x);
        __half l = __float2half_rn(x - __half2float(h));
        size_t o = (size_t)(n0 + ty + j) * 2048 + k0 + tx;
        dh[o] = h;
        dl[o] = l;
    }
}

// ---------------------------------------------------------------------------
// RoPE table
// ---------------------------------------------------------------------------
__global__ void rope_table_kernel()
{
    int idx = blockIdx.x * blockDim.x + threadIdx.x;
    if (idx >= SEQ * 64) return;
    int pos = idx >> 6, i = idx & 63;
    double inv = exp2(-(double)i * (13.287712379549449 / 64.0));
    double ang = (double)pos * inv;
    const double twopi = 6.283185307179586476925286766559;
    ang -= floor(ang * (1.0 / twopi)) * twopi;
    if (ang > 3.14159265358979323846) ang -= twopi;
    float s, c;
    sincosf((float)ang, &s, &c);
    g_cos[idx] = c;
    g_sin[idx] = s;
}

// ---------------------------------------------------------------------------
// GEMM mainloop: 128x128 CTA tile, fp16 2-product (Ah*Bh + Ah*Bl),
// 3-stage cp.async, one sync per K-chunk, 2 CTAs/SM.
// Stage layout: [Ah 8KB][Bh 8KB][Bl 8KB] = 24KB.
// ---------------------------------------------------------------------------
#define KCH       32
#define NCHUNKS   64
#define TILE_B    8192
#define STAGE_B   (3*TILE_B)      // 24 KB
#define NSTG      3
#define GEMM_SMEM (NSTG*STAGE_B)  // 72 KB

struct GemmCtx {
    uint32_t sbase;
    const __half* gsrc;   // null => this thread group loads nothing
    int row0, lch, lr0;
    uint32_t smoff;
    int m0w, n0w;
    int a_row, a_kh, b_row, b_kh;
};

__device__ __forceinline__ void gemm_mainloop(
    const GemmCtx& cx, float acc[4][4][4])
{
    auto load_chunk = [&](int ci, int st) {
        if (cx.gsrc) {
            const uint32_t tb = cx.sbase + st * STAGE_B + cx.smoff;
            #pragma unroll
            for (int i = 0; i < 8; i++) {
                const int r = cx.lr0 + i * 16;
                const uint32_t dst = tb + r * 64 + ((uint32_t)(cx.lch ^ ((r >> 1) & 3)) << 4);
                cp_async16(dst, cx.gsrc + (size_t)(cx.row0 + r) * 2048 + ci * KCH + cx.lch * 8);
            }
        }
        asm volatile("cp.async.commit_group;\n" ::: "memory");
    };

    load_chunk(0, 0);
    load_chunk(1, 1);

    for (int ci = 0; ci < NCHUNKS; ci++) {
        if (ci + 1 < NCHUNKS) asm volatile("cp.async.wait_group 1;\n" ::: "memory");
        else                  asm volatile("cp.async.wait_group 0;\n" ::: "memory");
        __syncthreads();
        if (ci + 2 < NCHUNKS) load_chunk(ci + 2, (ci + 2) % NSTG);

        const int st = ci % NSTG;
        const uint32_t ah_b = cx.sbase + st * STAGE_B;
        const uint32_t bh_b = ah_b + TILE_B;
        const uint32_t bl_b = ah_b + 2 * TILE_B;

        #pragma unroll
        for (int ks = 0; ks < 2; ks++) {
            uint32_t a4[4][4];
            #pragma unroll
            for (int mi = 0; mi < 4; mi++) {
                const int r = cx.m0w + mi * 16 + cx.a_row;
                const int c = ks * 2 + cx.a_kh;
                const uint32_t off = r * 64 + ((uint32_t)(c ^ ((r >> 1) & 3)) << 4);
                ldsm_x4(a4[mi][0], a4[mi][1], a4[mi][2], a4[mi][3], ah_b + off);
            }
            uint32_t bh[4][2], bl[4][2];
            #pragma unroll
            for (int jb = 0; jb < 2; jb++) {
                const int r = cx.n0w + jb * 16 + cx.b_row;
                const int c = ks * 2 + cx.b_kh;
                const uint32_t off = r * 64 + ((uint32_t)(c ^ ((r >> 1) & 3)) << 4);
                ldsm_x4(bh[2*jb][0], bh[2*jb][1], bh[2*jb+1][0], bh[2*jb+1][1], bh_b + off);
                ldsm_x4(bl[2*jb][0], bl[2*jb][1], bl[2*jb+1][0], bl[2*jb+1][1], bl_b + off);
            }
            // Pass 1: Ah*Bh (16 independent accumulators)
            #pragma unroll
            for (int mi = 0; mi < 4; mi++)
                #pragma unroll
                for (int nj = 0; nj < 4; nj++) {
                    float* cc = acc[mi][nj];
                    mma16816(cc[0], cc[1], cc[2], cc[3],
                             a4[mi][0], a4[mi][1], a4[mi][2], a4[mi][3],
                             bh[nj][0], bh[nj][1]);
                }
            // Pass 2: Ah*Bl
            #pragma unroll
            for (int mi = 0; mi < 4; mi++)
                #pragma unroll
                for (int nj = 0; nj < 4; nj++) {
                    float* cc = acc[mi][nj];
                    mma16816(cc[0], cc[1], cc[2], cc[3],
                             a4[mi][0], a4[mi][1], a4[mi][2], a4[mi][3],
                             bl[nj][0], bl[nj][1]);
                }
        }
    }
}

__device__ __forceinline__ void gemm_init_ctx(
    GemmCtx& cx, uint32_t sbase, int tid, int m0, int n0,
    const __half* Ah, const __half* Bh, const __half* Bl)
{
    cx.sbase = sbase;
    const int tt = tid >> 6;
    const int t6 = tid & 63;
    cx.lch = t6 & 3;
    cx.lr0 = t6 >> 2;
    switch (tt) {
        case 0:  cx.gsrc = Ah; cx.row0 = m0; cx.smoff = 0;          break;
        case 1:  cx.gsrc = Bh; cx.row0 = n0; cx.smoff = TILE_B;     break;
        case 2:  cx.gsrc = Bl; cx.row0 = n0; cx.smoff = 2*TILE_B;   break;
        default: cx.gsrc = nullptr; cx.row0 = 0; cx.smoff = 0;      break;
    }
    const int wid = tid >> 5, lane = tid & 31;
    cx.m0w = (wid & 1) * 64;
    cx.n0w = (wid >> 1) * 32;
    cx.a_row = lane & 15;
    cx.a_kh  = lane >> 4;
    cx.b_row = (lane & 7) + ((lane >> 4) & 1) * 8;
    cx.b_kh  = (lane >> 3) & 1;
}

// ---------------------------------------------------------------------------
// Plain GEMM (fp32 C output) — output projection.
// ---------------------------------------------------------------------------
__global__ __launch_bounds__(256, 2)
void gemm_mma(const __half* __restrict__ Ah,
              const __half* __restrict__ Bh, const __half* __restrict__ Bl,
              float* __restrict__ C, int ldc)
{
    extern __shared__ char dsm[];
    const int tid = threadIdx.x;
    const int lane = tid & 31;
    const int m0 = blockIdx.y * 128;
    const int n0 = blockIdx.x * 128;

    GemmCtx cx;
    gemm_init_ctx(cx, smem_u32(dsm), tid, m0, n0, Ah, Bh, Bl);

    float acc[4][4][4];
    #pragma unroll
    for (int i = 0; i < 4; i++)
        #pragma unroll
        for (int j = 0; j < 4; j++)
            #pragma unroll
            for (int q = 0; q < 4; q++) acc[i][j][q] = 0.0f;

    gemm_mainloop(cx, acc);

    const int er = lane >> 2;
    const int ec = (lane & 3) * 2;
    #pragma unroll
    for (int mi = 0; mi < 4; mi++) {
        const int row_a = m0 + cx.m0w + mi * 16 + er;
        #pragma unroll
        for (int nj = 0; nj < 4; nj++) {
            const int col = n0 + cx.n0w + nj * 8 + ec;
            float* cc = acc[mi][nj];
            *reinterpret_cast<float2*>(C + (size_t)row_a * ldc + col) =
                make_float2(cc[0], cc[1]);
            *reinterpret_cast<float2*>(C + (size_t)(row_a + 8) * ldc + col) =
                make_float2(cc[2], cc[3]);
        }
    }
}

// ---------------------------------------------------------------------------
// QKV GEMM with fused RoPE + scale + fp16 split epilogue.
// Q: hi only (+scale).  K: hi/lo.  V: hi/lo.
// ---------------------------------------------------------------------------
__global__ __launch_bounds__(256, 2)
void gemm_qkv_fused(const __half* __restrict__ Ah,
                    const __half* __restrict__ Bh, const __half* __restrict__ Bl,
                    __half* __restrict__ Qh,
                    __half* __restrict__ Kh, __half* __restrict__ Kl,
                    __half* __restrict__ Vh, __half* __restrict__ Vl)
{
    extern __shared__ char dsm[];
    const int tid = threadIdx.x;
    const int lane = tid & 31;
    const int m0 = blockIdx.y * 128;
    const int n0 = blockIdx.x * 128;

    GemmCtx cx;
    gemm_init_ctx(cx, smem_u32(dsm), tid, m0, n0, Ah, Bh, Bl);

    float acc[4][4][4];
    #pragma unroll
    for (int i = 0; i < 4; i++)
        #pragma unroll
        for (int j = 0; j < 4; j++)
            #pragma unroll
            for (int q = 0; q < 4; q++) acc[i][j][q] = 0.0f;

    gemm_mainloop(cx, acc);

    // ---- stage fp32 tile to smem [128][132] (67.6KB <= 72KB) ----
    __syncthreads();
    float* ft = reinterpret_cast<float*>(dsm);
    const int er = lane >> 2;
    const int ec = (lane & 3) * 2;
    #pragma unroll
    for (int mi = 0; mi < 4; mi++) {
        const int r = cx.m0w + mi * 16 + er;
        #pragma unroll
        for (int nj = 0; nj < 4; nj++) {
            const int c = cx.n0w + nj * 8 + ec;
            float* cc = acc[mi][nj];
            *reinterpret_cast<float2*>(ft + r * 132 + c)       = make_float2(cc[0], cc[1]);
            *reinterpret_cast<float2*>(ft + (r + 8) * 132 + c) = make_float2(cc[2], cc[3]);
        }
    }
    __syncthreads();

    // ---- fused epilogue by region ----
    if (n0 < QCOLS) {
        // Q head: rope + scale, hi only
        const int head = n0 >> 7;
        const float scale = 0.08838834764831845f;
        for (int it = 0; it < 32; it++) {
            const int idx = tid + it * 256;
            const int r = idx >> 6, i = idx & 63;
            const int grow = m0 + r;
            const int pos = grow & (SEQ - 1);
            const float x1 = ft[r * 132 + i];
            const float x2 = ft[r * 132 + i + 64];
            const float c = g_cos[pos * 64 + i];
            const float s = g_sin[pos * 64 + i];
            const float y1 = (x1 * c - x2 * s) * scale;
            const float y2 = (x2 * c + x1 * s) * scale;
            const size_t o = (size_t)grow * QCOLS + head * HDIM + i;
            Qh[o]      = __float2half_rn(y1);
            Qh[o + 64] = __float2half_rn(y2);
        }
    } else if (n0 < QCOLS + KCOLS) {
        // K head: rope, hi/lo
        const int head = (n0 - QCOLS) >> 7;
        for (int it = 0; it < 32; it++) {
            const int idx = tid + it * 256;
            const int r = idx >> 6, i = idx & 63;
            const int grow = m0 + r;
            const int pos = grow & (SEQ - 1);
            const float x1 = ft[r * 132 + i];
            const float x2 = ft[r * 132 + i + 64];
            const float c = g_cos[pos * 64 + i];
            const float s = g_sin[pos * 64 + i];
            const float y1 = x1 * c - x2 * s;
            const float y2 = x2 * c + x1 * s;
            const __half h1 = __float2half_rn(y1);
            const __half h2 = __float2half_rn(y2);
            const size_t o = (size_t)grow * KCOLS + head * HDIM + i;
            Kh[o]      = h1;
            Kh[o + 64] = h2;
            Kl[o]      = __float2half_rn(y1 - __half2float(h1));
            Kl[o + 64] = __float2half_rn(y2 - __half2float(h2));
        }
    } else {
        // V head: plain hi/lo
        const int cbase = n0 - (QCOLS + KCOLS);
        for (int it = 0; it < 64; it++) {
            const int idx = tid + it * 256;
            const int r = idx >> 7, c = idx & 127;
            const int grow = m0 + r;
            const float x = ft[r * 132 + c];
            const __half h = __float2half_rn(x);
            const size_t o = (size_t)grow * KCOLS + cbase + c;
            Vh[o] = h;
            Vl[o] = __float2half_rn(x - __half2float(h));
        }
    }
}

// ---------------------------------------------------------------------------
// Flash attention, fp16 2-product (Qh*Kh + Qh*Kl; Ph*Vh + Ph*Vl).
// qt processed descending (heavy tiles first). Writes ctx hi only.
// ---------------------------------------------------------------------------
#define FQT 128
#define FKT 64
#define FQ_B    32768
#define FTILE_B 16384
#define FKV_B   (4*FTILE_B)                 // Kh,Kl,Vh,Vl per stage
#define FLASH_SMEM (FQ_B + 2*FKV_B)         // 160KB

__global__ __launch_bounds__(256, 1)
void flash_mma(const __half* __restrict__ Qh_g,
               const __half* __restrict__ Kh_g, const __half* __restrict__ Kl_g,
               const __half* __restrict__ Vh_g, const __half* __restrict__ Vl_g,
               __half* __restrict__ Ch_g)
{
    extern __shared__ char dsm[];
    const uint32_t sb = smem_u32(dsm);
    const uint32_t Qh_s = sb;
    const uint32_t KV_s = sb + FQ_B;

    const int tid = threadIdx.x;
    const int w = tid >> 5, lane = tid & 31;
    const int qt = gridDim.x - 1 - blockIdx.x;
    const int h = blockIdx.y, b = blockIdx.z;
    const int kvh = h >> 2;
    const int qrow0 = b * SEQ + qt * FQT;
    const int nkt = 2 * qt + 2;

    {
        const int c = tid & 15, r0 = tid >> 4;
        #pragma unroll
        for (int i = 0; i < 8; i++) {
            const int r = r0 + i * 16;
            const size_t go = (size_t)(qrow0 + r) * QCOLS + h * HDIM + c * 8;
            cp_async16(Qh_s + SW(r, c), Qh_g + go);
        }
    }

    auto load_kv = [&](int kt, int st) {
        const int c = tid & 15, r0 = tid >> 4;
        const uint32_t base = KV_s + st * FKV_B;
        const int krow0 = b * SEQ + kt * FKT;
        #pragma unroll
        for (int i = 0; i < 4; i++) {
            const int r = r0 + i * 16;
            const size_t go = (size_t)(krow0 + r) * KCOLS + kvh * HDIM + c * 8;
            cp_async16(base +             SW(r, c), Kh_g + go);
            cp_async16(base +   FTILE_B + SW(r, c), Kl_g + go);
            cp_async16(base + 2*FTILE_B + SW(r, c), Vh_g + go);
            cp_async16(base + 3*FTILE_B + SW(r, c), Vl_g + go);
        }
        asm volatile("cp.async.commit_group;\n" ::: "memory");
    };

    load_kv(0, 0);
    asm volatile("cp.async.commit_group;\n" ::: "memory");

    const int er = lane >> 2, ec = lane & 3;
    const int a_row = w * 16 + (lane & 15);
    const int a_kh  = lane >> 4;
    const int b_n   = (lane & 7) + ((lane >> 4) & 1) * 8;
    const int b_kh  = (lane >> 3) & 1;
    const int v_key = (lane & 7) + ((lane >> 3) & 1) * 8;
    const int v_dc  = lane >> 4;

    const int rg0 = qt * FQT + w * 16 + er;
    const int rg1 = rg0 + 8;

    float o[16][4];
    #pragma unroll
    for (int j = 0; j < 16; j++)
        #pragma unroll
        for (int q = 0; q < 4; q++) o[j][q] = 0.0f;
    float m0 = -1e30f, m1 = -1e30f, l0 = 0.0f, l1 = 0.0f;

    for (int kt = 0; kt < nkt; kt++) {
        const int st = kt & 1;
        if (kt + 1 < nkt) {
            load_kv(kt + 1, (kt + 1) & 1);
            asm volatile("cp.async.wait_group 1;\n" ::: "memory");
        } else {
            asm volatile("cp.async.wait_group 0;\n" ::: "memory");
        }
        __syncthreads();

        const uint32_t Kh_s = KV_s + st * FKV_B;
        const uint32_t Kl_s = Kh_s + FTILE_B;
        const uint32_t Vh_s = Kh_s + 2 * FTILE_B;
        const uint32_t Vl_s = Kh_s + 3 * FTILE_B;

        float s[8][4];
        #pragma unroll
        for (int f = 0; f < 8; f++)
            #pragma unroll
            for (int q = 0; q < 4; q++) s[f][q] = 0.0f;

        #pragma unroll
        for (int ks = 0; ks < 8; ks++) {
            uint32_t qa[4];
            ldsm_x4(qa[0], qa[1], qa[2], qa[3], Qh_s + SW(a_row, ks*2 + a_kh));
            #pragma unroll
            for (int ng = 0; ng < 4; ng++) {
                uint32_t kh0, kh1, kh2, kh3, kl0, kl1, kl2, kl3;
                ldsm_x4(kh0, kh1, kh2, kh3, Kh_s + SW(ng*16 + b_n, ks*2 + b_kh));
                ldsm_x4(kl0, kl1, kl2, kl3, Kl_s + SW(ng*16 + b_n, ks*2 + b_kh));
                float* s0 = s[ng*2];
                float* s1 = s[ng*2 + 1];
                mma16816(s0[0], s0[1], s0[2], s0[3], qa[0], qa[1], qa[2], qa[3], kh0, kh1);
                mma16816(s1[0], s1[1], s1[2], s1[3], qa[0], qa[1], qa[2], qa[3], kh2, kh3);
                mma16816(s0[0], s0[1], s0[2], s0[3], qa[0], qa[1], qa[2], qa[3], kl0, kl1);
                mma16816(s1[0], s1[1], s1[2], s1[3], qa[0], qa[1], qa[2], qa[3], kl2, kl3);
            }
        }

        if (kt >= 2 * qt) {
            #pragma unroll
            for (int f = 0; f < 8; f++) {
                const int key0 = kt * FKT + f * 8 + ec * 2;
                if (key0     > rg0) s[f][0] = -1e30f;
                if (key0 + 1 > rg0) s[f][1] = -1e30f;
                if (key0     > rg1) s[f][2] = -1e30f;
                if (key0 + 1 > rg1) s[f][3] = -1e30f;
            }
        }

        float nm0 = -1e30f, nm1 = -1e30f;
        #pragma unroll
        for (int f = 0; f < 8; f++) {
            nm0 = fmaxf(nm0, fmaxf(s[f][0], s[f][1]));
            nm1 = fmaxf(nm1, fmaxf(s[f][2], s[f][3]));
        }
        nm0 = fmaxf(nm0, __shfl_xor_sync(0xffffffffu, nm0, 1));
        nm0 = fmaxf(nm0, __shfl_xor_sync(0xffffffffu, nm0, 2));
        nm1 = fmaxf(nm1, __shfl_xor_sync(0xffffffffu, nm1, 1));
        nm1 = fmaxf(nm1, __shfl_xor_sync(0xffffffffu, nm1, 2));
        nm0 = fmaxf(nm0, m0);
        nm1 = fmaxf(nm1, m1);
        const float corr0 = __expf(m0 - nm0);
        const float corr1 = __expf(m1 - nm1);
        m0 = nm0;
        m1 = nm1;

        float rs0 = 0.0f, rs1 = 0.0f;
        #pragma unroll
        for (int f = 0; f < 8; f++) {
            s[f][0] = __expf(s[f][0] - nm0);
            s[f][1] = __expf(s[f][1] - nm0);
            s[f][2] = __expf(s[f][2] - nm1);
            s[f][3] = __expf(s[f][3] - nm1);
            rs0 += s[f][0] + s[f][1];
            rs1 += s[f][2] + s[f][3];
        }
        rs0 += __shfl_xor_sync(0xffffffffu, rs0, 1);
        rs0 += __shfl_xor_sync(0xffffffffu, rs0, 2);
        rs1 += __shfl_xor_sync(0xffffffffu, rs1, 1);
        rs1 += __shfl_xor_sync(0xffffffffu, rs1, 2);
        l0 = l0 * corr0 + rs0;
        l1 = l1 * corr1 + rs1;
        #pragma unroll
        for (int j = 0; j < 16; j++) {
            o[j][0] *= corr0; o[j][1] *= corr0;
            o[j][2] *= corr1; o[j][3] *= corr1;
        }

        #pragma unroll
        for (int kp = 0; kp < 4; kp++) {
            // pack P hi fragments (fp16 rel err 2^-11 — lo product dropped)
            const float* f0 = s[2*kp];
            const float* f1 = s[2*kp + 1];
            uint32_t pa[4];
            __half2 t;
            t = __floats2half2_rn(f0[0], f0[1]); pa[0] = *reinterpret_cast<uint32_t*>(&t);
            t = __floats2half2_rn(f0[2], f0[3]); pa[1] = *reinterpret_cast<uint32_t*>(&t);
            t = __floats2half2_rn(f1[0], f1[1]); pa[2] = *reinterpret_cast<uint32_t*>(&t);
            t = __floats2half2_rn(f1[2], f1[3]); pa[3] = *reinterpret_cast<uint32_t*>(&t);

            #pragma unroll
            for (int nd = 0; nd < 8; nd++) {
                uint32_t vh0, vh1, vh2, vh3, vl0, vl1, vl2, vl3;
                ldsm_x4t(vh0, vh1, vh2, vh3, Vh_s + SW(kp*16 + v_key, nd*2 + v_dc));
                ldsm_x4t(vl0, vl1, vl2, vl3, Vl_s + SW(kp*16 + v_key, nd*2 + v_dc));
                float* o0 = o[nd*2];
                float* o1 = o[nd*2 + 1];
                mma16816(o0[0], o0[1], o0[2], o0[3], pa[0], pa[1], pa[2], pa[3], vh0, vh1);
                mma16816(o1[0], o1[1], o1[2], o1[3], pa[0], pa[1], pa[2], pa[3], vh2, vh3);
                mma16816(o0[0], o0[1], o0[2], o0[3], pa[0], pa[1], pa[2], pa[3], vl0, vl1);
                mma16816(o1[0], o1[1], o1[2], o1[3], pa[0], pa[1], pa[2], pa[3], vl2, vl3);
            }
        }
        __syncthreads();
    }

    const float inv0 = 1.0f / l0;
    const float inv1 = 1.0f / l1;
    const size_t row0 = (size_t)(qrow0 + w * 16 + er);
    const size_t row1 = row0 + 8;
    #pragma unroll
    for (int j = 0; j < 16; j++) {
        const int col = h * HDIM + j * 8 + ec * 2;
        *reinterpret_cast<__half2*>(Ch_g + row0 * QCOLS + col) =
            __floats2half2_rn(o[j][0] * inv0, o[j][1] * inv0);
        *reinterpret_cast<__half2*>(Ch_g + row1 * QCOLS + col) =
            __floats2half2_rn(o[j][2] * inv1, o[j][3] * inv1);
    }
}

// ---------------------------------------------------------------------------
extern "C" void kernel_launch(void* const* d_in, const int* in_sizes, int n_in,
                              void* d_out, int out_size)
{
    const float* hidden = (const float*)d_in[0];
    const float* Wq = (const float*)d_in[1];
    const float* Wk = (const float*)d_in[2];
    const float* Wv = (const float*)d_in[3];
    const float* Wo = (const float*)d_in[4];
    float* out = (float*)d_out;

    __half *ah, *ch, *qh, *kh, *kl, *vh, *vl, *wh, *wl, *woh, *wol;
    cudaGetSymbolAddress((void**)&ah, g_ah);
    cudaGetSymbolAddress((void**)&ch, g_ch);
    cudaGetSymbolAddress((void**)&qh, g_qh);
    cudaGetSymbolAddress((void**)&kh, g_kh);  cudaGetSymbolAddress((void**)&kl, g_kl);
    cudaGetSymbolAddress((void**)&vh, g_vh);  cudaGetSymbolAddress((void**)&vl, g_vl);
    cudaGetSymbolAddress((void**)&wh, g_wh);  cudaGetSymbolAddress((void**)&wl, g_wl);
    cudaGetSymbolAddress((void**)&woh, g_woh); cudaGetSymbolAddress((void**)&wol, g_wol);

    cudaFuncSetAttribute(gemm_mma,
                         cudaFuncAttributeMaxDynamicSharedMemorySize, GEMM_SMEM);
    cudaFuncSetAttribute(gemm_qkv_fused,
                         cudaFuncAttributeMaxDynamicSharedMemorySize, GEMM_SMEM);
    cudaFuncSetAttribute(flash_mma,
                         cudaFuncAttributeMaxDynamicSharedMemorySize, FLASH_SMEM);

    // 1) RoPE table, 2) hidden hi-split, 3) all weight transposes (one launch)
    rope_table_kernel<<<(SEQ*64 + 255)/256, 256>>>();
    split_hi_kernel<<<(ROWS*HID/4 + 255)/256, 256>>>(hidden, ah, ROWS*HID/4);
    tsplit_all_kernel<<<10240, dim3(32,8)>>>(Wq, Wk, Wv, Wo, wh, wl, woh, wol);

    // 4) Merged QKV projection with fused RoPE/scale/split epilogue
    gemm_qkv_fused<<<dim3(QKVC/128, ROWS/128), 256, GEMM_SMEM>>>(
        ah, wh, wl, qh, kh, kl, vh, vl);

    // 5) Attention, writes ctx hi directly
    flash_mma<<<dim3(SEQ/FQT, NHQ, BATCH), 256, FLASH_SMEM>>>(qh, kh, kl, vh, vl, ch);

    // 6) Output projection
    gemm_mma<<<dim3(HID/128, ROWS/128), 256, GEMM_SMEM>>>(ch, woh, wol, out, HID);
}

// round 11
// speedup vs baseline: 4.7141x; 1.0616x over previous
#include <cuda_runtime.h>
#include <cuda_fp16.h>
#include <math.h>
#include <stdint.h>

// Problem constants
#define BATCH 2
#define SEQ   2048
#define HID   2048
#define NHQ   16
#define NKV   4
#define HDIM  128
#define ROWS  (BATCH*SEQ)          // 4096
#define QCOLS (NHQ*HDIM)           // 2048
#define KCOLS (NKV*HDIM)           // 512
#define QKVC  (QCOLS + 2*KCOLS)    // 3072

// ---------------------------------------------------------------------------
// Device scratch (static — no allocation allowed)
// A-side operands are fp16 hi-only; B-side operands are fp16 hi+lo.
// ---------------------------------------------------------------------------
__device__ float g_cos[SEQ*64];
__device__ float g_sin[SEQ*64];

__device__ __half g_ah[ROWS*HID];                       // hidden (hi only)
__device__ __half g_ch[ROWS*QCOLS];                     // ctx (hi only)
__device__ __half g_qh[ROWS*QCOLS];                     // q (hi only, rope+scale)
__device__ __half g_kh[ROWS*KCOLS], g_kl[ROWS*KCOLS];   // k hi/lo (rope)
__device__ __half g_vh[ROWS*KCOLS], g_vl[ROWS*KCOLS];   // v hi/lo
__device__ __half g_wh[QKVC*HID],   g_wl[QKVC*HID];     // [Wq;Wk;Wv]^T hi/lo
__device__ __half g_woh[HID*QCOLS], g_wol[HID*QCOLS];   // Wo^T hi/lo

// ---------------------------------------------------------------------------
// Helpers
// ---------------------------------------------------------------------------
__device__ __forceinline__ uint32_t smem_u32(const void* p) {
    uint32_t a;
    asm("{ .reg .u64 t; cvta.to.shared.u64 t, %1; cvt.u32.u64 %0, t; }" : "=r"(a) : "l"(p));
    return a;
}
__device__ __forceinline__ void cp_async16(uint32_t dst, const void* src) {
    asm volatile("cp.async.cg.shared.global [%0], [%1], 16;\n" :: "r"(dst), "l"(src) : "memory");
}
__device__ __forceinline__ void ldsm_x4(uint32_t& r0, uint32_t& r1, uint32_t& r2, uint32_t& r3,
                                        uint32_t addr) {
    asm volatile("ldmatrix.sync.aligned.m8n8.x4.shared.b16 {%0,%1,%2,%3}, [%4];"
                 : "=r"(r0), "=r"(r1), "=r"(r2), "=r"(r3) : "r"(addr));
}
__device__ __forceinline__ void ldsm_x4t(uint32_t& r0, uint32_t& r1, uint32_t& r2, uint32_t& r3,
                                         uint32_t addr) {
    asm volatile("ldmatrix.sync.aligned.m8n8.x4.trans.shared.b16 {%0,%1,%2,%3}, [%4];"
                 : "=r"(r0), "=r"(r1), "=r"(r2), "=r"(r3) : "r"(addr));
}
__device__ __forceinline__ void mma16816(float& c0, float& c1, float& c2, float& c3,
                                         uint32_t a0, uint32_t a1, uint32_t a2, uint32_t a3,
                                         uint32_t b0, uint32_t b1) {
    asm volatile(
        "mma.sync.aligned.m16n8k16.row.col.f32.f16.f16.f32 "
        "{%0,%1,%2,%3}, {%4,%5,%6,%7}, {%8,%9}, {%0,%1,%2,%3};"
        : "+f"(c0), "+f"(c1), "+f"(c2), "+f"(c3)
        : "r"(a0), "r"(a1), "r"(a2), "r"(a3), "r"(b0), "r"(b1));
}
// flash smem swizzle: row r (256B rows of fp16[128]), 16B chunk c (0..15)
#define SW(r, c) ((uint32_t)((r) * 256 + (((c) ^ ((r) & 7)) << 4)))
// gemm smem swizzle: row r (128B rows of fp16[64]), 16B chunk c (0..7)
#define SWG(r, c) ((uint32_t)((r) * 128 + (((c) ^ ((r) & 7)) << 4)))

// ---------------------------------------------------------------------------
// fp32 -> fp16 hi (row-major, same layout)
// ---------------------------------------------------------------------------
__global__ void split_hi_kernel(const float* __restrict__ in,
                                __half* __restrict__ hi, int n4)
{
    int i = blockIdx.x * blockDim.x + threadIdx.x;
    if (i >= n4) return;
    float4 v = reinterpret_cast<const float4*>(in)[i];
    __half2* hp = reinterpret_cast<__half2*>(hi);
    hp[2*i]   = __floats2half2_rn(v.x, v.y);
    hp[2*i+1] = __floats2half2_rn(v.z, v.w);
}

// All four weight transposes+splits (fp16 hi/lo) in ONE launch.
__global__ void tsplit_all_kernel(const float* __restrict__ Wq, const float* __restrict__ Wk,
                                  const float* __restrict__ Wv, const float* __restrict__ Wo,
                                  __half* __restrict__ wh, __half* __restrict__ wl,
                                  __half* __restrict__ woh, __half* __restrict__ wol)
{
    __shared__ float t[32][33];
    const int bid = blockIdx.x;
    const float* src;
    __half *dh, *dl;
    int Nin, nbx, tile;
    if (bid < 4096)      { src = Wq; dh = wh; dl = wl; Nin = 2048; nbx = 64; tile = bid; }
    else if (bid < 5120) { src = Wk; dh = wh + (size_t)QCOLS*HID; dl = wl + (size_t)QCOLS*HID;
                           Nin = 512; nbx = 16; tile = bid - 4096; }
    else if (bid < 6144) { src = Wv; dh = wh + (size_t)(QCOLS+KCOLS)*HID; dl = wl + (size_t)(QCOLS+KCOLS)*HID;
                           Nin = 512; nbx = 16; tile = bid - 5120; }
    else                 { src = Wo; dh = woh; dl = wol; Nin = 2048; nbx = 64; tile = bid - 6144; }

    const int tx = threadIdx.x, ty = threadIdx.y;
    const int n0 = (tile % nbx) * 32, k0 = (tile / nbx) * 32;
    #pragma unroll
    for (int j = 0; j < 32; j += 8)
        t[ty + j][tx] = src[(size_t)(k0 + ty + j) * Nin + n0 + tx];
    __syncthreads();
    #pragma unroll
    for (int j = 0; j < 32; j += 8) {
        float x = t[tx][ty + j];
        __half h = __float2half_rn(x);
        __half l = __float2half_rn(x - __half2float(h));
        size_t o = (size_t)(n0 + ty + j) * 2048 + k0 + tx;
        dh[o] = h;
        dl[o] = l;
    }
}

// ---------------------------------------------------------------------------
// RoPE table
// ---------------------------------------------------------------------------
__global__ void rope_table_kernel()
{
    int idx = blockIdx.x * blockDim.x + threadIdx.x;
    if (idx >= SEQ * 64) return;
    int pos = idx >> 6, i = idx & 63;
    double inv = exp2(-(double)i * (13.287712379549449 / 64.0));
    double ang = (double)pos * inv;
    const double twopi = 6.283185307179586476925286766559;
    ang -= floor(ang * (1.0 / twopi)) * twopi;
    if (ang > 3.14159265358979323846) ang -= twopi;
    float s, c;
    sincosf((float)ang, &s, &c);
    g_cos[idx] = c;
    g_sin[idx] = s;
}

// ---------------------------------------------------------------------------
// GEMM mainloop: 128x128 CTA tile, fp16 2-product (Ah*Bh + Ah*Bl).
// KCH=64 (32 chunks), 2-stage double buffer, one sync per chunk, 2 CTAs/SM.
// Stage layout: [Ah 16KB][Bh 16KB][Bl 16KB] = 48KB; 2 stages = 96KB.
// ---------------------------------------------------------------------------
#define KCH       64
#define NCHUNKS   32
#define TILE_B    16384           // 128 rows x 128 B
#define STAGE_B   (3*TILE_B)      // 48 KB
#define NSTG      2
#define GEMM_SMEM (NSTG*STAGE_B)  // 96 KB

struct GemmCtx {
    uint32_t sbase;
    const __half* gsrc;   // null => this thread group loads nothing
    int row0, lch, lr0;
    uint32_t smoff;
    int m0w, n0w;
    int a_row, a_kh, b_row, b_kh;
};

__device__ __forceinline__ void gemm_mainloop(
    const GemmCtx& cx, float acc[4][4][4])
{
    auto load_chunk = [&](int ci, int st) {
        if (cx.gsrc) {
            const uint32_t tb = cx.sbase + st * STAGE_B + cx.smoff;
            #pragma unroll
            for (int i = 0; i < 16; i++) {
                const int r = cx.lr0 + i * 8;
                const uint32_t dst = tb + SWG(r, cx.lch);
                cp_async16(dst, cx.gsrc + (size_t)(cx.row0 + r) * 2048 + ci * KCH + cx.lch * 8);
            }
        }
        asm volatile("cp.async.commit_group;\n" ::: "memory");
    };

    load_chunk(0, 0);

    for (int ci = 0; ci < NCHUNKS; ci++) {
        asm volatile("cp.async.wait_group 0;\n" ::: "memory");
        __syncthreads();
        // stage (ci+1)&1 was last computed in iteration ci-1 — freed by the
        // barrier above (all warps past compute(ci-1)).
        if (ci + 1 < NCHUNKS) load_chunk(ci + 1, (ci + 1) & 1);

        const uint32_t ah_b = cx.sbase + (ci & 1) * STAGE_B;
        const uint32_t bh_b = ah_b + TILE_B;
        const uint32_t bl_b = ah_b + 2 * TILE_B;

        #pragma unroll
        for (int ks = 0; ks < 4; ks++) {
            uint32_t a4[4][4];
            #pragma unroll
            for (int mi = 0; mi < 4; mi++) {
                const int r = cx.m0w + mi * 16 + cx.a_row;
                ldsm_x4(a4[mi][0], a4[mi][1], a4[mi][2], a4[mi][3],
                        ah_b + SWG(r, ks * 2 + cx.a_kh));
            }
            uint32_t bh[4][2], bl[4][2];
            #pragma unroll
            for (int jb = 0; jb < 2; jb++) {
                const int r = cx.n0w + jb * 16 + cx.b_row;
                const uint32_t off = SWG(r, ks * 2 + cx.b_kh);
                ldsm_x4(bh[2*jb][0], bh[2*jb][1], bh[2*jb+1][0], bh[2*jb+1][1], bh_b + off);
                ldsm_x4(bl[2*jb][0], bl[2*jb][1], bl[2*jb+1][0], bl[2*jb+1][1], bl_b + off);
            }
            // Pass 1: Ah*Bh (16 independent accumulators)
            #pragma unroll
            for (int mi = 0; mi < 4; mi++)
                #pragma unroll
                for (int nj = 0; nj < 4; nj++) {
                    float* cc = acc[mi][nj];
                    mma16816(cc[0], cc[1], cc[2], cc[3],
                             a4[mi][0], a4[mi][1], a4[mi][2], a4[mi][3],
                             bh[nj][0], bh[nj][1]);
                }
            // Pass 2: Ah*Bl
            #pragma unroll
            for (int mi = 0; mi < 4; mi++)
                #pragma unroll
                for (int nj = 0; nj < 4; nj++) {
                    float* cc = acc[mi][nj];
                    mma16816(cc[0], cc[1], cc[2], cc[3],
                             a4[mi][0], a4[mi][1], a4[mi][2], a4[mi][3],
                             bl[nj][0], bl[nj][1]);
                }
        }
    }
}

__device__ __forceinline__ void gemm_init_ctx(
    GemmCtx& cx, uint32_t sbase, int tid, int m0, int n0,
    const __half* Ah, const __half* Bh, const __half* Bl)
{
    cx.sbase = sbase;
    const int tt = tid >> 6;
    const int t6 = tid & 63;
    cx.lch = t6 & 7;          // 16B chunk within 128B row
    cx.lr0 = t6 >> 3;         // row 0..7 (stride 8)
    switch (tt) {
        case 0:  cx.gsrc = Ah; cx.row0 = m0; cx.smoff = 0;          break;
        case 1:  cx.gsrc = Bh; cx.row0 = n0; cx.smoff = TILE_B;     break;
        case 2:  cx.gsrc = Bl; cx.row0 = n0; cx.smoff = 2*TILE_B;   break;
        default: cx.gsrc = nullptr; cx.row0 = 0; cx.smoff = 0;      break;
    }
    const int wid = tid >> 5, lane = tid & 31;
    cx.m0w = (wid & 1) * 64;
    cx.n0w = (wid >> 1) * 32;
    cx.a_row = lane & 15;
    cx.a_kh  = lane >> 4;
    cx.b_row = (lane & 7) + ((lane >> 4) & 1) * 8;
    cx.b_kh  = (lane >> 3) & 1;
}

// ---------------------------------------------------------------------------
// Plain GEMM (fp32 C output) — output projection.
// ---------------------------------------------------------------------------
__global__ __launch_bounds__(256, 2)
void gemm_mma(const __half* __restrict__ Ah,
              const __half* __restrict__ Bh, const __half* __restrict__ Bl,
              float* __restrict__ C, int ldc)
{
    extern __shared__ char dsm[];
    const int tid = threadIdx.x;
    const int lane = tid & 31;
    const int m0 = blockIdx.y * 128;
    const int n0 = blockIdx.x * 128;

    GemmCtx cx;
    gemm_init_ctx(cx, smem_u32(dsm), tid, m0, n0, Ah, Bh, Bl);

    float acc[4][4][4];
    #pragma unroll
    for (int i = 0; i < 4; i++)
        #pragma unroll
        for (int j = 0; j < 4; j++)
            #pragma unroll
            for (int q = 0; q < 4; q++) acc[i][j][q] = 0.0f;

    gemm_mainloop(cx, acc);

    const int er = lane >> 2;
    const int ec = (lane & 3) * 2;
    #pragma unroll
    for (int mi = 0; mi < 4; mi++) {
        const int row_a = m0 + cx.m0w + mi * 16 + er;
        #pragma unroll
        for (int nj = 0; nj < 4; nj++) {
            const int col = n0 + cx.n0w + nj * 8 + ec;
            float* cc = acc[mi][nj];
            *reinterpret_cast<float2*>(C + (size_t)row_a * ldc + col) =
                make_float2(cc[0], cc[1]);
            *reinterpret_cast<float2*>(C + (size_t)(row_a + 8) * ldc + col) =
                make_float2(cc[2], cc[3]);
        }
    }
}

// ---------------------------------------------------------------------------
// QKV GEMM with fused RoPE + scale + fp16 split epilogue.
// Q: hi only (+scale).  K: hi/lo.  V: hi/lo.
// ---------------------------------------------------------------------------
__global__ __launch_bounds__(256, 2)
void gemm_qkv_fused(const __half* __restrict__ Ah,
                    const __half* __restrict__ Bh, const __half* __restrict__ Bl,
                    __half* __restrict__ Qh,
                    __half* __restrict__ Kh, __half* __restrict__ Kl,
                    __half* __restrict__ Vh, __half* __restrict__ Vl)
{
    extern __shared__ char dsm[];
    const int tid = threadIdx.x;
    const int lane = tid & 31;
    const int m0 = blockIdx.y * 128;
    const int n0 = blockIdx.x * 128;

    GemmCtx cx;
    gemm_init_ctx(cx, smem_u32(dsm), tid, m0, n0, Ah, Bh, Bl);

    float acc[4][4][4];
    #pragma unroll
    for (int i = 0; i < 4; i++)
        #pragma unroll
        for (int j = 0; j < 4; j++)
            #pragma unroll
            for (int q = 0; q < 4; q++) acc[i][j][q] = 0.0f;

    gemm_mainloop(cx, acc);

    // ---- stage fp32 tile to smem [128][132] (67.6KB <= 96KB) ----
    __syncthreads();
    float* ft = reinterpret_cast<float*>(dsm);
    const int er = lane >> 2;
    const int ec = (lane & 3) * 2;
    #pragma unroll
    for (int mi = 0; mi < 4; mi++) {
        const int r = cx.m0w + mi * 16 + er;
        #pragma unroll
        for (int nj = 0; nj < 4; nj++) {
            const int c = cx.n0w + nj * 8 + ec;
            float* cc = acc[mi][nj];
            *reinterpret_cast<float2*>(ft + r * 132 + c)       = make_float2(cc[0], cc[1]);
            *reinterpret_cast<float2*>(ft + (r + 8) * 132 + c) = make_float2(cc[2], cc[3]);
        }
    }
    __syncthreads();

    // ---- fused epilogue by region ----
    if (n0 < QCOLS) {
        // Q head: rope + scale, hi only
        const int head = n0 >> 7;
        const float scale = 0.08838834764831845f;
        for (int it = 0; it < 32; it++) {
            const int idx = tid + it * 256;
            const int r = idx >> 6, i = idx & 63;
            const int grow = m0 + r;
            const int pos = grow & (SEQ - 1);
            const float x1 = ft[r * 132 + i];
            const float x2 = ft[r * 132 + i + 64];
            const float c = g_cos[pos * 64 + i];
            const float s = g_sin[pos * 64 + i];
            const float y1 = (x1 * c - x2 * s) * scale;
            const float y2 = (x2 * c + x1 * s) * scale;
            const size_t o = (size_t)grow * QCOLS + head * HDIM + i;
            Qh[o]      = __float2half_rn(y1);
            Qh[o + 64] = __float2half_rn(y2);
        }
    } else if (n0 < QCOLS + KCOLS) {
        // K head: rope, hi/lo
        const int head = (n0 - QCOLS) >> 7;
        for (int it = 0; it < 32; it++) {
            const int idx = tid + it * 256;
            const int r = idx >> 6, i = idx & 63;
            const int grow = m0 + r;
            const int pos = grow & (SEQ - 1);
            const float x1 = ft[r * 132 + i];
            const float x2 = ft[r * 132 + i + 64];
            const float c = g_cos[pos * 64 + i];
            const float s = g_sin[pos * 64 + i];
            const float y1 = x1 * c - x2 * s;
            const float y2 = x2 * c + x1 * s;
            const __half h1 = __float2half_rn(y1);
            const __half h2 = __float2half_rn(y2);
            const size_t o = (size_t)grow * KCOLS + head * HDIM + i;
            Kh[o]      = h1;
            Kh[o + 64] = h2;
            Kl[o]      = __float2half_rn(y1 - __half2float(h1));
            Kl[o + 64] = __float2half_rn(y2 - __half2float(h2));
        }
    } else {
        // V head: plain hi/lo
        const int cbase = n0 - (QCOLS + KCOLS);
        for (int it = 0; it < 64; it++) {
            const int idx = tid + it * 256;
            const int r = idx >> 7, c = idx & 127;
            const int grow = m0 + r;
            const float x = ft[r * 132 + c];
            const __half h = __float2half_rn(x);
            const size_t o = (size_t)grow * KCOLS + cbase + c;
            Vh[o] = h;
            Vl[o] = __float2half_rn(x - __half2float(h));
        }
    }
}

// ---------------------------------------------------------------------------
// Flash attention, fp16 2-product (Qh*Kh + Qh*Kl; Ph*Vh + Ph*Vl).
// qt processed descending (heavy tiles first). Writes ctx hi only.
// ---------------------------------------------------------------------------
#define FQT 128
#define FKT 64
#define FQ_B    32768
#define FTILE_B 16384
#define FKV_B   (4*FTILE_B)                 // Kh,Kl,Vh,Vl per stage
#define FLASH_SMEM (FQ_B + 2*FKV_B)         // 160KB

__global__ __launch_bounds__(256, 1)
void flash_mma(const __half* __restrict__ Qh_g,
               const __half* __restrict__ Kh_g, const __half* __restrict__ Kl_g,
               const __half* __restrict__ Vh_g, const __half* __restrict__ Vl_g,
               __half* __restrict__ Ch_g)
{
    extern __shared__ char dsm[];
    const uint32_t sb = smem_u32(dsm);
    const uint32_t Qh_s = sb;
    const uint32_t KV_s = sb + FQ_B;

    const int tid = threadIdx.x;
    const int w = tid >> 5, lane = tid & 31;
    const int qt = gridDim.x - 1 - blockIdx.x;
    const int h = blockIdx.y, b = blockIdx.z;
    const int kvh = h >> 2;
    const int qrow0 = b * SEQ + qt * FQT;
    const int nkt = 2 * qt + 2;

    {
        const int c = tid & 15, r0 = tid >> 4;
        #pragma unroll
        for (int i = 0; i < 8; i++) {
            const int r = r0 + i * 16;
            const size_t go = (size_t)(qrow0 + r) * QCOLS + h * HDIM + c * 8;
            cp_async16(Qh_s + SW(r, c), Qh_g + go);
        }
    }

    auto load_kv = [&](int kt, int st) {
        const int c = tid & 15, r0 = tid >> 4;
        const uint32_t base = KV_s + st * FKV_B;
        const int krow0 = b * SEQ + kt * FKT;
        #pragma unroll
        for (int i = 0; i < 4; i++) {
            const int r = r0 + i * 16;
            const size_t go = (size_t)(krow0 + r) * KCOLS + kvh * HDIM + c * 8;
            cp_async16(base +             SW(r, c), Kh_g + go);
            cp_async16(base +   FTILE_B + SW(r, c), Kl_g + go);
            cp_async16(base + 2*FTILE_B + SW(r, c), Vh_g + go);
            cp_async16(base + 3*FTILE_B + SW(r, c), Vl_g + go);
        }
        asm volatile("cp.async.commit_group;\n" ::: "memory");
    };

    load_kv(0, 0);
    asm volatile("cp.async.commit_group;\n" ::: "memory");

    const int er = lane >> 2, ec = lane & 3;
    const int a_row = w * 16 + (lane & 15);
    const int a_kh  = lane >> 4;
    const int b_n   = (lane & 7) + ((lane >> 4) & 1) * 8;
    const int b_kh  = (lane >> 3) & 1;
    const int v_key = (lane & 7) + ((lane >> 3) & 1) * 8;
    const int v_dc  = lane >> 4;

    const int rg0 = qt * FQT + w * 16 + er;
    const int rg1 = rg0 + 8;

    float o[16][4];
    #pragma unroll
    for (int j = 0; j < 16; j++)
        #pragma unroll
        for (int q = 0; q < 4; q++) o[j][q] = 0.0f;
    float m0 = -1e30f, m1 = -1e30f, l0 = 0.0f, l1 = 0.0f;

    for (int kt = 0; kt < nkt; kt++) {
        const int st = kt & 1;
        if (kt + 1 < nkt) {
            load_kv(kt + 1, (kt + 1) & 1);
            asm volatile("cp.async.wait_group 1;\n" ::: "memory");
        } else {
            asm volatile("cp.async.wait_group 0;\n" ::: "memory");
        }
        __syncthreads();

        const uint32_t Kh_s = KV_s + st * FKV_B;
        const uint32_t Kl_s = Kh_s + FTILE_B;
        const uint32_t Vh_s = Kh_s + 2 * FTILE_B;
        const uint32_t Vl_s = Kh_s + 3 * FTILE_B;

        float s[8][4];
        #pragma unroll
        for (int f = 0; f < 8; f++)
            #pragma unroll
            for (int q = 0; q < 4; q++) s[f][q] = 0.0f;

        #pragma unroll
        for (int ks = 0; ks < 8; ks++) {
            uint32_t qa[4];
            ldsm_x4(qa[0], qa[1], qa[2], qa[3], Qh_s + SW(a_row, ks*2 + a_kh));
            #pragma unroll
            for (int ng = 0; ng < 4; ng++) {
                uint32_t kh0, kh1, kh2, kh3, kl0, kl1, kl2, kl3;
                ldsm_x4(kh0, kh1, kh2, kh3, Kh_s + SW(ng*16 + b_n, ks*2 + b_kh));
                ldsm_x4(kl0, kl1, kl2, kl3, Kl_s + SW(ng*16 + b_n, ks*2 + b_kh));
                float* s0 = s[ng*2];
                float* s1 = s[ng*2 + 1];
                mma16816(s0[0], s0[1], s0[2], s0[3], qa[0], qa[1], qa[2], qa[3], kh0, kh1);
                mma16816(s1[0], s1[1], s1[2], s1[3], qa[0], qa[1], qa[2], qa[3], kh2, kh3);
                mma16816(s0[0], s0[1], s0[2], s0[3], qa[0], qa[1], qa[2], qa[3], kl0, kl1);
                mma16816(s1[0], s1[1], s1[2], s1[3], qa[0], qa[1], qa[2], qa[3], kl2, kl3);
            }
        }

        if (kt >= 2 * qt) {
            #pragma unroll
            for (int f = 0; f < 8; f++) {
                const int key0 = kt * FKT + f * 8 + ec * 2;
                if (key0     > rg0) s[f][0] = -1e30f;
                if (key0 + 1 > rg0) s[f][1] = -1e30f;
                if (key0     > rg1) s[f][2] = -1e30f;
                if (key0 + 1 > rg1) s[f][3] = -1e30f;
            }
        }

        float nm0 = -1e30f, nm1 = -1e30f;
        #pragma unroll
        for (int f = 0; f < 8; f++) {
            nm0 = fmaxf(nm0, fmaxf(s[f][0], s[f][1]));
            nm1 = fmaxf(nm1, fmaxf(s[f][2], s[f][3]));
        }
        nm0 = fmaxf(nm0, __shfl_xor_sync(0xffffffffu, nm0, 1));
        nm0 = fmaxf(nm0, __shfl_xor_sync(0xffffffffu, nm0, 2));
        nm1 = fmaxf(nm1, __shfl_xor_sync(0xffffffffu, nm1, 1));
        nm1 = fmaxf(nm1, __shfl_xor_sync(0xffffffffu, nm1, 2));
        nm0 = fmaxf(nm0, m0);
        nm1 = fmaxf(nm1, m1);
        const float corr0 = __expf(m0 - nm0);
        const float corr1 = __expf(m1 - nm1);
        m0 = nm0;
        m1 = nm1;

        float rs0 = 0.0f, rs1 = 0.0f;
        #pragma unroll
        for (int f = 0; f < 8; f++) {
            s[f][0] = __expf(s[f][0] - nm0);
            s[f][1] = __expf(s[f][1] - nm0);
            s[f][2] = __expf(s[f][2] - nm1);
            s[f][3] = __expf(s[f][3] - nm1);
            rs0 += s[f][0] + s[f][1];
            rs1 += s[f][2] + s[f][3];
        }
        rs0 += __shfl_xor_sync(0xffffffffu, rs0, 1);
        rs0 += __shfl_xor_sync(0xffffffffu, rs0, 2);
        rs1 += __shfl_xor_sync(0xffffffffu, rs1, 1);
        rs1 += __shfl_xor_sync(0xffffffffu, rs1, 2);
        l0 = l0 * corr0 + rs0;
        l1 = l1 * corr1 + rs1;
        #pragma unroll
        for (int j = 0; j < 16; j++) {
            o[j][0] *= corr0; o[j][1] *= corr0;
            o[j][2] *= corr1; o[j][3] *= corr1;
        }

        #pragma unroll
        for (int kp = 0; kp < 4; kp++) {
            // pack P hi fragments (fp16 rel err 2^-11 — lo product dropped)
            const float* f0 = s[2*kp];
            const float* f1 = s[2*kp + 1];
            uint32_t pa[4];
            __half2 t;
            t = __floats2half2_rn(f0[0], f0[1]); pa[0] = *reinterpret_cast<uint32_t*>(&t);
            t = __floats2half2_rn(f0[2], f0[3]); pa[1] = *reinterpret_cast<uint32_t*>(&t);
            t = __floats2half2_rn(f1[0], f1[1]); pa[2] = *reinterpret_cast<uint32_t*>(&t);
            t = __floats2half2_rn(f1[2], f1[3]); pa[3] = *reinterpret_cast<uint32_t*>(&t);

            #pragma unroll
            for (int nd = 0; nd < 8; nd++) {
                uint32_t vh0, vh1, vh2, vh3, vl0, vl1, vl2, vl3;
                ldsm_x4t(vh0, vh1, vh2, vh3, Vh_s + SW(kp*16 + v_key, nd*2 + v_dc));
                ldsm_x4t(vl0, vl1, vl2, vl3, Vl_s + SW(kp*16 + v_key, nd*2 + v_dc));
                float* o0 = o[nd*2];
                float* o1 = o[nd*2 + 1];
                mma16816(o0[0], o0[1], o0[2], o0[3], pa[0], pa[1], pa[2], pa[3], vh0, vh1);
                mma16816(o1[0], o1[1], o1[2], o1[3], pa[0], pa[1], pa[2], pa[3], vh2, vh3);
                mma16816(o0[0], o0[1], o0[2], o0[3], pa[0], pa[1], pa[2], pa[3], vl0, vl1);
                mma16816(o1[0], o1[1], o1[2], o1[3], pa[0], pa[1], pa[2], pa[3], vl2, vl3);
            }
        }
        __syncthreads();
    }

    const float inv0 = 1.0f / l0;
    const float inv1 = 1.0f / l1;
    const size_t row0 = (size_t)(qrow0 + w * 16 + er);
    const size_t row1 = row0 + 8;
    #pragma unroll
    for (int j = 0; j < 16; j++) {
        const int col = h * HDIM + j * 8 + ec * 2;
        *reinterpret_cast<__half2*>(Ch_g + row0 * QCOLS + col) =
            __floats2half2_rn(o[j][0] * inv0, o[j][1] * inv0);
        *reinterpret_cast<__half2*>(Ch_g + row1 * QCOLS + col) =
            __floats2half2_rn(o[j][2] * inv1, o[j][3] * inv1);
    }
}

// ---------------------------------------------------------------------------
extern "C" void kernel_launch(void* const* d_in, const int* in_sizes, int n_in,
                              void* d_out, int out_size)
{
    const float* hidden = (const float*)d_in[0];
    const float* Wq = (const float*)d_in[1];
    const float* Wk = (const float*)d_in[2];
    const float* Wv = (const float*)d_in[3];
    const float* Wo = (const float*)d_in[4];
    float* out = (float*)d_out;

    __half *ah, *ch, *qh, *kh, *kl, *vh, *vl, *wh, *wl, *woh, *wol;
    cudaGetSymbolAddress((void**)&ah, g_ah);
    cudaGetSymbolAddress((void**)&ch, g_ch);
    cudaGetSymbolAddress((void**)&qh, g_qh);
    cudaGetSymbolAddress((void**)&kh, g_kh);  cudaGetSymbolAddress((void**)&kl, g_kl);
    cudaGetSymbolAddress((void**)&vh, g_vh);  cudaGetSymbolAddress((void**)&vl, g_vl);
    cudaGetSymbolAddress((void**)&wh, g_wh);  cudaGetSymbolAddress((void**)&wl, g_wl);
    cudaGetSymbolAddress((void**)&woh, g_woh); cudaGetSymbolAddress((void**)&wol, g_wol);

    cudaFuncSetAttribute(gemm_mma,
                         cudaFuncAttributeMaxDynamicSharedMemorySize, GEMM_SMEM);
    cudaFuncSetAttribute(gemm_qkv_fused,
                         cudaFuncAttributeMaxDynamicSharedMemorySize, GEMM_SMEM);
    cudaFuncSetAttribute(flash_mma,
                         cudaFuncAttributeMaxDynamicSharedMemorySize, FLASH_SMEM);

    // 1) RoPE table, 2) hidden hi-split, 3) all weight transposes (one launch)
    rope_table_kernel<<<(SEQ*64 + 255)/256, 256>>>();
    split_hi_kernel<<<(ROWS*HID/4 + 255)/256, 256>>>(hidden, ah, ROWS*HID/4);
    tsplit_all_kernel<<<10240, dim3(32,8)>>>(Wq, Wk, Wv, Wo, wh, wl, woh, wol);

    // 4) Merged QKV projection with fused RoPE/scale/split epilogue
    gemm_qkv_fused<<<dim3(QKVC/128, ROWS/128), 256, GEMM_SMEM>>>(
        ah, wh, wl, qh, kh, kl, vh, vl);

    // 5) Attention, writes ctx hi directly
    flash_mma<<<dim3(SEQ/FQT, NHQ, BATCH), 256, FLASH_SMEM>>>(qh, kh, kl, vh, vl, ch);

    // 6) Output projection
    gemm_mma<<<dim3(HID/128, ROWS/128), 256, GEMM_SMEM>>>(ch, woh, wol, out, HID);
}